// round 2
// baseline (speedup 1.0000x reference)
#include <cuda_runtime.h>
#include <cuda_bf16.h>
#include <cstddef>

// Problem constants
#define Bsz 4
#define NQ  512
#define NK  2048
#define CDIM 1024
#define NHEADS 16
#define HDIM 64

// Scratch (device globals — no allocation allowed)
__device__ float g_tmp_q[(size_t)Bsz * NQ * CDIM];   // 8 MB
__device__ float g_tmp_k[(size_t)Bsz * NK * CDIM];   // 32 MB
__device__ float g_tmp_v[(size_t)Bsz * NK * CDIM];   // 32 MB
__device__ float g_x    [(size_t)Bsz * NQ * CDIM];   // 8 MB

// ---------------------------------------------------------------------------
// GEMM: Cout[m,n] = sum_k A[m,k] * W[n,k]  (+ optional bias[n])
// BM=BN=128, BK=16, 256 threads, 8x8 per-thread microtile.
// ---------------------------------------------------------------------------
#define BM 128
#define BN 128
#define BK 16

__global__ __launch_bounds__(256, 2)
void gemm_abT_kernel(const float* __restrict__ A, const float* __restrict__ W,
                     const float* __restrict__ bias, float* __restrict__ Cout,
                     int M, int N, int K)
{
    __shared__ float As[BK][BM];
    __shared__ float Bs[BK][BN];

    const int tid = threadIdx.x;
    const int ty  = tid >> 4;        // 0..15
    const int tx  = tid & 15;        // 0..15
    const int m0  = blockIdx.y * BM;
    const int n0  = blockIdx.x * BN;

    float acc[8][8];
#pragma unroll
    for (int i = 0; i < 8; i++)
#pragma unroll
        for (int j = 0; j < 8; j++) acc[i][j] = 0.f;

    for (int k0 = 0; k0 < K; k0 += BK) {
        // Load A tile [128][16] and W tile [128][16], store transposed.
#pragma unroll
        for (int i = 0; i < 2; i++) {
            int f  = tid + i * 256;      // 0..511 float4 slots
            int r  = f >> 2;             // 0..127
            int c4 = f & 3;              // 0..3
            float4 va = *(const float4*)&A[(size_t)(m0 + r) * K + k0 + c4 * 4];
            As[c4 * 4 + 0][r] = va.x;
            As[c4 * 4 + 1][r] = va.y;
            As[c4 * 4 + 2][r] = va.z;
            As[c4 * 4 + 3][r] = va.w;
            float4 vw = *(const float4*)&W[(size_t)(n0 + r) * K + k0 + c4 * 4];
            Bs[c4 * 4 + 0][r] = vw.x;
            Bs[c4 * 4 + 1][r] = vw.y;
            Bs[c4 * 4 + 2][r] = vw.z;
            Bs[c4 * 4 + 3][r] = vw.w;
        }
        __syncthreads();

#pragma unroll
        for (int kk = 0; kk < BK; kk++) {
            float a[8], b[8];
            *(float4*)&a[0] = *(const float4*)&As[kk][ty * 8 + 0];
            *(float4*)&a[4] = *(const float4*)&As[kk][ty * 8 + 4];
            *(float4*)&b[0] = *(const float4*)&Bs[kk][tx * 8 + 0];
            *(float4*)&b[4] = *(const float4*)&Bs[kk][tx * 8 + 4];
#pragma unroll
            for (int i = 0; i < 8; i++)
#pragma unroll
                for (int j = 0; j < 8; j++)
                    acc[i][j] += a[i] * b[j];
        }
        __syncthreads();
    }

    // Epilogue
#pragma unroll
    for (int i = 0; i < 8; i++) {
        float out[8];
#pragma unroll
        for (int j = 0; j < 8; j++) {
            out[j] = acc[i][j];
            if (bias) out[j] += bias[n0 + tx * 8 + j];
        }
        float* crow = &Cout[(size_t)(m0 + ty * 8 + i) * N + n0 + tx * 8];
        *(float4*)&crow[0] = *(float4*)&out[0];
        *(float4*)&crow[4] = *(float4*)&out[4];
    }
}

// ---------------------------------------------------------------------------
// RoPE (in-place on [rows, C] projected buffer; rotate-half convention)
// ---------------------------------------------------------------------------
__global__ void rope_kernel(float* __restrict__ buf, const int* __restrict__ pos,
                            int rows)
{
    int idx = blockIdx.x * blockDim.x + threadIdx.x;
    int total = rows * NHEADS * (HDIM / 2);
    if (idx >= total) return;
    int j   = idx & 31;          // 0..31 frequency index
    int h   = (idx >> 5) & (NHEADS - 1);
    int row = idx >> 9;          // 32*16 = 512 per row

    float p = (float)pos[row];
    // inv_freq = 10000^(-j/32)  -> exp2f(-j * log2(10000)/32)
    const float k = 13.2877123795494f / 32.0f; // log2(10000)/32
    float inv_freq = exp2f(-(float)j * k);
    float ang = p * inv_freq;
    float s, c;
    sincosf(ang, &s, &c);

    size_t base = (size_t)row * CDIM + h * HDIM + j;
    float x1 = buf[base];
    float x2 = buf[base + 32];
    buf[base]      = x1 * c - x2 * s;
    buf[base + 32] = x2 * c + x1 * s;
}

// ---------------------------------------------------------------------------
// Flash attention: 1 query per thread, 128 queries per block.
// q/k/v buffers are in [B, N, C] layout (head h occupies cols h*64..h*64+63).
// Output written directly to [B, Nq, C].
// ---------------------------------------------------------------------------
#define TK 32

__global__ __launch_bounds__(128, 1)
void attn_kernel(const float* __restrict__ qb, const float* __restrict__ kb,
                 const float* __restrict__ vb, float* __restrict__ xb)
{
    __shared__ float Ks[TK][HDIM];
    __shared__ float Vs[TK][HDIM];

    const int tid = threadIdx.x;
    const int h   = blockIdx.y;
    const int b   = blockIdx.z;
    const int qi  = blockIdx.x * 128 + tid;

    const float* qrow = qb + ((size_t)(b * NQ + qi)) * CDIM + h * HDIM;
    float q[HDIM];
#pragma unroll
    for (int i = 0; i < 16; i++)
        *(float4*)&q[i * 4] = *(const float4*)&qrow[i * 4];

    float m = -1e30f, l = 0.f;
    float o[HDIM];
#pragma unroll
    for (int d = 0; d < HDIM; d++) o[d] = 0.f;

    const float* kbase = kb + ((size_t)b * NK) * CDIM + h * HDIM;
    const float* vbase = vb + ((size_t)b * NK) * CDIM + h * HDIM;

    for (int kt = 0; kt < NK; kt += TK) {
        __syncthreads();
        // Load K/V tiles: 32 rows x 64 cols = 512 float4 each; 4 per thread.
#pragma unroll
        for (int i = 0; i < 4; i++) {
            int g = tid + i * 128;   // 0..511
            int r = g >> 4;          // 0..31
            int c = g & 15;          // float4 column
            *(float4*)&Ks[r][c * 4] = *(const float4*)&kbase[(size_t)(kt + r) * CDIM + c * 4];
            *(float4*)&Vs[r][c * 4] = *(const float4*)&vbase[(size_t)(kt + r) * CDIM + c * 4];
        }
        __syncthreads();

        float s[TK];
#pragma unroll
        for (int kk = 0; kk < TK; kk++) {
            const float4* k4 = (const float4*)Ks[kk];
            float acc = 0.f;
#pragma unroll
            for (int i = 0; i < 16; i++) {
                float4 kv = k4[i];
                acc += q[i * 4 + 0] * kv.x + q[i * 4 + 1] * kv.y
                     + q[i * 4 + 2] * kv.z + q[i * 4 + 3] * kv.w;
            }
            s[kk] = acc * 0.125f;   // 1/sqrt(64)
        }

        float mt = m;
#pragma unroll
        for (int kk = 0; kk < TK; kk++) mt = fmaxf(mt, s[kk]);
        float corr = __expf(m - mt);
        m = mt;
        l *= corr;
#pragma unroll
        for (int d = 0; d < HDIM; d++) o[d] *= corr;

#pragma unroll
        for (int kk = 0; kk < TK; kk++) {
            float p = __expf(s[kk] - m);
            l += p;
            const float4* v4 = (const float4*)Vs[kk];
#pragma unroll
            for (int i = 0; i < 16; i++) {
                float4 vv = v4[i];
                o[i * 4 + 0] += p * vv.x;
                o[i * 4 + 1] += p * vv.y;
                o[i * 4 + 2] += p * vv.z;
                o[i * 4 + 3] += p * vv.w;
            }
        }
    }

    float inv_l = 1.f / l;
    float* xrow = xb + ((size_t)(b * NQ + qi)) * CDIM + h * HDIM;
#pragma unroll
    for (int i = 0; i < 16; i++) {
        float4 ov;
        ov.x = o[i * 4 + 0] * inv_l;
        ov.y = o[i * 4 + 1] * inv_l;
        ov.z = o[i * 4 + 2] * inv_l;
        ov.w = o[i * 4 + 3] * inv_l;
        *(float4*)&xrow[i * 4] = ov;
    }
}

// ---------------------------------------------------------------------------
// Launcher
// ---------------------------------------------------------------------------
extern "C" void kernel_launch(void* const* d_in, const int* in_sizes, int n_in,
                              void* d_out, int out_size)
{
    const float* query = (const float*)d_in[0];
    const float* key   = (const float*)d_in[1];
    const float* value = (const float*)d_in[2];
    const int*   qpos  = (const int*)  d_in[3];
    const int*   kpos  = (const int*)  d_in[4];
    const float* Wq    = (const float*)d_in[5];
    const float* Wk    = (const float*)d_in[6];
    const float* Wv    = (const float*)d_in[7];
    const float* Wp    = (const float*)d_in[8];
    const float* bp    = (const float*)d_in[9];
    float* out = (float*)d_out;

    float *tq, *tk, *tv, *xb;
    cudaGetSymbolAddress((void**)&tq, g_tmp_q);
    cudaGetSymbolAddress((void**)&tk, g_tmp_k);
    cudaGetSymbolAddress((void**)&tv, g_tmp_v);
    cudaGetSymbolAddress((void**)&xb, g_x);

    const int Mq = Bsz * NQ;   // 2048
    const int Mk = Bsz * NK;   // 8192

    // Projections
    gemm_abT_kernel<<<dim3(CDIM / BN, Mq / BM), 256>>>(query, Wq, nullptr, tq, Mq, CDIM, CDIM);
    gemm_abT_kernel<<<dim3(CDIM / BN, Mk / BM), 256>>>(key,   Wk, nullptr, tk, Mk, CDIM, CDIM);
    gemm_abT_kernel<<<dim3(CDIM / BN, Mk / BM), 256>>>(value, Wv, nullptr, tv, Mk, CDIM, CDIM);

    // RoPE (in place)
    {
        int tq_total = Mq * NHEADS * (HDIM / 2);
        int tk_total = Mk * NHEADS * (HDIM / 2);
        rope_kernel<<<(tq_total + 255) / 256, 256>>>(tq, qpos, Mq);
        rope_kernel<<<(tk_total + 255) / 256, 256>>>(tk, kpos, Mk);
    }

    // Attention
    attn_kernel<<<dim3(NQ / 128, NHEADS, Bsz), 128>>>(tq, tk, tv, xb);

    // Output projection + bias
    gemm_abT_kernel<<<dim3(CDIM / BN, Mq / BM), 256>>>(xb, Wp, bp, out, Mq, CDIM, CDIM);
}

// round 4
// speedup vs baseline: 1.6515x; 1.6515x over previous
#include <cuda_runtime.h>
#include <cuda_bf16.h>
#include <cstdint>
#include <cstddef>

// Problem constants
#define Bsz 4
#define NQ  512
#define NK  2048
#define CDIM 1024
#define NHEADS 16
#define HDIM 64

// ---------------------------------------------------------------------------
// Scratch (device globals — no allocation allowed)
// ---------------------------------------------------------------------------
__device__ float g_tmp_q[(size_t)Bsz * NQ * CDIM];   // 8 MB
__device__ float g_tmp_k[(size_t)Bsz * NK * CDIM];   // 32 MB
__device__ float g_tmp_v[(size_t)Bsz * NK * CDIM];   // 32 MB
__device__ float g_x    [(size_t)Bsz * NQ * CDIM];   // 8 MB
__device__ __nv_bfloat16 g_ahi[(size_t)Bsz * NK * CDIM]; // 16 MB
__device__ __nv_bfloat16 g_alo[(size_t)Bsz * NK * CDIM]; // 16 MB
__device__ __nv_bfloat16 g_whi[(size_t)CDIM * CDIM];     // 2 MB
__device__ __nv_bfloat16 g_wlo[(size_t)CDIM * CDIM];     // 2 MB

// ---------------------------------------------------------------------------
// fp32 -> (bf16 hi, bf16 lo) split (vectorized by 4)
// ---------------------------------------------------------------------------
__global__ void split_bf16_kernel(const float4* __restrict__ in,
                                  __nv_bfloat162* __restrict__ hi,
                                  __nv_bfloat162* __restrict__ lo, int n4)
{
    int i = blockIdx.x * blockDim.x + threadIdx.x;
    if (i >= n4) return;
    float4 a = in[i];
    __nv_bfloat162 h01 = __floats2bfloat162_rn(a.x, a.y);
    __nv_bfloat162 h23 = __floats2bfloat162_rn(a.z, a.w);
    float2 f01 = __bfloat1622float2(h01);
    float2 f23 = __bfloat1622float2(h23);
    __nv_bfloat162 l01 = __floats2bfloat162_rn(a.x - f01.x, a.y - f01.y);
    __nv_bfloat162 l23 = __floats2bfloat162_rn(a.z - f23.x, a.w - f23.y);
    hi[i * 2 + 0] = h01;
    hi[i * 2 + 1] = h23;
    lo[i * 2 + 0] = l01;
    lo[i * 2 + 1] = l23;
}

// ---------------------------------------------------------------------------
// mma.sync split-bf16 GEMM: C[m,n] = sum_k A[m,k]*W[n,k] (+bias[n])
// 128x128 tile/CTA, BK=32, 256 thr (8 warps 4x2, 32x64 per warp),
// cp.async double-buffered smem, ldmatrix fragments, 3 compensation passes.
// ---------------------------------------------------------------------------
#define PITCH_B 80                       // bytes per smem row (32 bf16 + pad)
#define TILE_B  (128 * PITCH_B)          // 10240 B per tile
#define STAGE_B (4 * TILE_B)             // Ahi, Alo, Whi, Wlo
#define GM_SMEM (2 * STAGE_B)            // 81920 B

__device__ __forceinline__ uint32_t smem_u32(const void* p) {
    uint32_t a;
    asm("{ .reg .u64 t; cvta.to.shared.u64 t, %1; cvt.u32.u64 %0, t; }"
        : "=r"(a) : "l"(p));
    return a;
}

__device__ __forceinline__ void cp16(uint32_t dst, const void* src) {
    asm volatile("cp.async.cg.shared.global [%0], [%1], 16;"
                 :: "r"(dst), "l"(src) : "memory");
}

__device__ __forceinline__ void ldm_x4(uint32_t* r, uint32_t addr) {
    asm volatile("ldmatrix.sync.aligned.m8n8.x4.shared.b16 {%0,%1,%2,%3}, [%4];"
                 : "=r"(r[0]), "=r"(r[1]), "=r"(r[2]), "=r"(r[3]) : "r"(addr));
}

__device__ __forceinline__ void mma_bf16(float* c, const uint32_t* a,
                                         uint32_t b0, uint32_t b1) {
    asm volatile(
        "mma.sync.aligned.m16n8k16.row.col.f32.bf16.bf16.f32 "
        "{%0,%1,%2,%3}, {%4,%5,%6,%7}, {%8,%9}, {%0,%1,%2,%3};"
        : "+f"(c[0]), "+f"(c[1]), "+f"(c[2]), "+f"(c[3])
        : "r"(a[0]), "r"(a[1]), "r"(a[2]), "r"(a[3]), "r"(b0), "r"(b1));
}

// Load one 128x32 bf16 tile (rows row0.., k offset k0) into smem at base.
__device__ __forceinline__ void load_tile_async(const __nv_bfloat16* __restrict__ g,
                                                int row0, int k0,
                                                uint32_t sbase, int tid)
{
#pragma unroll
    for (int i = 0; i < 2; i++) {
        int idx = tid + i * 256;       // 0..511
        int r = idx >> 2;              // 0..127
        int j = idx & 3;               // 16B chunk within row
        cp16(sbase + r * PITCH_B + j * 16,
             g + (size_t)(row0 + r) * CDIM + k0 + j * 8);
    }
}

__global__ void __launch_bounds__(256)
gemm_mma_kernel(const __nv_bfloat16* __restrict__ Ahi,
                const __nv_bfloat16* __restrict__ Alo,
                const __nv_bfloat16* __restrict__ Whi,
                const __nv_bfloat16* __restrict__ Wlo,
                const float* __restrict__ bias,
                float* __restrict__ Cout)
{
    extern __shared__ __align__(128) char smem[];
    const uint32_t sb = smem_u32(smem);
    const int tid  = threadIdx.x;
    const int lane = tid & 31;
    const int warp = tid >> 5;
    const int wm   = warp >> 1;        // 0..3
    const int wn   = warp & 1;         // 0..1
    const int m0   = blockIdx.y * 128;
    const int n0   = blockIdx.x * 128;

    float acc[2][8][4];
#pragma unroll
    for (int mi = 0; mi < 2; mi++)
#pragma unroll
        for (int q = 0; q < 8; q++)
#pragma unroll
            for (int t = 0; t < 4; t++) acc[mi][q][t] = 0.f;

    // Fragment smem addressing (within a tile base):
    // A: row = wm*32 + mi*16 + ((lane>>3)&1)*8 + (lane&7), col = kk + (lane>>4)*8
    // B: row = wn*64 + nj*16 + ((lane>>4)&1)*8 + (lane&7), col = kk + ((lane>>3)&1)*8
    const int arow = wm * 32 + ((lane >> 3) & 1) * 8 + (lane & 7);
    const int acol = (lane >> 4) * 8;
    const int brow = wn * 64 + ((lane >> 4) & 1) * 8 + (lane & 7);
    const int bcol = ((lane >> 3) & 1) * 8;

    // Prefetch chunk 0 into stage 0
    load_tile_async(Ahi, m0, 0, sb + 0 * TILE_B, tid);
    load_tile_async(Alo, m0, 0, sb + 1 * TILE_B, tid);
    load_tile_async(Whi, n0, 0, sb + 2 * TILE_B, tid);
    load_tile_async(Wlo, n0, 0, sb + 3 * TILE_B, tid);
    asm volatile("cp.async.commit_group;" ::: "memory");

    const int NCHUNK = CDIM / 32;      // 32
    for (int c = 0; c < NCHUNK; c++) {
        if (c + 1 < NCHUNK) {
            uint32_t st = sb + ((c + 1) & 1) * STAGE_B;
            int k0 = (c + 1) * 32;
            load_tile_async(Ahi, m0, k0, st + 0 * TILE_B, tid);
            load_tile_async(Alo, m0, k0, st + 1 * TILE_B, tid);
            load_tile_async(Whi, n0, k0, st + 2 * TILE_B, tid);
            load_tile_async(Wlo, n0, k0, st + 3 * TILE_B, tid);
        }
        asm volatile("cp.async.commit_group;" ::: "memory");
        asm volatile("cp.async.wait_group 1;" ::: "memory");
        __syncthreads();

        const uint32_t stg  = sb + (c & 1) * STAGE_B;
        const uint32_t aHiB = stg + 0 * TILE_B;
        const uint32_t aLoB = stg + 1 * TILE_B;
        const uint32_t wHiB = stg + 2 * TILE_B;
        const uint32_t wLoB = stg + 3 * TILE_B;

#pragma unroll
        for (int s = 0; s < 2; s++) {
            const int kk = s * 16;
            uint32_t Ah[2][4], Al[2][4], Wh[4][4], Wl[4][4];
#pragma unroll
            for (int mi = 0; mi < 2; mi++) {
                uint32_t off = (uint32_t)((arow + mi * 16) * PITCH_B + (kk + acol) * 2);
                ldm_x4(Ah[mi], aHiB + off);
                ldm_x4(Al[mi], aLoB + off);
            }
#pragma unroll
            for (int nj = 0; nj < 4; nj++) {
                uint32_t off = (uint32_t)((brow + nj * 16) * PITCH_B + (kk + bcol) * 2);
                ldm_x4(Wh[nj], wHiB + off);
                ldm_x4(Wl[nj], wLoB + off);
            }
            // Pass 1: Ahi * Whi
#pragma unroll
            for (int mi = 0; mi < 2; mi++)
#pragma unroll
                for (int q = 0; q < 8; q++)
                    mma_bf16(acc[mi][q], Ah[mi],
                             Wh[q >> 1][(q & 1) * 2], Wh[q >> 1][(q & 1) * 2 + 1]);
            // Pass 2: Ahi * Wlo
#pragma unroll
            for (int mi = 0; mi < 2; mi++)
#pragma unroll
                for (int q = 0; q < 8; q++)
                    mma_bf16(acc[mi][q], Ah[mi],
                             Wl[q >> 1][(q & 1) * 2], Wl[q >> 1][(q & 1) * 2 + 1]);
            // Pass 3: Alo * Whi
#pragma unroll
            for (int mi = 0; mi < 2; mi++)
#pragma unroll
                for (int q = 0; q < 8; q++)
                    mma_bf16(acc[mi][q], Al[mi],
                             Wh[q >> 1][(q & 1) * 2], Wh[q >> 1][(q & 1) * 2 + 1]);
        }
        __syncthreads();
    }

    // Epilogue: frag (mi,q): rows m0+wm*32+mi*16+lane/4 (+8), col n0+wn*64+q*8+(lane%4)*2
    const int er = m0 + wm * 32 + (lane >> 2);
    const int ec = n0 + wn * 64 + (lane & 3) * 2;
#pragma unroll
    for (int mi = 0; mi < 2; mi++) {
#pragma unroll
        for (int q = 0; q < 8; q++) {
            float b0 = 0.f, b1 = 0.f;
            if (bias) { b0 = bias[ec + q * 8]; b1 = bias[ec + q * 8 + 1]; }
            float2 v0 = { acc[mi][q][0] + b0, acc[mi][q][1] + b1 };
            float2 v1 = { acc[mi][q][2] + b0, acc[mi][q][3] + b1 };
            *(float2*)&Cout[(size_t)(er + mi * 16) * CDIM + ec + q * 8]     = v0;
            *(float2*)&Cout[(size_t)(er + mi * 16 + 8) * CDIM + ec + q * 8] = v1;
        }
    }
}

// ---------------------------------------------------------------------------
// RoPE (in-place on [rows, C] projected buffer; rotate-half convention)
// ---------------------------------------------------------------------------
__global__ void rope_kernel(float* __restrict__ buf, const int* __restrict__ pos,
                            int rows)
{
    int idx = blockIdx.x * blockDim.x + threadIdx.x;
    int total = rows * NHEADS * (HDIM / 2);
    if (idx >= total) return;
    int j   = idx & 31;
    int h   = (idx >> 5) & (NHEADS - 1);
    int row = idx >> 9;

    float p = (float)pos[row];
    const float k = 13.2877123795494f / 32.0f; // log2(10000)/32
    float inv_freq = exp2f(-(float)j * k);
    float ang = p * inv_freq;
    float s, c;
    sincosf(ang, &s, &c);

    size_t base = (size_t)row * CDIM + h * HDIM + j;
    float x1 = buf[base];
    float x2 = buf[base + 32];
    buf[base]      = x1 * c - x2 * s;
    buf[base + 32] = x2 * c + x1 * s;
}

// ---------------------------------------------------------------------------
// Flash attention: 1 query per thread, 128 queries per block (fp32 CUDA core).
// ---------------------------------------------------------------------------
#define TK 32

__global__ __launch_bounds__(128, 1)
void attn_kernel(const float* __restrict__ qb, const float* __restrict__ kb,
                 const float* __restrict__ vb, float* __restrict__ xb)
{
    __shared__ float Ks[TK][HDIM];
    __shared__ float Vs[TK][HDIM];

    const int tid = threadIdx.x;
    const int h   = blockIdx.y;
    const int b   = blockIdx.z;
    const int qi  = blockIdx.x * 128 + tid;

    const float* qrow = qb + ((size_t)(b * NQ + qi)) * CDIM + h * HDIM;
    float q[HDIM];
#pragma unroll
    for (int i = 0; i < 16; i++)
        *(float4*)&q[i * 4] = *(const float4*)&qrow[i * 4];

    float m = -1e30f, l = 0.f;
    float o[HDIM];
#pragma unroll
    for (int d = 0; d < HDIM; d++) o[d] = 0.f;

    const float* kbase = kb + ((size_t)b * NK) * CDIM + h * HDIM;
    const float* vbase = vb + ((size_t)b * NK) * CDIM + h * HDIM;

    for (int kt = 0; kt < NK; kt += TK) {
        __syncthreads();
#pragma unroll
        for (int i = 0; i < 4; i++) {
            int g = tid + i * 128;
            int r = g >> 4;
            int c = g & 15;
            *(float4*)&Ks[r][c * 4] = *(const float4*)&kbase[(size_t)(kt + r) * CDIM + c * 4];
            *(float4*)&Vs[r][c * 4] = *(const float4*)&vbase[(size_t)(kt + r) * CDIM + c * 4];
        }
        __syncthreads();

        float s[TK];
#pragma unroll
        for (int kk = 0; kk < TK; kk++) {
            const float4* k4 = (const float4*)Ks[kk];
            float acc = 0.f;
#pragma unroll
            for (int i = 0; i < 16; i++) {
                float4 kv = k4[i];
                acc += q[i * 4 + 0] * kv.x + q[i * 4 + 1] * kv.y
                     + q[i * 4 + 2] * kv.z + q[i * 4 + 3] * kv.w;
            }
            s[kk] = acc * 0.125f;
        }

        float mt = m;
#pragma unroll
        for (int kk = 0; kk < TK; kk++) mt = fmaxf(mt, s[kk]);
        float corr = __expf(m - mt);
        m = mt;
        l *= corr;
#pragma unroll
        for (int d = 0; d < HDIM; d++) o[d] *= corr;

#pragma unroll
        for (int kk = 0; kk < TK; kk++) {
            float p = __expf(s[kk] - m);
            l += p;
            const float4* v4 = (const float4*)Vs[kk];
#pragma unroll
            for (int i = 0; i < 16; i++) {
                float4 vv = v4[i];
                o[i * 4 + 0] += p * vv.x;
                o[i * 4 + 1] += p * vv.y;
                o[i * 4 + 2] += p * vv.z;
                o[i * 4 + 3] += p * vv.w;
            }
        }
    }

    float inv_l = 1.f / l;
    float* xrow = xb + ((size_t)(b * NQ + qi)) * CDIM + h * HDIM;
#pragma unroll
    for (int i = 0; i < 16; i++) {
        float4 ov;
        ov.x = o[i * 4 + 0] * inv_l;
        ov.y = o[i * 4 + 1] * inv_l;
        ov.z = o[i * 4 + 2] * inv_l;
        ov.w = o[i * 4 + 3] * inv_l;
        *(float4*)&xrow[i * 4] = ov;
    }
}

// ---------------------------------------------------------------------------
// Launcher
// ---------------------------------------------------------------------------
static void run_split(const float* src, __nv_bfloat16* hi, __nv_bfloat16* lo, int n)
{
    int n4 = n / 4;
    split_bf16_kernel<<<(n4 + 255) / 256, 256>>>(
        (const float4*)src, (__nv_bfloat162*)hi, (__nv_bfloat162*)lo, n4);
}

extern "C" void kernel_launch(void* const* d_in, const int* in_sizes, int n_in,
                              void* d_out, int out_size)
{
    const float* query = (const float*)d_in[0];
    const float* key   = (const float*)d_in[1];
    const float* value = (const float*)d_in[2];
    const int*   qpos  = (const int*)  d_in[3];
    const int*   kpos  = (const int*)  d_in[4];
    const float* Wq    = (const float*)d_in[5];
    const float* Wk    = (const float*)d_in[6];
    const float* Wv    = (const float*)d_in[7];
    const float* Wp    = (const float*)d_in[8];
    const float* bp    = (const float*)d_in[9];
    float* out = (float*)d_out;

    float *tq, *tk, *tv, *xb;
    __nv_bfloat16 *ahi, *alo, *whi, *wlo;
    cudaGetSymbolAddress((void**)&tq, g_tmp_q);
    cudaGetSymbolAddress((void**)&tk, g_tmp_k);
    cudaGetSymbolAddress((void**)&tv, g_tmp_v);
    cudaGetSymbolAddress((void**)&xb, g_x);
    cudaGetSymbolAddress((void**)&ahi, g_ahi);
    cudaGetSymbolAddress((void**)&alo, g_alo);
    cudaGetSymbolAddress((void**)&whi, g_whi);
    cudaGetSymbolAddress((void**)&wlo, g_wlo);

    cudaFuncSetAttribute(gemm_mma_kernel,
                         cudaFuncAttributeMaxDynamicSharedMemorySize, GM_SMEM);

    const int Mq = Bsz * NQ;   // 2048
    const int Mk = Bsz * NK;   // 8192

    // Q projection
    run_split(query, ahi, alo, Mq * CDIM);
    run_split(Wq, whi, wlo, CDIM * CDIM);
    gemm_mma_kernel<<<dim3(CDIM / 128, Mq / 128), 256, GM_SMEM>>>(
        ahi, alo, whi, wlo, nullptr, tq);

    // K projection
    run_split(key, ahi, alo, Mk * CDIM);
    run_split(Wk, whi, wlo, CDIM * CDIM);
    gemm_mma_kernel<<<dim3(CDIM / 128, Mk / 128), 256, GM_SMEM>>>(
        ahi, alo, whi, wlo, nullptr, tk);

    // V projection
    run_split(value, ahi, alo, Mk * CDIM);
    run_split(Wv, whi, wlo, CDIM * CDIM);
    gemm_mma_kernel<<<dim3(CDIM / 128, Mk / 128), 256, GM_SMEM>>>(
        ahi, alo, whi, wlo, nullptr, tv);

    // RoPE (in place)
    {
        int tq_total = Mq * NHEADS * (HDIM / 2);
        int tk_total = Mk * NHEADS * (HDIM / 2);
        rope_kernel<<<(tq_total + 255) / 256, 256>>>(tq, qpos, Mq);
        rope_kernel<<<(tk_total + 255) / 256, 256>>>(tk, kpos, Mk);
    }

    // Attention
    attn_kernel<<<dim3(NQ / 128, NHEADS, Bsz), 128>>>(tq, tk, tv, xb);

    // Output projection + bias
    run_split(xb, ahi, alo, Mq * CDIM);
    run_split(Wp, whi, wlo, CDIM * CDIM);
    gemm_mma_kernel<<<dim3(CDIM / 128, Mq / 128), 256, GM_SMEM>>>(
        ahi, alo, whi, wlo, bp, out);
}

// round 5
// speedup vs baseline: 2.8801x; 1.7439x over previous
#include <cuda_runtime.h>
#include <cuda_bf16.h>
#include <cstdint>
#include <cstddef>

// Problem constants
#define Bsz 4
#define NQ  512
#define NK  2048
#define CDIM 1024
#define NHEADS 16
#define HDIM 64

// ---------------------------------------------------------------------------
// Scratch (device globals — no allocation allowed)
// ---------------------------------------------------------------------------
__device__ float g_tmp_q[(size_t)Bsz * NQ * CDIM];       // 8 MB  (fp32 q proj)
__device__ float g_tmp_k[(size_t)Bsz * NK * CDIM];       // 32 MB (fp32 k proj)
__device__ __nv_bfloat16 g_ahi[(size_t)Bsz * NK * CDIM]; // 16 MB
__device__ __nv_bfloat16 g_alo[(size_t)Bsz * NK * CDIM]; // 16 MB
__device__ __nv_bfloat16 g_whi[(size_t)CDIM * CDIM];     // 2 MB
__device__ __nv_bfloat16 g_wlo[(size_t)CDIM * CDIM];     // 2 MB
__device__ __nv_bfloat16 g_qhi[(size_t)Bsz * NQ * CDIM]; // 4 MB
__device__ __nv_bfloat16 g_qlo[(size_t)Bsz * NQ * CDIM]; // 4 MB
__device__ __nv_bfloat16 g_khi[(size_t)Bsz * NK * CDIM]; // 16 MB
__device__ __nv_bfloat16 g_klo[(size_t)Bsz * NK * CDIM]; // 16 MB
__device__ __nv_bfloat16 g_vhi[(size_t)Bsz * NK * CDIM]; // 16 MB
__device__ __nv_bfloat16 g_vlo[(size_t)Bsz * NK * CDIM]; // 16 MB

// ---------------------------------------------------------------------------
// Common helpers
// ---------------------------------------------------------------------------
__device__ __forceinline__ uint32_t smem_u32(const void* p) {
    uint32_t a;
    asm("{ .reg .u64 t; cvta.to.shared.u64 t, %1; cvt.u32.u64 %0, t; }"
        : "=r"(a) : "l"(p));
    return a;
}

__device__ __forceinline__ void cp16(uint32_t dst, const void* src) {
    asm volatile("cp.async.cg.shared.global [%0], [%1], 16;"
                 :: "r"(dst), "l"(src) : "memory");
}

__device__ __forceinline__ void ldm_x4(uint32_t* r, uint32_t addr) {
    asm volatile("ldmatrix.sync.aligned.m8n8.x4.shared.b16 {%0,%1,%2,%3}, [%4];"
                 : "=r"(r[0]), "=r"(r[1]), "=r"(r[2]), "=r"(r[3]) : "r"(addr));
}

__device__ __forceinline__ void ldm_x4_t(uint32_t* r, uint32_t addr) {
    asm volatile("ldmatrix.sync.aligned.m8n8.x4.trans.shared.b16 {%0,%1,%2,%3}, [%4];"
                 : "=r"(r[0]), "=r"(r[1]), "=r"(r[2]), "=r"(r[3]) : "r"(addr));
}

__device__ __forceinline__ void mma_bf16(float* c, const uint32_t* a,
                                         uint32_t b0, uint32_t b1) {
    asm volatile(
        "mma.sync.aligned.m16n8k16.row.col.f32.bf16.bf16.f32 "
        "{%0,%1,%2,%3}, {%4,%5,%6,%7}, {%8,%9}, {%0,%1,%2,%3};"
        : "+f"(c[0]), "+f"(c[1]), "+f"(c[2]), "+f"(c[3])
        : "r"(a[0]), "r"(a[1]), "r"(a[2]), "r"(a[3]), "r"(b0), "r"(b1));
}

__device__ __forceinline__ uint32_t pack_hi(float a, float b) {
    __nv_bfloat162 t = __floats2bfloat162_rn(a, b);
    return *(uint32_t*)&t;
}
__device__ __forceinline__ uint32_t pack_lo(float a, float b, uint32_t hi) {
    __nv_bfloat162 h = *(__nv_bfloat162*)&hi;
    float2 f = __bfloat1622float2(h);
    __nv_bfloat162 t = __floats2bfloat162_rn(a - f.x, b - f.y);
    return *(uint32_t*)&t;
}

// ---------------------------------------------------------------------------
// fp32 -> (bf16 hi, bf16 lo) split (vectorized by 4)
// ---------------------------------------------------------------------------
__global__ void split_bf16_kernel(const float4* __restrict__ in,
                                  __nv_bfloat162* __restrict__ hi,
                                  __nv_bfloat162* __restrict__ lo, int n4)
{
    int i = blockIdx.x * blockDim.x + threadIdx.x;
    if (i >= n4) return;
    float4 a = in[i];
    __nv_bfloat162 h01 = __floats2bfloat162_rn(a.x, a.y);
    __nv_bfloat162 h23 = __floats2bfloat162_rn(a.z, a.w);
    float2 f01 = __bfloat1622float2(h01);
    float2 f23 = __bfloat1622float2(h23);
    hi[i * 2 + 0] = h01;
    hi[i * 2 + 1] = h23;
    lo[i * 2 + 0] = __floats2bfloat162_rn(a.x - f01.x, a.y - f01.y);
    lo[i * 2 + 1] = __floats2bfloat162_rn(a.z - f23.x, a.w - f23.y);
}

// ---------------------------------------------------------------------------
// RoPE + split: reads fp32 projected buffer, applies rotate-half RoPE
// (optionally scaled), writes bf16 hi/lo pair buffers.
// ---------------------------------------------------------------------------
__global__ void rope_split_kernel(const float* __restrict__ buf,
                                  const int* __restrict__ pos,
                                  __nv_bfloat16* __restrict__ hi,
                                  __nv_bfloat16* __restrict__ lo,
                                  int rows, float scale)
{
    int idx = blockIdx.x * blockDim.x + threadIdx.x;
    int total = rows * NHEADS * (HDIM / 2);
    if (idx >= total) return;
    int j   = idx & 31;
    int h   = (idx >> 5) & (NHEADS - 1);
    int row = idx >> 9;

    float p = (float)pos[row];
    const float kf = 13.2877123795494f / 32.0f; // log2(10000)/32
    float inv_freq = exp2f(-(float)j * kf);
    float ang = p * inv_freq;
    float s, c;
    sincosf(ang, &s, &c);

    size_t base = (size_t)row * CDIM + h * HDIM + j;
    float x1 = buf[base];
    float x2 = buf[base + 32];
    float y1 = (x1 * c - x2 * s) * scale;
    float y2 = (x2 * c + x1 * s) * scale;

    __nv_bfloat16 h1 = __float2bfloat16_rn(y1);
    __nv_bfloat16 h2 = __float2bfloat16_rn(y2);
    hi[base]      = h1;
    hi[base + 32] = h2;
    lo[base]      = __float2bfloat16_rn(y1 - __bfloat162float(h1));
    lo[base + 32] = __float2bfloat16_rn(y2 - __bfloat162float(h2));
}

// ---------------------------------------------------------------------------
// mma.sync split-bf16 GEMM: C[m,n] = sum_k A[m,k]*W[n,k] (+bias[n])
// If HiO != nullptr, writes bf16 hi/lo split instead of fp32 Cout.
// ---------------------------------------------------------------------------
#define PITCH_B 80
#define TILE_B  (128 * PITCH_B)
#define STAGE_B (4 * TILE_B)
#define GM_SMEM (2 * STAGE_B)

__device__ __forceinline__ void load_tile_async(const __nv_bfloat16* __restrict__ g,
                                                int row0, int k0,
                                                uint32_t sbase, int tid)
{
#pragma unroll
    for (int i = 0; i < 2; i++) {
        int idx = tid + i * 256;
        int r = idx >> 2;
        int j = idx & 3;
        cp16(sbase + r * PITCH_B + j * 16,
             g + (size_t)(row0 + r) * CDIM + k0 + j * 8);
    }
}

__global__ void __launch_bounds__(256)
gemm_mma_kernel(const __nv_bfloat16* __restrict__ Ahi,
                const __nv_bfloat16* __restrict__ Alo,
                const __nv_bfloat16* __restrict__ Whi,
                const __nv_bfloat16* __restrict__ Wlo,
                const float* __restrict__ bias,
                float* __restrict__ Cout,
                __nv_bfloat16* __restrict__ HiO,
                __nv_bfloat16* __restrict__ LoO)
{
    extern __shared__ __align__(128) char smem[];
    const uint32_t sb = smem_u32(smem);
    const int tid  = threadIdx.x;
    const int lane = tid & 31;
    const int warp = tid >> 5;
    const int wm   = warp >> 1;
    const int wn   = warp & 1;
    const int m0   = blockIdx.y * 128;
    const int n0   = blockIdx.x * 128;

    float acc[2][8][4];
#pragma unroll
    for (int mi = 0; mi < 2; mi++)
#pragma unroll
        for (int q = 0; q < 8; q++)
#pragma unroll
            for (int t = 0; t < 4; t++) acc[mi][q][t] = 0.f;

    const int arow = wm * 32 + ((lane >> 3) & 1) * 8 + (lane & 7);
    const int acol = (lane >> 4) * 8;
    const int brow = wn * 64 + ((lane >> 4) & 1) * 8 + (lane & 7);
    const int bcol = ((lane >> 3) & 1) * 8;

    load_tile_async(Ahi, m0, 0, sb + 0 * TILE_B, tid);
    load_tile_async(Alo, m0, 0, sb + 1 * TILE_B, tid);
    load_tile_async(Whi, n0, 0, sb + 2 * TILE_B, tid);
    load_tile_async(Wlo, n0, 0, sb + 3 * TILE_B, tid);
    asm volatile("cp.async.commit_group;" ::: "memory");

    const int NCHUNK = CDIM / 32;
    for (int c = 0; c < NCHUNK; c++) {
        if (c + 1 < NCHUNK) {
            uint32_t st = sb + ((c + 1) & 1) * STAGE_B;
            int k0 = (c + 1) * 32;
            load_tile_async(Ahi, m0, k0, st + 0 * TILE_B, tid);
            load_tile_async(Alo, m0, k0, st + 1 * TILE_B, tid);
            load_tile_async(Whi, n0, k0, st + 2 * TILE_B, tid);
            load_tile_async(Wlo, n0, k0, st + 3 * TILE_B, tid);
        }
        asm volatile("cp.async.commit_group;" ::: "memory");
        asm volatile("cp.async.wait_group 1;" ::: "memory");
        __syncthreads();

        const uint32_t stg  = sb + (c & 1) * STAGE_B;
        const uint32_t aHiB = stg + 0 * TILE_B;
        const uint32_t aLoB = stg + 1 * TILE_B;
        const uint32_t wHiB = stg + 2 * TILE_B;
        const uint32_t wLoB = stg + 3 * TILE_B;

#pragma unroll
        for (int s = 0; s < 2; s++) {
            const int kk = s * 16;
            uint32_t Ah[2][4], Al[2][4], Wh[4][4], Wl[4][4];
#pragma unroll
            for (int mi = 0; mi < 2; mi++) {
                uint32_t off = (uint32_t)((arow + mi * 16) * PITCH_B + (kk + acol) * 2);
                ldm_x4(Ah[mi], aHiB + off);
                ldm_x4(Al[mi], aLoB + off);
            }
#pragma unroll
            for (int nj = 0; nj < 4; nj++) {
                uint32_t off = (uint32_t)((brow + nj * 16) * PITCH_B + (kk + bcol) * 2);
                ldm_x4(Wh[nj], wHiB + off);
                ldm_x4(Wl[nj], wLoB + off);
            }
#pragma unroll
            for (int mi = 0; mi < 2; mi++)
#pragma unroll
                for (int q = 0; q < 8; q++)
                    mma_bf16(acc[mi][q], Ah[mi],
                             Wh[q >> 1][(q & 1) * 2], Wh[q >> 1][(q & 1) * 2 + 1]);
#pragma unroll
            for (int mi = 0; mi < 2; mi++)
#pragma unroll
                for (int q = 0; q < 8; q++)
                    mma_bf16(acc[mi][q], Ah[mi],
                             Wl[q >> 1][(q & 1) * 2], Wl[q >> 1][(q & 1) * 2 + 1]);
#pragma unroll
            for (int mi = 0; mi < 2; mi++)
#pragma unroll
                for (int q = 0; q < 8; q++)
                    mma_bf16(acc[mi][q], Al[mi],
                             Wh[q >> 1][(q & 1) * 2], Wh[q >> 1][(q & 1) * 2 + 1]);
        }
        __syncthreads();
    }

    const int er = m0 + wm * 32 + (lane >> 2);
    const int ec = n0 + wn * 64 + (lane & 3) * 2;
#pragma unroll
    for (int mi = 0; mi < 2; mi++) {
#pragma unroll
        for (int q = 0; q < 8; q++) {
            float b0 = 0.f, b1 = 0.f;
            if (bias) { b0 = bias[ec + q * 8]; b1 = bias[ec + q * 8 + 1]; }
            float x0 = acc[mi][q][0] + b0, x1 = acc[mi][q][1] + b1;
            float x2 = acc[mi][q][2] + b0, x3 = acc[mi][q][3] + b1;
            size_t off0 = (size_t)(er + mi * 16) * CDIM + ec + q * 8;
            size_t off1 = (size_t)(er + mi * 16 + 8) * CDIM + ec + q * 8;
            if (HiO) {
                uint32_t h0 = pack_hi(x0, x1), h1 = pack_hi(x2, x3);
                uint32_t l0 = pack_lo(x0, x1, h0), l1 = pack_lo(x2, x3, h1);
                *(uint32_t*)(HiO + off0) = h0;
                *(uint32_t*)(HiO + off1) = h1;
                *(uint32_t*)(LoO + off0) = l0;
                *(uint32_t*)(LoO + off1) = l1;
            } else {
                float2 v0 = { x0, x1 };
                float2 v1 = { x2, x3 };
                *(float2*)&Cout[off0] = v0;
                *(float2*)&Cout[off1] = v1;
            }
        }
    }
}

// ---------------------------------------------------------------------------
// Flash attention on mma.sync, split-bf16 QK and PV (3 passes each).
// CTA: 128 q rows x one (b,h). 8 warps x 16 rows. K/V 128-key tiles,
// hi/lo bf16, cp.async double-buffered. Output written as bf16 hi/lo split.
// ---------------------------------------------------------------------------
#define KV_PITCH 144
#define KV_TILE  (128 * KV_PITCH)      // 18432
#define AT_STAGE (4 * KV_TILE)         // 73728
#define AT_SMEM  (2 * AT_STAGE)        // 147456

__device__ __forceinline__ void at_load(const __nv_bfloat16* __restrict__ g,
                                        size_t gbase, uint32_t sbase, int tid)
{
#pragma unroll
    for (int i = 0; i < 4; i++) {
        int idx = tid + i * 256;       // 0..1023
        int rr = idx >> 3;
        int ch = idx & 7;
        cp16(sbase + rr * KV_PITCH + ch * 16,
             g + gbase + (size_t)rr * CDIM + ch * 8);
    }
}

__global__ void __launch_bounds__(256, 1)
attn_mma_kernel(const __nv_bfloat16* __restrict__ qhi,
                const __nv_bfloat16* __restrict__ qlo,
                const __nv_bfloat16* __restrict__ khi,
                const __nv_bfloat16* __restrict__ klo,
                const __nv_bfloat16* __restrict__ vhi,
                const __nv_bfloat16* __restrict__ vlo,
                __nv_bfloat16* __restrict__ ohi,
                __nv_bfloat16* __restrict__ olo)
{
    extern __shared__ __align__(128) char smem[];
    const uint32_t sb = smem_u32(smem);
    const int tid  = threadIdx.x;
    const int lane = tid & 31;
    const int warp = tid >> 5;
    const int m0   = blockIdx.x * 128;
    const int h    = blockIdx.y;
    const int b    = blockIdx.z;

    const int r  = lane >> 2;
    const int c2 = (lane & 3) * 2;

    // Q fragments (registers, whole loop)
    uint32_t Qh[4][4], Ql[4][4];
    {
        size_t qbase = ((size_t)(b * NQ + m0 + warp * 16)) * CDIM + h * HDIM;
#pragma unroll
        for (int ks = 0; ks < 4; ks++) {
            int col = ks * 16 + c2;
            Qh[ks][0] = *(const uint32_t*)(qhi + qbase + (size_t)r * CDIM + col);
            Qh[ks][1] = *(const uint32_t*)(qhi + qbase + (size_t)(r + 8) * CDIM + col);
            Qh[ks][2] = *(const uint32_t*)(qhi + qbase + (size_t)r * CDIM + col + 8);
            Qh[ks][3] = *(const uint32_t*)(qhi + qbase + (size_t)(r + 8) * CDIM + col + 8);
            Ql[ks][0] = *(const uint32_t*)(qlo + qbase + (size_t)r * CDIM + col);
            Ql[ks][1] = *(const uint32_t*)(qlo + qbase + (size_t)(r + 8) * CDIM + col);
            Ql[ks][2] = *(const uint32_t*)(qlo + qbase + (size_t)r * CDIM + col + 8);
            Ql[ks][3] = *(const uint32_t*)(qlo + qbase + (size_t)(r + 8) * CDIM + col + 8);
        }
    }

    const size_t kgbase = ((size_t)(b * NK)) * CDIM + h * HDIM;

    // Prefetch tile 0
    at_load(khi, kgbase, sb + 0 * KV_TILE, tid);
    at_load(klo, kgbase, sb + 1 * KV_TILE, tid);
    at_load(vhi, kgbase, sb + 2 * KV_TILE, tid);
    at_load(vlo, kgbase, sb + 3 * KV_TILE, tid);
    asm volatile("cp.async.commit_group;" ::: "memory");

    float m[2] = { -1e30f, -1e30f };
    float l[2] = { 0.f, 0.f };
    float o[8][4];
#pragma unroll
    for (int nb = 0; nb < 8; nb++)
#pragma unroll
        for (int t = 0; t < 4; t++) o[nb][t] = 0.f;

    const int krow_off = ((lane >> 4) & 1) * 8 + (lane & 7);
    const int kcol_off = ((lane >> 3) & 1) * 16;          // bytes
    const int vrow_off = (lane & 7) + ((lane >> 3) & 1) * 8;
    const int vcol_off = (lane >> 4) * 16;                 // bytes
    const float L2E = 1.44269504f;

    for (int t = 0; t < NK / 128; t++) {
        if (t + 1 < NK / 128) {
            uint32_t st = sb + ((t + 1) & 1) * AT_STAGE;
            size_t gb2 = kgbase + (size_t)(t + 1) * 128 * CDIM;
            at_load(khi, gb2, st + 0 * KV_TILE, tid);
            at_load(klo, gb2, st + 1 * KV_TILE, tid);
            at_load(vhi, gb2, st + 2 * KV_TILE, tid);
            at_load(vlo, gb2, st + 3 * KV_TILE, tid);
        }
        asm volatile("cp.async.commit_group;" ::: "memory");
        asm volatile("cp.async.wait_group 1;" ::: "memory");
        __syncthreads();

        const uint32_t stg  = sb + (t & 1) * AT_STAGE;
        const uint32_t kHiB = stg + 0 * KV_TILE;
        const uint32_t kLoB = stg + 1 * KV_TILE;
        const uint32_t vHiB = stg + 2 * KV_TILE;
        const uint32_t vLoB = stg + 3 * KV_TILE;

        // --- scores ---
        float sc[16][4];
#pragma unroll
        for (int nb = 0; nb < 16; nb++)
#pragma unroll
            for (int u = 0; u < 4; u++) sc[nb][u] = 0.f;

#pragma unroll
        for (int nj = 0; nj < 8; nj++) {
#pragma unroll
            for (int ks = 0; ks < 4; ks++) {
                uint32_t kh[4], kl[4];
                uint32_t off = (uint32_t)((nj * 16 + krow_off) * KV_PITCH
                                          + ks * 32 + kcol_off);
                ldm_x4(kh, kHiB + off);
                ldm_x4(kl, kLoB + off);
#pragma unroll
                for (int nb = 0; nb < 2; nb++) {
                    float* cc = sc[nj * 2 + nb];
                    mma_bf16(cc, Qh[ks], kh[nb * 2], kh[nb * 2 + 1]);
                    mma_bf16(cc, Qh[ks], kl[nb * 2], kl[nb * 2 + 1]);
                    mma_bf16(cc, Ql[ks], kh[nb * 2], kh[nb * 2 + 1]);
                }
            }
        }

        // --- softmax (rows r, r+8) ---
#pragma unroll
        for (int i = 0; i < 2; i++) {
            float mx = sc[0][2 * i];
#pragma unroll
            for (int nb = 0; nb < 16; nb++)
                mx = fmaxf(mx, fmaxf(sc[nb][2 * i], sc[nb][2 * i + 1]));
            mx = fmaxf(mx, __shfl_xor_sync(0xFFFFFFFFu, mx, 1));
            mx = fmaxf(mx, __shfl_xor_sync(0xFFFFFFFFu, mx, 2));
            float mn = fmaxf(m[i], mx);
            float corr = exp2f((m[i] - mn) * L2E);
            m[i] = mn;
            float mnL = mn * L2E;
            float ls = 0.f;
#pragma unroll
            for (int nb = 0; nb < 16; nb++) {
                float p0 = exp2f(fmaf(sc[nb][2 * i], L2E, -mnL));
                float p1 = exp2f(fmaf(sc[nb][2 * i + 1], L2E, -mnL));
                sc[nb][2 * i] = p0;
                sc[nb][2 * i + 1] = p1;
                ls += p0 + p1;
            }
            l[i] = l[i] * corr + ls;
#pragma unroll
            for (int nb = 0; nb < 8; nb++) {
                o[nb][2 * i]     *= corr;
                o[nb][2 * i + 1] *= corr;
            }
        }

        // --- PV ---
#pragma unroll
        for (int j = 0; j < 8; j++) {
            uint32_t Ph[4], Pl[4];
            Ph[0] = pack_hi(sc[2 * j][0],     sc[2 * j][1]);
            Ph[1] = pack_hi(sc[2 * j][2],     sc[2 * j][3]);
            Ph[2] = pack_hi(sc[2 * j + 1][0], sc[2 * j + 1][1]);
            Ph[3] = pack_hi(sc[2 * j + 1][2], sc[2 * j + 1][3]);
            Pl[0] = pack_lo(sc[2 * j][0],     sc[2 * j][1],     Ph[0]);
            Pl[1] = pack_lo(sc[2 * j][2],     sc[2 * j][3],     Ph[1]);
            Pl[2] = pack_lo(sc[2 * j + 1][0], sc[2 * j + 1][1], Ph[2]);
            Pl[3] = pack_lo(sc[2 * j + 1][2], sc[2 * j + 1][3], Ph[3]);
#pragma unroll
            for (int g = 0; g < 4; g++) {
                uint32_t vh[4], vl[4];
                uint32_t off = (uint32_t)((j * 16 + vrow_off) * KV_PITCH
                                          + g * 32 + vcol_off);
                ldm_x4_t(vh, vHiB + off);
                ldm_x4_t(vl, vLoB + off);
#pragma unroll
                for (int nb = 0; nb < 2; nb++) {
                    float* oo = o[g * 2 + nb];
                    mma_bf16(oo, Ph, vh[nb * 2], vh[nb * 2 + 1]);
                    mma_bf16(oo, Ph, vl[nb * 2], vl[nb * 2 + 1]);
                    mma_bf16(oo, Pl, vh[nb * 2], vh[nb * 2 + 1]);
                }
            }
        }
        __syncthreads();
    }

    // Epilogue: reduce l over lane quads, normalize, write bf16 hi/lo
    float inv[2];
#pragma unroll
    for (int i = 0; i < 2; i++) {
        float lt = l[i];
        lt += __shfl_xor_sync(0xFFFFFFFFu, lt, 1);
        lt += __shfl_xor_sync(0xFFFFFFFFu, lt, 2);
        inv[i] = 1.f / lt;
    }
    size_t obase = ((size_t)(b * NQ + m0 + warp * 16)) * CDIM + h * HDIM;
#pragma unroll
    for (int nb = 0; nb < 8; nb++) {
#pragma unroll
        for (int i = 0; i < 2; i++) {
            float x0 = o[nb][2 * i] * inv[i];
            float x1 = o[nb][2 * i + 1] * inv[i];
            uint32_t hh = pack_hi(x0, x1);
            uint32_t ll = pack_lo(x0, x1, hh);
            size_t off = obase + (size_t)(r + i * 8) * CDIM + nb * 8 + c2;
            *(uint32_t*)(ohi + off) = hh;
            *(uint32_t*)(olo + off) = ll;
        }
    }
}

// ---------------------------------------------------------------------------
// Launcher
// ---------------------------------------------------------------------------
static void run_split(const float* src, __nv_bfloat16* hi, __nv_bfloat16* lo, int n)
{
    int n4 = n / 4;
    split_bf16_kernel<<<(n4 + 255) / 256, 256>>>(
        (const float4*)src, (__nv_bfloat162*)hi, (__nv_bfloat162*)lo, n4);
}

extern "C" void kernel_launch(void* const* d_in, const int* in_sizes, int n_in,
                              void* d_out, int out_size)
{
    const float* query = (const float*)d_in[0];
    const float* key   = (const float*)d_in[1];
    const float* value = (const float*)d_in[2];
    const int*   qpos  = (const int*)  d_in[3];
    const int*   kpos  = (const int*)  d_in[4];
    const float* Wq    = (const float*)d_in[5];
    const float* Wk    = (const float*)d_in[6];
    const float* Wv    = (const float*)d_in[7];
    const float* Wp    = (const float*)d_in[8];
    const float* bp    = (const float*)d_in[9];
    float* out = (float*)d_out;

    float *tq, *tk;
    __nv_bfloat16 *ahi, *alo, *whi, *wlo, *qhi, *qlo, *khi, *klo, *vhi, *vlo;
    cudaGetSymbolAddress((void**)&tq, g_tmp_q);
    cudaGetSymbolAddress((void**)&tk, g_tmp_k);
    cudaGetSymbolAddress((void**)&ahi, g_ahi);
    cudaGetSymbolAddress((void**)&alo, g_alo);
    cudaGetSymbolAddress((void**)&whi, g_whi);
    cudaGetSymbolAddress((void**)&wlo, g_wlo);
    cudaGetSymbolAddress((void**)&qhi, g_qhi);
    cudaGetSymbolAddress((void**)&qlo, g_qlo);
    cudaGetSymbolAddress((void**)&khi, g_khi);
    cudaGetSymbolAddress((void**)&klo, g_klo);
    cudaGetSymbolAddress((void**)&vhi, g_vhi);
    cudaGetSymbolAddress((void**)&vlo, g_vlo);

    cudaFuncSetAttribute(gemm_mma_kernel,
                         cudaFuncAttributeMaxDynamicSharedMemorySize, GM_SMEM);
    cudaFuncSetAttribute(attn_mma_kernel,
                         cudaFuncAttributeMaxDynamicSharedMemorySize, AT_SMEM);

    const int Mq = Bsz * NQ;   // 2048
    const int Mk = Bsz * NK;   // 8192

    // Q projection -> fp32 tq
    run_split(query, ahi, alo, Mq * CDIM);
    run_split(Wq, whi, wlo, CDIM * CDIM);
    gemm_mma_kernel<<<dim3(CDIM / 128, Mq / 128), 256, GM_SMEM>>>(
        ahi, alo, whi, wlo, nullptr, tq, nullptr, nullptr);

    // K projection -> fp32 tk
    run_split(key, ahi, alo, Mk * CDIM);
    run_split(Wk, whi, wlo, CDIM * CDIM);
    gemm_mma_kernel<<<dim3(CDIM / 128, Mk / 128), 256, GM_SMEM>>>(
        ahi, alo, whi, wlo, nullptr, tk, nullptr, nullptr);

    // V projection -> bf16 split directly
    run_split(value, ahi, alo, Mk * CDIM);
    run_split(Wv, whi, wlo, CDIM * CDIM);
    gemm_mma_kernel<<<dim3(CDIM / 128, Mk / 128), 256, GM_SMEM>>>(
        ahi, alo, whi, wlo, nullptr, nullptr, vhi, vlo);

    // RoPE + split (q scaled by 1/sqrt(D))
    rope_split_kernel<<<(Mq * 512 + 255) / 256, 256>>>(tq, qpos, qhi, qlo, Mq, 0.125f);
    rope_split_kernel<<<(Mk * 512 + 255) / 256, 256>>>(tk, kpos, khi, klo, Mk, 1.0f);

    // Attention -> bf16 split output into ahi/alo
    attn_mma_kernel<<<dim3(NQ / 128, NHEADS, Bsz), 256, AT_SMEM>>>(
        qhi, qlo, khi, klo, vhi, vlo, ahi, alo);

    // Output projection + bias
    run_split(Wp, whi, wlo, CDIM * CDIM);
    gemm_mma_kernel<<<dim3(CDIM / 128, Mq / 128), 256, GM_SMEM>>>(
        ahi, alo, whi, wlo, bp, out, nullptr, nullptr);
}

// round 6
// speedup vs baseline: 2.9683x; 1.0306x over previous
#include <cuda_runtime.h>
#include <cuda_bf16.h>
#include <cstdint>
#include <cstddef>

// Problem constants
#define Bsz 4
#define NQ  512
#define NK  2048
#define CDIM 1024
#define NHEADS 16
#define HDIM 64

// ---------------------------------------------------------------------------
// Scratch (device globals — no allocation allowed)
// ---------------------------------------------------------------------------
__device__ __nv_bfloat16 g_inq_hi[(size_t)Bsz * NQ * CDIM];
__device__ __nv_bfloat16 g_inq_lo[(size_t)Bsz * NQ * CDIM];
__device__ __nv_bfloat16 g_ink_hi[(size_t)Bsz * NK * CDIM];
__device__ __nv_bfloat16 g_ink_lo[(size_t)Bsz * NK * CDIM];
__device__ __nv_bfloat16 g_inv_hi[(size_t)Bsz * NK * CDIM];
__device__ __nv_bfloat16 g_inv_lo[(size_t)Bsz * NK * CDIM];
__device__ __nv_bfloat16 g_w_hi[(size_t)4 * CDIM * CDIM];   // Wq,Wk,Wv,Wp
__device__ __nv_bfloat16 g_w_lo[(size_t)4 * CDIM * CDIM];
__device__ __nv_bfloat16 g_qhi[(size_t)Bsz * NQ * CDIM];
__device__ __nv_bfloat16 g_qlo[(size_t)Bsz * NQ * CDIM];
__device__ __nv_bfloat16 g_khi[(size_t)Bsz * NK * CDIM];
__device__ __nv_bfloat16 g_klo[(size_t)Bsz * NK * CDIM];
__device__ __nv_bfloat16 g_vhi[(size_t)Bsz * NK * CDIM];
__device__ __nv_bfloat16 g_vlo[(size_t)Bsz * NK * CDIM];
__device__ __nv_bfloat16 g_ohi[(size_t)Bsz * NQ * CDIM];
__device__ __nv_bfloat16 g_olo[(size_t)Bsz * NQ * CDIM];

// ---------------------------------------------------------------------------
// Common helpers
// ---------------------------------------------------------------------------
__device__ __forceinline__ uint32_t smem_u32(const void* p) {
    uint32_t a;
    asm("{ .reg .u64 t; cvta.to.shared.u64 t, %1; cvt.u32.u64 %0, t; }"
        : "=r"(a) : "l"(p));
    return a;
}

__device__ __forceinline__ void cp16(uint32_t dst, const void* src) {
    asm volatile("cp.async.cg.shared.global [%0], [%1], 16;"
                 :: "r"(dst), "l"(src) : "memory");
}

__device__ __forceinline__ void ldm_x4(uint32_t* r, uint32_t addr) {
    asm volatile("ldmatrix.sync.aligned.m8n8.x4.shared.b16 {%0,%1,%2,%3}, [%4];"
                 : "=r"(r[0]), "=r"(r[1]), "=r"(r[2]), "=r"(r[3]) : "r"(addr));
}

__device__ __forceinline__ void ldm_x4_t(uint32_t* r, uint32_t addr) {
    asm volatile("ldmatrix.sync.aligned.m8n8.x4.trans.shared.b16 {%0,%1,%2,%3}, [%4];"
                 : "=r"(r[0]), "=r"(r[1]), "=r"(r[2]), "=r"(r[3]) : "r"(addr));
}

__device__ __forceinline__ void mma_bf16(float* c, const uint32_t* a,
                                         uint32_t b0, uint32_t b1) {
    asm volatile(
        "mma.sync.aligned.m16n8k16.row.col.f32.bf16.bf16.f32 "
        "{%0,%1,%2,%3}, {%4,%5,%6,%7}, {%8,%9}, {%0,%1,%2,%3};"
        : "+f"(c[0]), "+f"(c[1]), "+f"(c[2]), "+f"(c[3])
        : "r"(a[0]), "r"(a[1]), "r"(a[2]), "r"(a[3]), "r"(b0), "r"(b1));
}

__device__ __forceinline__ uint32_t pack_hi(float a, float b) {
    __nv_bfloat162 t = __floats2bfloat162_rn(a, b);
    return *(uint32_t*)&t;
}
__device__ __forceinline__ uint32_t pack_lo(float a, float b, uint32_t hi) {
    __nv_bfloat162 h = *(__nv_bfloat162*)&hi;
    float2 f = __bfloat1622float2(h);
    __nv_bfloat162 t = __floats2bfloat162_rn(a - f.x, b - f.y);
    return *(uint32_t*)&t;
}

__device__ __forceinline__ void split4(float4 a, __nv_bfloat162* hi,
                                       __nv_bfloat162* lo) {
    __nv_bfloat162 h01 = __floats2bfloat162_rn(a.x, a.y);
    __nv_bfloat162 h23 = __floats2bfloat162_rn(a.z, a.w);
    float2 f01 = __bfloat1622float2(h01);
    float2 f23 = __bfloat1622float2(h23);
    hi[0] = h01;
    hi[1] = h23;
    lo[0] = __floats2bfloat162_rn(a.x - f01.x, a.y - f01.y);
    lo[1] = __floats2bfloat162_rn(a.z - f23.x, a.w - f23.y);
}

// ---------------------------------------------------------------------------
// Input split: query + key + value in one launch (fp32 -> bf16 hi/lo)
// ---------------------------------------------------------------------------
#define QN4 ((Bsz * NQ * CDIM) / 4)      // 524288
#define KN4 ((Bsz * NK * CDIM) / 4)      // 2097152

__global__ void input_split_kernel(const float4* __restrict__ q,
                                   const float4* __restrict__ k,
                                   const float4* __restrict__ v)
{
    int idx = blockIdx.x * blockDim.x + threadIdx.x;
    const float4* src;
    __nv_bfloat162 *hi, *lo;
    int off;
    if (idx < QN4) {
        src = q; off = idx;
        hi = (__nv_bfloat162*)g_inq_hi; lo = (__nv_bfloat162*)g_inq_lo;
    } else if (idx < QN4 + KN4) {
        src = k; off = idx - QN4;
        hi = (__nv_bfloat162*)g_ink_hi; lo = (__nv_bfloat162*)g_ink_lo;
    } else {
        src = v; off = idx - QN4 - KN4;
        hi = (__nv_bfloat162*)g_inv_hi; lo = (__nv_bfloat162*)g_inv_lo;
    }
    split4(src[off], hi + off * 2, lo + off * 2);
}

// ---------------------------------------------------------------------------
// Weight split: all four W matrices in one launch
// ---------------------------------------------------------------------------
#define WN4 ((CDIM * CDIM) / 4)          // 262144

__global__ void w_split_kernel(const float4* __restrict__ wq,
                               const float4* __restrict__ wk,
                               const float4* __restrict__ wv,
                               const float4* __restrict__ wp)
{
    int idx = blockIdx.x * blockDim.x + threadIdx.x;
    int seg = idx / WN4;
    int off = idx - seg * WN4;
    const float4* src = (seg == 0) ? wq : (seg == 1) ? wk : (seg == 2) ? wv : wp;
    __nv_bfloat162* hi = (__nv_bfloat162*)(g_w_hi + (size_t)seg * CDIM * CDIM);
    __nv_bfloat162* lo = (__nv_bfloat162*)(g_w_lo + (size_t)seg * CDIM * CDIM);
    split4(src[off], hi + off * 2, lo + off * 2);
}

// ---------------------------------------------------------------------------
// Shared GEMM mainloop pieces (128x128 tile, BK=32, 8 warps, 3 passes)
// ---------------------------------------------------------------------------
#define PITCH_B 80
#define TILE_B  (128 * PITCH_B)
#define STAGE_B (4 * TILE_B)
#define GM_SMEM (2 * STAGE_B)

__device__ __forceinline__ void load_tile_async(const __nv_bfloat16* __restrict__ g,
                                                int row0, int k0,
                                                uint32_t sbase, int tid)
{
#pragma unroll
    for (int i = 0; i < 2; i++) {
        int idx = tid + i * 256;
        int r = idx >> 2;
        int j = idx & 3;
        cp16(sbase + r * PITCH_B + j * 16,
             g + (size_t)(row0 + r) * CDIM + k0 + j * 8);
    }
}

// Mainloop: accumulates into acc[2][8][4]. Caller provides smem base.
__device__ __forceinline__ void gemm_mainloop(
    const __nv_bfloat16* __restrict__ Ahi, const __nv_bfloat16* __restrict__ Alo,
    const __nv_bfloat16* __restrict__ Whi, const __nv_bfloat16* __restrict__ Wlo,
    int m0, int n0, uint32_t sb, int tid, float acc[2][8][4])
{
    const int lane = tid & 31;
    const int warp = tid >> 5;
    const int wm   = warp >> 1;
    const int wn   = warp & 1;

    const int arow = wm * 32 + ((lane >> 3) & 1) * 8 + (lane & 7);
    const int acol = (lane >> 4) * 8;
    const int brow = wn * 64 + ((lane >> 4) & 1) * 8 + (lane & 7);
    const int bcol = ((lane >> 3) & 1) * 8;

    load_tile_async(Ahi, m0, 0, sb + 0 * TILE_B, tid);
    load_tile_async(Alo, m0, 0, sb + 1 * TILE_B, tid);
    load_tile_async(Whi, n0, 0, sb + 2 * TILE_B, tid);
    load_tile_async(Wlo, n0, 0, sb + 3 * TILE_B, tid);
    asm volatile("cp.async.commit_group;" ::: "memory");

    const int NCHUNK = CDIM / 32;
    for (int c = 0; c < NCHUNK; c++) {
        if (c + 1 < NCHUNK) {
            uint32_t st = sb + ((c + 1) & 1) * STAGE_B;
            int k0 = (c + 1) * 32;
            load_tile_async(Ahi, m0, k0, st + 0 * TILE_B, tid);
            load_tile_async(Alo, m0, k0, st + 1 * TILE_B, tid);
            load_tile_async(Whi, n0, k0, st + 2 * TILE_B, tid);
            load_tile_async(Wlo, n0, k0, st + 3 * TILE_B, tid);
        }
        asm volatile("cp.async.commit_group;" ::: "memory");
        asm volatile("cp.async.wait_group 1;" ::: "memory");
        __syncthreads();

        const uint32_t stg  = sb + (c & 1) * STAGE_B;
        const uint32_t aHiB = stg + 0 * TILE_B;
        const uint32_t aLoB = stg + 1 * TILE_B;
        const uint32_t wHiB = stg + 2 * TILE_B;
        const uint32_t wLoB = stg + 3 * TILE_B;

#pragma unroll
        for (int s = 0; s < 2; s++) {
            const int kk = s * 16;
            uint32_t Ah[2][4], Al[2][4], Wh[4][4], Wl[4][4];
#pragma unroll
            for (int mi = 0; mi < 2; mi++) {
                uint32_t off = (uint32_t)((arow + mi * 16) * PITCH_B + (kk + acol) * 2);
                ldm_x4(Ah[mi], aHiB + off);
                ldm_x4(Al[mi], aLoB + off);
            }
#pragma unroll
            for (int nj = 0; nj < 4; nj++) {
                uint32_t off = (uint32_t)((brow + nj * 16) * PITCH_B + (kk + bcol) * 2);
                ldm_x4(Wh[nj], wHiB + off);
                ldm_x4(Wl[nj], wLoB + off);
            }
#pragma unroll
            for (int mi = 0; mi < 2; mi++)
#pragma unroll
                for (int q = 0; q < 8; q++)
                    mma_bf16(acc[mi][q], Ah[mi],
                             Wh[q >> 1][(q & 1) * 2], Wh[q >> 1][(q & 1) * 2 + 1]);
#pragma unroll
            for (int mi = 0; mi < 2; mi++)
#pragma unroll
                for (int q = 0; q < 8; q++)
                    mma_bf16(acc[mi][q], Ah[mi],
                             Wl[q >> 1][(q & 1) * 2], Wl[q >> 1][(q & 1) * 2 + 1]);
#pragma unroll
            for (int mi = 0; mi < 2; mi++)
#pragma unroll
                for (int q = 0; q < 8; q++)
                    mma_bf16(acc[mi][q], Al[mi],
                             Wh[q >> 1][(q & 1) * 2], Wh[q >> 1][(q & 1) * 2 + 1]);
        }
        __syncthreads();
    }
}

// ---------------------------------------------------------------------------
// Fused QKV projection: 1152 tiles in one launch.
//   gemm 0: Q proj -> RoPE(qpos, scale 1/8)  -> g_qhi/g_qlo
//   gemm 1: K proj -> RoPE(kpos, scale 1)    -> g_khi/g_klo
//   gemm 2: V proj -> plain split            -> g_vhi/g_vlo
// ---------------------------------------------------------------------------
__global__ void __launch_bounds__(256)
qkv_proj_kernel(const int* __restrict__ qpos, const int* __restrict__ kpos)
{
    extern __shared__ __align__(128) char smem[];
    const uint32_t sb = smem_u32(smem);
    const int tid  = threadIdx.x;
    const int lane = tid & 31;
    const int warp = tid >> 5;
    const int t    = blockIdx.x;

    int gemm, local;
    if (t < 512)       { gemm = 1; local = t; }          // K first (largest)
    else if (t < 1024) { gemm = 2; local = t - 512; }    // V
    else               { gemm = 0; local = t - 1024; }   // Q
    const int m0 = (local >> 3) * 128;
    const int n0 = (local & 7) * 128;

    const __nv_bfloat16 *Ah, *Al, *Wh, *Wl;
    if (gemm == 0) { Ah = g_inq_hi; Al = g_inq_lo; Wh = g_w_hi; Wl = g_w_lo; }
    else if (gemm == 1) {
        Ah = g_ink_hi; Al = g_ink_lo;
        Wh = g_w_hi + (size_t)CDIM * CDIM; Wl = g_w_lo + (size_t)CDIM * CDIM;
    } else {
        Ah = g_inv_hi; Al = g_inv_lo;
        Wh = g_w_hi + (size_t)2 * CDIM * CDIM; Wl = g_w_lo + (size_t)2 * CDIM * CDIM;
    }

    float acc[2][8][4];
#pragma unroll
    for (int mi = 0; mi < 2; mi++)
#pragma unroll
        for (int q = 0; q < 8; q++)
#pragma unroll
            for (int u = 0; u < 4; u++) acc[mi][q][u] = 0.f;

    gemm_mainloop(Ah, Al, Wh, Wl, m0, n0, sb, tid, acc);

    const int wm = warp >> 1;
    const int wn = warp & 1;
    const int er = m0 + wm * 32 + (lane >> 2);
    const int ec = n0 + wn * 64 + (lane & 3) * 2;

    if (gemm == 2) {
        // plain split epilogue
#pragma unroll
        for (int mi = 0; mi < 2; mi++) {
#pragma unroll
            for (int q = 0; q < 8; q++) {
                size_t off0 = (size_t)(er + mi * 16) * CDIM + ec + q * 8;
                size_t off1 = (size_t)(er + mi * 16 + 8) * CDIM + ec + q * 8;
                uint32_t h0 = pack_hi(acc[mi][q][0], acc[mi][q][1]);
                uint32_t h1 = pack_hi(acc[mi][q][2], acc[mi][q][3]);
                *(uint32_t*)(g_vhi + off0) = h0;
                *(uint32_t*)(g_vhi + off1) = h1;
                *(uint32_t*)(g_vlo + off0) = pack_lo(acc[mi][q][0], acc[mi][q][1], h0);
                *(uint32_t*)(g_vlo + off1) = pack_lo(acc[mi][q][2], acc[mi][q][3], h1);
            }
        }
        return;
    }

    // RoPE epilogue (gemm 0 or 1)
    const int* posarr = (gemm == 0) ? qpos : kpos;
    const float scale = (gemm == 0) ? 0.125f : 1.0f;
    __nv_bfloat16* dsthi = (gemm == 0) ? g_qhi : g_khi;
    __nv_bfloat16* dstlo = (gemm == 0) ? g_qlo : g_klo;
    const float kf = 13.2877123795494f / 32.0f;   // log2(10000)/32

    float invf[8];
#pragma unroll
    for (int qp = 0; qp < 4; qp++)
#pragma unroll
        for (int c = 0; c < 2; c++) {
            int j = (lane & 3) * 2 + qp * 8 + c;
            invf[qp * 2 + c] = exp2f(-(float)j * kf);
        }

#pragma unroll
    for (int mi = 0; mi < 2; mi++) {
#pragma unroll
        for (int tr = 0; tr < 2; tr++) {
            const int row = er + mi * 16 + tr * 8;
            const float p = (float)posarr[row];
#pragma unroll
            for (int qp = 0; qp < 4; qp++) {
                float y1[2], y2[2];
#pragma unroll
                for (int c = 0; c < 2; c++) {
                    float ang = p * invf[qp * 2 + c];
                    float s, co;
                    sincosf(ang, &s, &co);
                    float x1 = acc[mi][qp][tr * 2 + c];
                    float x2 = acc[mi][qp + 4][tr * 2 + c];
                    y1[c] = (x1 * co - x2 * s) * scale;
                    y2[c] = (x2 * co + x1 * s) * scale;
                }
                size_t offA = (size_t)row * CDIM + ec + qp * 8;
                size_t offB = (size_t)row * CDIM + ec + (qp + 4) * 8;
                uint32_t hA = pack_hi(y1[0], y1[1]);
                uint32_t hB = pack_hi(y2[0], y2[1]);
                *(uint32_t*)(dsthi + offA) = hA;
                *(uint32_t*)(dsthi + offB) = hB;
                *(uint32_t*)(dstlo + offA) = pack_lo(y1[0], y1[1], hA);
                *(uint32_t*)(dstlo + offB) = pack_lo(y2[0], y2[1], hB);
            }
        }
    }
}

// ---------------------------------------------------------------------------
// Output projection GEMM (fp32 out + bias)
// ---------------------------------------------------------------------------
__global__ void __launch_bounds__(256)
out_proj_kernel(const float* __restrict__ bias, float* __restrict__ Cout)
{
    extern __shared__ __align__(128) char smem[];
    const uint32_t sb = smem_u32(smem);
    const int tid  = threadIdx.x;
    const int lane = tid & 31;
    const int warp = tid >> 5;
    const int m0   = blockIdx.y * 128;
    const int n0   = blockIdx.x * 128;

    float acc[2][8][4];
#pragma unroll
    for (int mi = 0; mi < 2; mi++)
#pragma unroll
        for (int q = 0; q < 8; q++)
#pragma unroll
            for (int u = 0; u < 4; u++) acc[mi][q][u] = 0.f;

    gemm_mainloop(g_ohi, g_olo,
                  g_w_hi + (size_t)3 * CDIM * CDIM, g_w_lo + (size_t)3 * CDIM * CDIM,
                  m0, n0, sb, tid, acc);

    const int wm = warp >> 1;
    const int wn = warp & 1;
    const int er = m0 + wm * 32 + (lane >> 2);
    const int ec = n0 + wn * 64 + (lane & 3) * 2;
#pragma unroll
    for (int mi = 0; mi < 2; mi++) {
#pragma unroll
        for (int q = 0; q < 8; q++) {
            float b0 = bias[ec + q * 8];
            float b1 = bias[ec + q * 8 + 1];
            float2 v0 = { acc[mi][q][0] + b0, acc[mi][q][1] + b1 };
            float2 v1 = { acc[mi][q][2] + b0, acc[mi][q][3] + b1 };
            *(float2*)&Cout[(size_t)(er + mi * 16) * CDIM + ec + q * 8]     = v0;
            *(float2*)&Cout[(size_t)(er + mi * 16 + 8) * CDIM + ec + q * 8] = v1;
        }
    }
}

// ---------------------------------------------------------------------------
// Flash attention on mma.sync, split-bf16 QK and PV (3 passes each).
// ---------------------------------------------------------------------------
#define KV_PITCH 144
#define KV_TILE  (128 * KV_PITCH)
#define AT_STAGE (4 * KV_TILE)
#define AT_SMEM  (2 * AT_STAGE)

__device__ __forceinline__ void at_load(const __nv_bfloat16* __restrict__ g,
                                        size_t gbase, uint32_t sbase, int tid)
{
#pragma unroll
    for (int i = 0; i < 4; i++) {
        int idx = tid + i * 256;
        int rr = idx >> 3;
        int ch = idx & 7;
        cp16(sbase + rr * KV_PITCH + ch * 16,
             g + gbase + (size_t)rr * CDIM + ch * 8);
    }
}

__global__ void __launch_bounds__(256, 1)
attn_mma_kernel()
{
    extern __shared__ __align__(128) char smem[];
    const uint32_t sb = smem_u32(smem);
    const int tid  = threadIdx.x;
    const int lane = tid & 31;
    const int warp = tid >> 5;
    const int m0   = blockIdx.x * 128;
    const int h    = blockIdx.y;
    const int b    = blockIdx.z;

    const int r  = lane >> 2;
    const int c2 = (lane & 3) * 2;

    uint32_t Qh[4][4], Ql[4][4];
    {
        size_t qbase = ((size_t)(b * NQ + m0 + warp * 16)) * CDIM + h * HDIM;
#pragma unroll
        for (int ks = 0; ks < 4; ks++) {
            int col = ks * 16 + c2;
            Qh[ks][0] = *(const uint32_t*)(g_qhi + qbase + (size_t)r * CDIM + col);
            Qh[ks][1] = *(const uint32_t*)(g_qhi + qbase + (size_t)(r + 8) * CDIM + col);
            Qh[ks][2] = *(const uint32_t*)(g_qhi + qbase + (size_t)r * CDIM + col + 8);
            Qh[ks][3] = *(const uint32_t*)(g_qhi + qbase + (size_t)(r + 8) * CDIM + col + 8);
            Ql[ks][0] = *(const uint32_t*)(g_qlo + qbase + (size_t)r * CDIM + col);
            Ql[ks][1] = *(const uint32_t*)(g_qlo + qbase + (size_t)(r + 8) * CDIM + col);
            Ql[ks][2] = *(const uint32_t*)(g_qlo + qbase + (size_t)r * CDIM + col + 8);
            Ql[ks][3] = *(const uint32_t*)(g_qlo + qbase + (size_t)(r + 8) * CDIM + col + 8);
        }
    }

    const size_t kgbase = ((size_t)(b * NK)) * CDIM + h * HDIM;

    at_load(g_khi, kgbase, sb + 0 * KV_TILE, tid);
    at_load(g_klo, kgbase, sb + 1 * KV_TILE, tid);
    at_load(g_vhi, kgbase, sb + 2 * KV_TILE, tid);
    at_load(g_vlo, kgbase, sb + 3 * KV_TILE, tid);
    asm volatile("cp.async.commit_group;" ::: "memory");

    float m[2] = { -1e30f, -1e30f };
    float l[2] = { 0.f, 0.f };
    float o[8][4];
#pragma unroll
    for (int nb = 0; nb < 8; nb++)
#pragma unroll
        for (int u = 0; u < 4; u++) o[nb][u] = 0.f;

    const int krow_off = ((lane >> 4) & 1) * 8 + (lane & 7);
    const int kcol_off = ((lane >> 3) & 1) * 16;
    const int vrow_off = (lane & 7) + ((lane >> 3) & 1) * 8;
    const int vcol_off = (lane >> 4) * 16;
    const float L2E = 1.44269504f;

    for (int t = 0; t < NK / 128; t++) {
        if (t + 1 < NK / 128) {
            uint32_t st = sb + ((t + 1) & 1) * AT_STAGE;
            size_t gb2 = kgbase + (size_t)(t + 1) * 128 * CDIM;
            at_load(g_khi, gb2, st + 0 * KV_TILE, tid);
            at_load(g_klo, gb2, st + 1 * KV_TILE, tid);
            at_load(g_vhi, gb2, st + 2 * KV_TILE, tid);
            at_load(g_vlo, gb2, st + 3 * KV_TILE, tid);
        }
        asm volatile("cp.async.commit_group;" ::: "memory");
        asm volatile("cp.async.wait_group 1;" ::: "memory");
        __syncthreads();

        const uint32_t stg  = sb + (t & 1) * AT_STAGE;
        const uint32_t kHiB = stg + 0 * KV_TILE;
        const uint32_t kLoB = stg + 1 * KV_TILE;
        const uint32_t vHiB = stg + 2 * KV_TILE;
        const uint32_t vLoB = stg + 3 * KV_TILE;

        float sc[16][4];
#pragma unroll
        for (int nb = 0; nb < 16; nb++)
#pragma unroll
            for (int u = 0; u < 4; u++) sc[nb][u] = 0.f;

#pragma unroll
        for (int nj = 0; nj < 8; nj++) {
#pragma unroll
            for (int ks = 0; ks < 4; ks++) {
                uint32_t kh[4], kl[4];
                uint32_t off = (uint32_t)((nj * 16 + krow_off) * KV_PITCH
                                          + ks * 32 + kcol_off);
                ldm_x4(kh, kHiB + off);
                ldm_x4(kl, kLoB + off);
#pragma unroll
                for (int nb = 0; nb < 2; nb++) {
                    float* cc = sc[nj * 2 + nb];
                    mma_bf16(cc, Qh[ks], kh[nb * 2], kh[nb * 2 + 1]);
                    mma_bf16(cc, Qh[ks], kl[nb * 2], kl[nb * 2 + 1]);
                    mma_bf16(cc, Ql[ks], kh[nb * 2], kh[nb * 2 + 1]);
                }
            }
        }

#pragma unroll
        for (int i = 0; i < 2; i++) {
            float mx = sc[0][2 * i];
#pragma unroll
            for (int nb = 0; nb < 16; nb++)
                mx = fmaxf(mx, fmaxf(sc[nb][2 * i], sc[nb][2 * i + 1]));
            mx = fmaxf(mx, __shfl_xor_sync(0xFFFFFFFFu, mx, 1));
            mx = fmaxf(mx, __shfl_xor_sync(0xFFFFFFFFu, mx, 2));
            float mn = fmaxf(m[i], mx);
            float corr = exp2f((m[i] - mn) * L2E);
            m[i] = mn;
            float mnL = mn * L2E;
            float ls = 0.f;
#pragma unroll
            for (int nb = 0; nb < 16; nb++) {
                float p0 = exp2f(fmaf(sc[nb][2 * i], L2E, -mnL));
                float p1 = exp2f(fmaf(sc[nb][2 * i + 1], L2E, -mnL));
                sc[nb][2 * i] = p0;
                sc[nb][2 * i + 1] = p1;
                ls += p0 + p1;
            }
            l[i] = l[i] * corr + ls;
#pragma unroll
            for (int nb = 0; nb < 8; nb++) {
                o[nb][2 * i]     *= corr;
                o[nb][2 * i + 1] *= corr;
            }
        }

#pragma unroll
        for (int j = 0; j < 8; j++) {
            uint32_t Ph[4], Pl[4];
            Ph[0] = pack_hi(sc[2 * j][0],     sc[2 * j][1]);
            Ph[1] = pack_hi(sc[2 * j][2],     sc[2 * j][3]);
            Ph[2] = pack_hi(sc[2 * j + 1][0], sc[2 * j + 1][1]);
            Ph[3] = pack_hi(sc[2 * j + 1][2], sc[2 * j + 1][3]);
            Pl[0] = pack_lo(sc[2 * j][0],     sc[2 * j][1],     Ph[0]);
            Pl[1] = pack_lo(sc[2 * j][2],     sc[2 * j][3],     Ph[1]);
            Pl[2] = pack_lo(sc[2 * j + 1][0], sc[2 * j + 1][1], Ph[2]);
            Pl[3] = pack_lo(sc[2 * j + 1][2], sc[2 * j + 1][3], Ph[3]);
#pragma unroll
            for (int g = 0; g < 4; g++) {
                uint32_t vh[4], vl[4];
                uint32_t off = (uint32_t)((j * 16 + vrow_off) * KV_PITCH
                                          + g * 32 + vcol_off);
                ldm_x4_t(vh, vHiB + off);
                ldm_x4_t(vl, vLoB + off);
#pragma unroll
                for (int nb = 0; nb < 2; nb++) {
                    float* oo = o[g * 2 + nb];
                    mma_bf16(oo, Ph, vh[nb * 2], vh[nb * 2 + 1]);
                    mma_bf16(oo, Ph, vl[nb * 2], vl[nb * 2 + 1]);
                    mma_bf16(oo, Pl, vh[nb * 2], vh[nb * 2 + 1]);
                }
            }
        }
        __syncthreads();
    }

    float inv[2];
#pragma unroll
    for (int i = 0; i < 2; i++) {
        float lt = l[i];
        lt += __shfl_xor_sync(0xFFFFFFFFu, lt, 1);
        lt += __shfl_xor_sync(0xFFFFFFFFu, lt, 2);
        inv[i] = 1.f / lt;
    }
    size_t obase = ((size_t)(b * NQ + m0 + warp * 16)) * CDIM + h * HDIM;
#pragma unroll
    for (int nb = 0; nb < 8; nb++) {
#pragma unroll
        for (int i = 0; i < 2; i++) {
            float x0 = o[nb][2 * i] * inv[i];
            float x1 = o[nb][2 * i + 1] * inv[i];
            uint32_t hh = pack_hi(x0, x1);
            uint32_t ll = pack_lo(x0, x1, hh);
            size_t off = obase + (size_t)(r + i * 8) * CDIM + nb * 8 + c2;
            *(uint32_t*)(g_ohi + off) = hh;
            *(uint32_t*)(g_olo + off) = ll;
        }
    }
}

// ---------------------------------------------------------------------------
// Launcher
// ---------------------------------------------------------------------------
extern "C" void kernel_launch(void* const* d_in, const int* in_sizes, int n_in,
                              void* d_out, int out_size)
{
    const float* query = (const float*)d_in[0];
    const float* key   = (const float*)d_in[1];
    const float* value = (const float*)d_in[2];
    const int*   qpos  = (const int*)  d_in[3];
    const int*   kpos  = (const int*)  d_in[4];
    const float* Wq    = (const float*)d_in[5];
    const float* Wk    = (const float*)d_in[6];
    const float* Wv    = (const float*)d_in[7];
    const float* Wp    = (const float*)d_in[8];
    const float* bp    = (const float*)d_in[9];
    float* out = (float*)d_out;

    cudaFuncSetAttribute(qkv_proj_kernel,
                         cudaFuncAttributeMaxDynamicSharedMemorySize, GM_SMEM);
    cudaFuncSetAttribute(out_proj_kernel,
                         cudaFuncAttributeMaxDynamicSharedMemorySize, GM_SMEM);
    cudaFuncSetAttribute(attn_mma_kernel,
                         cudaFuncAttributeMaxDynamicSharedMemorySize, AT_SMEM);

    // Splits (two launches)
    const int in_n4 = QN4 + 2 * KN4;                        // 4718592
    input_split_kernel<<<in_n4 / 256, 256>>>(
        (const float4*)query, (const float4*)key, (const float4*)value);
    w_split_kernel<<<4 * WN4 / 256, 256>>>(
        (const float4*)Wq, (const float4*)Wk, (const float4*)Wv, (const float4*)Wp);

    // Fused QKV projections (+RoPE, +split epilogues), one launch
    qkv_proj_kernel<<<1152, 256, GM_SMEM>>>(qpos, kpos);

    // Attention -> bf16 split output
    attn_mma_kernel<<<dim3(NQ / 128, NHEADS, Bsz), 256, AT_SMEM>>>();

    // Output projection + bias
    out_proj_kernel<<<dim3(CDIM / 128, (Bsz * NQ) / 128), 256, GM_SMEM>>>(bp, out);
}

// round 7
// speedup vs baseline: 3.2943x; 1.1098x over previous
#include <cuda_runtime.h>
#include <cuda_bf16.h>
#include <cstdint>
#include <cstddef>

// Problem constants
#define Bsz 4
#define NQ  512
#define NK  2048
#define CDIM 1024
#define NHEADS 16
#define HDIM 64

// ---------------------------------------------------------------------------
// Scratch (device globals — no allocation allowed)
// ---------------------------------------------------------------------------
__device__ __nv_bfloat16 g_inq_hi[(size_t)Bsz * NQ * CDIM];
__device__ __nv_bfloat16 g_inq_lo[(size_t)Bsz * NQ * CDIM];
__device__ __nv_bfloat16 g_ink_hi[(size_t)Bsz * NK * CDIM];
__device__ __nv_bfloat16 g_ink_lo[(size_t)Bsz * NK * CDIM];
__device__ __nv_bfloat16 g_inv_hi[(size_t)Bsz * NK * CDIM];
__device__ __nv_bfloat16 g_inv_lo[(size_t)Bsz * NK * CDIM];
__device__ __nv_bfloat16 g_w_hi[(size_t)4 * CDIM * CDIM];   // Wq,Wk,Wv,Wp
__device__ __nv_bfloat16 g_w_lo[(size_t)4 * CDIM * CDIM];
__device__ __nv_bfloat16 g_qhi[(size_t)Bsz * NQ * CDIM];
__device__ __nv_bfloat16 g_qlo[(size_t)Bsz * NQ * CDIM];
__device__ __nv_bfloat16 g_khi[(size_t)Bsz * NK * CDIM];
__device__ __nv_bfloat16 g_klo[(size_t)Bsz * NK * CDIM];
__device__ __nv_bfloat16 g_vhi[(size_t)Bsz * NK * CDIM];
__device__ __nv_bfloat16 g_vlo[(size_t)Bsz * NK * CDIM];
__device__ __nv_bfloat16 g_ohi[(size_t)Bsz * NQ * CDIM];
__device__ __nv_bfloat16 g_olo[(size_t)Bsz * NQ * CDIM];

// ---------------------------------------------------------------------------
// Common helpers
// ---------------------------------------------------------------------------
__device__ __forceinline__ uint32_t smem_u32(const void* p) {
    uint32_t a;
    asm("{ .reg .u64 t; cvta.to.shared.u64 t, %1; cvt.u32.u64 %0, t; }"
        : "=r"(a) : "l"(p));
    return a;
}

__device__ __forceinline__ void cp16(uint32_t dst, const void* src) {
    asm volatile("cp.async.cg.shared.global [%0], [%1], 16;"
                 :: "r"(dst), "l"(src) : "memory");
}

__device__ __forceinline__ void ldm_x4(uint32_t* r, uint32_t addr) {
    asm volatile("ldmatrix.sync.aligned.m8n8.x4.shared.b16 {%0,%1,%2,%3}, [%4];"
                 : "=r"(r[0]), "=r"(r[1]), "=r"(r[2]), "=r"(r[3]) : "r"(addr));
}

__device__ __forceinline__ void ldm_x4_t(uint32_t* r, uint32_t addr) {
    asm volatile("ldmatrix.sync.aligned.m8n8.x4.trans.shared.b16 {%0,%1,%2,%3}, [%4];"
                 : "=r"(r[0]), "=r"(r[1]), "=r"(r[2]), "=r"(r[3]) : "r"(addr));
}

__device__ __forceinline__ void mma_bf16(float* c, const uint32_t* a,
                                         uint32_t b0, uint32_t b1) {
    asm volatile(
        "mma.sync.aligned.m16n8k16.row.col.f32.bf16.bf16.f32 "
        "{%0,%1,%2,%3}, {%4,%5,%6,%7}, {%8,%9}, {%0,%1,%2,%3};"
        : "+f"(c[0]), "+f"(c[1]), "+f"(c[2]), "+f"(c[3])
        : "r"(a[0]), "r"(a[1]), "r"(a[2]), "r"(a[3]), "r"(b0), "r"(b1));
}

__device__ __forceinline__ uint32_t pack_hi(float a, float b) {
    __nv_bfloat162 t = __floats2bfloat162_rn(a, b);
    return *(uint32_t*)&t;
}
__device__ __forceinline__ uint32_t pack_lo(float a, float b, uint32_t hi) {
    __nv_bfloat162 h = *(__nv_bfloat162*)&hi;
    float2 f = __bfloat1622float2(h);
    __nv_bfloat162 t = __floats2bfloat162_rn(a - f.x, b - f.y);
    return *(uint32_t*)&t;
}

__device__ __forceinline__ void split4(float4 a, __nv_bfloat162* hi,
                                       __nv_bfloat162* lo) {
    __nv_bfloat162 h01 = __floats2bfloat162_rn(a.x, a.y);
    __nv_bfloat162 h23 = __floats2bfloat162_rn(a.z, a.w);
    float2 f01 = __bfloat1622float2(h01);
    float2 f23 = __bfloat1622float2(h23);
    hi[0] = h01;
    hi[1] = h23;
    lo[0] = __floats2bfloat162_rn(a.x - f01.x, a.y - f01.y);
    lo[1] = __floats2bfloat162_rn(a.z - f23.x, a.w - f23.y);
}

// ---------------------------------------------------------------------------
// Input split: query + key + value in one launch (fp32 -> bf16 hi/lo)
// ---------------------------------------------------------------------------
#define QN4 ((Bsz * NQ * CDIM) / 4)      // 524288
#define KN4 ((Bsz * NK * CDIM) / 4)      // 2097152

__global__ void input_split_kernel(const float4* __restrict__ q,
                                   const float4* __restrict__ k,
                                   const float4* __restrict__ v)
{
    int idx = blockIdx.x * blockDim.x + threadIdx.x;
    const float4* src;
    __nv_bfloat162 *hi, *lo;
    int off;
    if (idx < QN4) {
        src = q; off = idx;
        hi = (__nv_bfloat162*)g_inq_hi; lo = (__nv_bfloat162*)g_inq_lo;
    } else if (idx < QN4 + KN4) {
        src = k; off = idx - QN4;
        hi = (__nv_bfloat162*)g_ink_hi; lo = (__nv_bfloat162*)g_ink_lo;
    } else {
        src = v; off = idx - QN4 - KN4;
        hi = (__nv_bfloat162*)g_inv_hi; lo = (__nv_bfloat162*)g_inv_lo;
    }
    split4(src[off], hi + off * 2, lo + off * 2);
}

// ---------------------------------------------------------------------------
// Weight split: all four W matrices in one launch
// ---------------------------------------------------------------------------
#define WN4 ((CDIM * CDIM) / 4)          // 262144

__global__ void w_split_kernel(const float4* __restrict__ wq,
                               const float4* __restrict__ wk,
                               const float4* __restrict__ wv,
                               const float4* __restrict__ wp)
{
    int idx = blockIdx.x * blockDim.x + threadIdx.x;
    int seg = idx / WN4;
    int off = idx - seg * WN4;
    const float4* src = (seg == 0) ? wq : (seg == 1) ? wk : (seg == 2) ? wv : wp;
    __nv_bfloat162* hi = (__nv_bfloat162*)(g_w_hi + (size_t)seg * CDIM * CDIM);
    __nv_bfloat162* lo = (__nv_bfloat162*)(g_w_lo + (size_t)seg * CDIM * CDIM);
    split4(src[off], hi + off * 2, lo + off * 2);
}

// ---------------------------------------------------------------------------
// Shared GEMM mainloop pieces (128x128 tile, BK=32, 8 warps, 3 passes)
// ---------------------------------------------------------------------------
#define PITCH_B 80
#define TILE_B  (128 * PITCH_B)
#define STAGE_B (4 * TILE_B)
#define GM_SMEM (2 * STAGE_B)

__device__ __forceinline__ void load_tile_async(const __nv_bfloat16* __restrict__ g,
                                                int row0, int k0,
                                                uint32_t sbase, int tid)
{
#pragma unroll
    for (int i = 0; i < 2; i++) {
        int idx = tid + i * 256;
        int r = idx >> 2;
        int j = idx & 3;
        cp16(sbase + r * PITCH_B + j * 16,
             g + (size_t)(row0 + r) * CDIM + k0 + j * 8);
    }
}

__device__ __forceinline__ void gemm_mainloop(
    const __nv_bfloat16* __restrict__ Ahi, const __nv_bfloat16* __restrict__ Alo,
    const __nv_bfloat16* __restrict__ Whi, const __nv_bfloat16* __restrict__ Wlo,
    int m0, int n0, uint32_t sb, int tid, float acc[2][8][4])
{
    const int lane = tid & 31;
    const int warp = tid >> 5;
    const int wm   = warp >> 1;
    const int wn   = warp & 1;

    const int arow = wm * 32 + ((lane >> 3) & 1) * 8 + (lane & 7);
    const int acol = (lane >> 4) * 8;
    const int brow = wn * 64 + ((lane >> 4) & 1) * 8 + (lane & 7);
    const int bcol = ((lane >> 3) & 1) * 8;

    load_tile_async(Ahi, m0, 0, sb + 0 * TILE_B, tid);
    load_tile_async(Alo, m0, 0, sb + 1 * TILE_B, tid);
    load_tile_async(Whi, n0, 0, sb + 2 * TILE_B, tid);
    load_tile_async(Wlo, n0, 0, sb + 3 * TILE_B, tid);
    asm volatile("cp.async.commit_group;" ::: "memory");

    const int NCHUNK = CDIM / 32;
    for (int c = 0; c < NCHUNK; c++) {
        if (c + 1 < NCHUNK) {
            uint32_t st = sb + ((c + 1) & 1) * STAGE_B;
            int k0 = (c + 1) * 32;
            load_tile_async(Ahi, m0, k0, st + 0 * TILE_B, tid);
            load_tile_async(Alo, m0, k0, st + 1 * TILE_B, tid);
            load_tile_async(Whi, n0, k0, st + 2 * TILE_B, tid);
            load_tile_async(Wlo, n0, k0, st + 3 * TILE_B, tid);
        }
        asm volatile("cp.async.commit_group;" ::: "memory");
        asm volatile("cp.async.wait_group 1;" ::: "memory");
        __syncthreads();

        const uint32_t stg  = sb + (c & 1) * STAGE_B;
        const uint32_t aHiB = stg + 0 * TILE_B;
        const uint32_t aLoB = stg + 1 * TILE_B;
        const uint32_t wHiB = stg + 2 * TILE_B;
        const uint32_t wLoB = stg + 3 * TILE_B;

#pragma unroll
        for (int s = 0; s < 2; s++) {
            const int kk = s * 16;
            uint32_t Ah[2][4], Al[2][4], Wh[4][4], Wl[4][4];
#pragma unroll
            for (int mi = 0; mi < 2; mi++) {
                uint32_t off = (uint32_t)((arow + mi * 16) * PITCH_B + (kk + acol) * 2);
                ldm_x4(Ah[mi], aHiB + off);
                ldm_x4(Al[mi], aLoB + off);
            }
#pragma unroll
            for (int nj = 0; nj < 4; nj++) {
                uint32_t off = (uint32_t)((brow + nj * 16) * PITCH_B + (kk + bcol) * 2);
                ldm_x4(Wh[nj], wHiB + off);
                ldm_x4(Wl[nj], wLoB + off);
            }
#pragma unroll
            for (int mi = 0; mi < 2; mi++)
#pragma unroll
                for (int q = 0; q < 8; q++)
                    mma_bf16(acc[mi][q], Ah[mi],
                             Wh[q >> 1][(q & 1) * 2], Wh[q >> 1][(q & 1) * 2 + 1]);
#pragma unroll
            for (int mi = 0; mi < 2; mi++)
#pragma unroll
                for (int q = 0; q < 8; q++)
                    mma_bf16(acc[mi][q], Ah[mi],
                             Wl[q >> 1][(q & 1) * 2], Wl[q >> 1][(q & 1) * 2 + 1]);
#pragma unroll
            for (int mi = 0; mi < 2; mi++)
#pragma unroll
                for (int q = 0; q < 8; q++)
                    mma_bf16(acc[mi][q], Al[mi],
                             Wh[q >> 1][(q & 1) * 2], Wh[q >> 1][(q & 1) * 2 + 1]);
        }
        __syncthreads();
    }
}

// ---------------------------------------------------------------------------
// Fused QKV projection: 1152 tiles in one launch, 2 CTAs/SM target.
// ---------------------------------------------------------------------------
__global__ void __launch_bounds__(256, 2)
qkv_proj_kernel(const int* __restrict__ qpos, const int* __restrict__ kpos)
{
    extern __shared__ __align__(128) char smem[];
    const uint32_t sb = smem_u32(smem);
    const int tid  = threadIdx.x;
    const int lane = tid & 31;
    const int warp = tid >> 5;
    const int t    = blockIdx.x;

    int gemm, local;
    if (t < 512)       { gemm = 1; local = t; }
    else if (t < 1024) { gemm = 2; local = t - 512; }
    else               { gemm = 0; local = t - 1024; }
    const int m0 = (local >> 3) * 128;
    const int n0 = (local & 7) * 128;

    const __nv_bfloat16 *Ah, *Al, *Wh, *Wl;
    if (gemm == 0) { Ah = g_inq_hi; Al = g_inq_lo; Wh = g_w_hi; Wl = g_w_lo; }
    else if (gemm == 1) {
        Ah = g_ink_hi; Al = g_ink_lo;
        Wh = g_w_hi + (size_t)CDIM * CDIM; Wl = g_w_lo + (size_t)CDIM * CDIM;
    } else {
        Ah = g_inv_hi; Al = g_inv_lo;
        Wh = g_w_hi + (size_t)2 * CDIM * CDIM; Wl = g_w_lo + (size_t)2 * CDIM * CDIM;
    }

    float acc[2][8][4];
#pragma unroll
    for (int mi = 0; mi < 2; mi++)
#pragma unroll
        for (int q = 0; q < 8; q++)
#pragma unroll
            for (int u = 0; u < 4; u++) acc[mi][q][u] = 0.f;

    gemm_mainloop(Ah, Al, Wh, Wl, m0, n0, sb, tid, acc);

    const int wm = warp >> 1;
    const int wn = warp & 1;
    const int er = m0 + wm * 32 + (lane >> 2);
    const int ec = n0 + wn * 64 + (lane & 3) * 2;

    if (gemm == 2) {
#pragma unroll
        for (int mi = 0; mi < 2; mi++) {
#pragma unroll
            for (int q = 0; q < 8; q++) {
                size_t off0 = (size_t)(er + mi * 16) * CDIM + ec + q * 8;
                size_t off1 = (size_t)(er + mi * 16 + 8) * CDIM + ec + q * 8;
                uint32_t h0 = pack_hi(acc[mi][q][0], acc[mi][q][1]);
                uint32_t h1 = pack_hi(acc[mi][q][2], acc[mi][q][3]);
                *(uint32_t*)(g_vhi + off0) = h0;
                *(uint32_t*)(g_vhi + off1) = h1;
                *(uint32_t*)(g_vlo + off0) = pack_lo(acc[mi][q][0], acc[mi][q][1], h0);
                *(uint32_t*)(g_vlo + off1) = pack_lo(acc[mi][q][2], acc[mi][q][3], h1);
            }
        }
        return;
    }

    const int* posarr = (gemm == 0) ? qpos : kpos;
    const float scale = (gemm == 0) ? 0.125f : 1.0f;
    __nv_bfloat16* dsthi = (gemm == 0) ? g_qhi : g_khi;
    __nv_bfloat16* dstlo = (gemm == 0) ? g_qlo : g_klo;
    const float kf = 13.2877123795494f / 32.0f;

    float invf[8];
#pragma unroll
    for (int qp = 0; qp < 4; qp++)
#pragma unroll
        for (int c = 0; c < 2; c++) {
            int j = (lane & 3) * 2 + qp * 8 + c;
            invf[qp * 2 + c] = exp2f(-(float)j * kf);
        }

#pragma unroll
    for (int mi = 0; mi < 2; mi++) {
#pragma unroll
        for (int tr = 0; tr < 2; tr++) {
            const int row = er + mi * 16 + tr * 8;
            const float p = (float)posarr[row];
#pragma unroll
            for (int qp = 0; qp < 4; qp++) {
                float y1[2], y2[2];
#pragma unroll
                for (int c = 0; c < 2; c++) {
                    float ang = p * invf[qp * 2 + c];
                    float s, co;
                    sincosf(ang, &s, &co);
                    float x1 = acc[mi][qp][tr * 2 + c];
                    float x2 = acc[mi][qp + 4][tr * 2 + c];
                    y1[c] = (x1 * co - x2 * s) * scale;
                    y2[c] = (x2 * co + x1 * s) * scale;
                }
                size_t offA = (size_t)row * CDIM + ec + qp * 8;
                size_t offB = (size_t)row * CDIM + ec + (qp + 4) * 8;
                uint32_t hA = pack_hi(y1[0], y1[1]);
                uint32_t hB = pack_hi(y2[0], y2[1]);
                *(uint32_t*)(dsthi + offA) = hA;
                *(uint32_t*)(dsthi + offB) = hB;
                *(uint32_t*)(dstlo + offA) = pack_lo(y1[0], y1[1], hA);
                *(uint32_t*)(dstlo + offB) = pack_lo(y2[0], y2[1], hB);
            }
        }
    }
}

// ---------------------------------------------------------------------------
// Output projection GEMM (fp32 out + bias), 2 CTAs/SM target.
// ---------------------------------------------------------------------------
__global__ void __launch_bounds__(256, 2)
out_proj_kernel(const float* __restrict__ bias, float* __restrict__ Cout)
{
    extern __shared__ __align__(128) char smem[];
    const uint32_t sb = smem_u32(smem);
    const int tid  = threadIdx.x;
    const int lane = tid & 31;
    const int warp = tid >> 5;
    const int m0   = blockIdx.y * 128;
    const int n0   = blockIdx.x * 128;

    float acc[2][8][4];
#pragma unroll
    for (int mi = 0; mi < 2; mi++)
#pragma unroll
        for (int q = 0; q < 8; q++)
#pragma unroll
            for (int u = 0; u < 4; u++) acc[mi][q][u] = 0.f;

    gemm_mainloop(g_ohi, g_olo,
                  g_w_hi + (size_t)3 * CDIM * CDIM, g_w_lo + (size_t)3 * CDIM * CDIM,
                  m0, n0, sb, tid, acc);

    const int wm = warp >> 1;
    const int wn = warp & 1;
    const int er = m0 + wm * 32 + (lane >> 2);
    const int ec = n0 + wn * 64 + (lane & 3) * 2;
#pragma unroll
    for (int mi = 0; mi < 2; mi++) {
#pragma unroll
        for (int q = 0; q < 8; q++) {
            float b0 = bias[ec + q * 8];
            float b1 = bias[ec + q * 8 + 1];
            float2 v0 = { acc[mi][q][0] + b0, acc[mi][q][1] + b1 };
            float2 v1 = { acc[mi][q][2] + b0, acc[mi][q][3] + b1 };
            *(float2*)&Cout[(size_t)(er + mi * 16) * CDIM + ec + q * 8]     = v0;
            *(float2*)&Cout[(size_t)(er + mi * 16 + 8) * CDIM + ec + q * 8] = v1;
        }
    }
}

// ---------------------------------------------------------------------------
// Flash attention on mma.sync: 512 threads (16 warps), 256 q-rows/CTA,
// 64-key tiles, grid = (2, 16, 4) = 128 CTAs = single wave.
// ---------------------------------------------------------------------------
#define ATK 64
#define KV_PITCH 144
#define KV_TILE  (ATK * KV_PITCH)      // 9216
#define AT_STAGE (4 * KV_TILE)         // 36864
#define AT_SMEM  (2 * AT_STAGE)        // 73728

__device__ __forceinline__ void at_load(const __nv_bfloat16* __restrict__ g,
                                        size_t gbase, uint32_t sbase, int tid)
{
    // 64 rows x 8 chunks = 512 cp16 ops; exactly one per thread
    int rr = tid >> 3;
    int ch = tid & 7;
    cp16(sbase + rr * KV_PITCH + ch * 16,
         g + gbase + (size_t)rr * CDIM + ch * 8);
}

__global__ void __launch_bounds__(512, 1)
attn_mma_kernel()
{
    extern __shared__ __align__(128) char smem[];
    const uint32_t sb = smem_u32(smem);
    const int tid  = threadIdx.x;
    const int lane = tid & 31;
    const int warp = tid >> 5;        // 0..15
    const int m0   = blockIdx.x * 256;
    const int h    = blockIdx.y;
    const int b    = blockIdx.z;

    const int r  = lane >> 2;
    const int c2 = (lane & 3) * 2;

    uint32_t Qh[4][4], Ql[4][4];
    {
        size_t qbase = ((size_t)(b * NQ + m0 + warp * 16)) * CDIM + h * HDIM;
#pragma unroll
        for (int ks = 0; ks < 4; ks++) {
            int col = ks * 16 + c2;
            Qh[ks][0] = *(const uint32_t*)(g_qhi + qbase + (size_t)r * CDIM + col);
            Qh[ks][1] = *(const uint32_t*)(g_qhi + qbase + (size_t)(r + 8) * CDIM + col);
            Qh[ks][2] = *(const uint32_t*)(g_qhi + qbase + (size_t)r * CDIM + col + 8);
            Qh[ks][3] = *(const uint32_t*)(g_qhi + qbase + (size_t)(r + 8) * CDIM + col + 8);
            Ql[ks][0] = *(const uint32_t*)(g_qlo + qbase + (size_t)r * CDIM + col);
            Ql[ks][1] = *(const uint32_t*)(g_qlo + qbase + (size_t)(r + 8) * CDIM + col);
            Ql[ks][2] = *(const uint32_t*)(g_qlo + qbase + (size_t)r * CDIM + col + 8);
            Ql[ks][3] = *(const uint32_t*)(g_qlo + qbase + (size_t)(r + 8) * CDIM + col + 8);
        }
    }

    const size_t kgbase = ((size_t)(b * NK)) * CDIM + h * HDIM;

    at_load(g_khi, kgbase, sb + 0 * KV_TILE, tid);
    at_load(g_klo, kgbase, sb + 1 * KV_TILE, tid);
    at_load(g_vhi, kgbase, sb + 2 * KV_TILE, tid);
    at_load(g_vlo, kgbase, sb + 3 * KV_TILE, tid);
    asm volatile("cp.async.commit_group;" ::: "memory");

    float m[2] = { -1e30f, -1e30f };
    float l[2] = { 0.f, 0.f };
    float o[8][4];
#pragma unroll
    for (int nb = 0; nb < 8; nb++)
#pragma unroll
        for (int u = 0; u < 4; u++) o[nb][u] = 0.f;

    const int krow_off = ((lane >> 4) & 1) * 8 + (lane & 7);
    const int kcol_off = ((lane >> 3) & 1) * 16;
    const int vrow_off = (lane & 7) + ((lane >> 3) & 1) * 8;
    const int vcol_off = (lane >> 4) * 16;
    const float L2E = 1.44269504f;

    for (int t = 0; t < NK / ATK; t++) {
        if (t + 1 < NK / ATK) {
            uint32_t st = sb + ((t + 1) & 1) * AT_STAGE;
            size_t gb2 = kgbase + (size_t)(t + 1) * ATK * CDIM;
            at_load(g_khi, gb2, st + 0 * KV_TILE, tid);
            at_load(g_klo, gb2, st + 1 * KV_TILE, tid);
            at_load(g_vhi, gb2, st + 2 * KV_TILE, tid);
            at_load(g_vlo, gb2, st + 3 * KV_TILE, tid);
        }
        asm volatile("cp.async.commit_group;" ::: "memory");
        asm volatile("cp.async.wait_group 1;" ::: "memory");
        __syncthreads();

        const uint32_t stg  = sb + (t & 1) * AT_STAGE;
        const uint32_t kHiB = stg + 0 * KV_TILE;
        const uint32_t kLoB = stg + 1 * KV_TILE;
        const uint32_t vHiB = stg + 2 * KV_TILE;
        const uint32_t vLoB = stg + 3 * KV_TILE;

        float sc[8][4];
#pragma unroll
        for (int nb = 0; nb < 8; nb++)
#pragma unroll
            for (int u = 0; u < 4; u++) sc[nb][u] = 0.f;

#pragma unroll
        for (int nj = 0; nj < 4; nj++) {
#pragma unroll
            for (int ks = 0; ks < 4; ks++) {
                uint32_t kh[4], kl[4];
                uint32_t off = (uint32_t)((nj * 16 + krow_off) * KV_PITCH
                                          + ks * 32 + kcol_off);
                ldm_x4(kh, kHiB + off);
                ldm_x4(kl, kLoB + off);
#pragma unroll
                for (int nb = 0; nb < 2; nb++) {
                    float* cc = sc[nj * 2 + nb];
                    mma_bf16(cc, Qh[ks], kh[nb * 2], kh[nb * 2 + 1]);
                    mma_bf16(cc, Qh[ks], kl[nb * 2], kl[nb * 2 + 1]);
                    mma_bf16(cc, Ql[ks], kh[nb * 2], kh[nb * 2 + 1]);
                }
            }
        }

#pragma unroll
        for (int i = 0; i < 2; i++) {
            float mx = sc[0][2 * i];
#pragma unroll
            for (int nb = 0; nb < 8; nb++)
                mx = fmaxf(mx, fmaxf(sc[nb][2 * i], sc[nb][2 * i + 1]));
            mx = fmaxf(mx, __shfl_xor_sync(0xFFFFFFFFu, mx, 1));
            mx = fmaxf(mx, __shfl_xor_sync(0xFFFFFFFFu, mx, 2));
            float mn = fmaxf(m[i], mx);
            float corr = exp2f((m[i] - mn) * L2E);
            m[i] = mn;
            float mnL = mn * L2E;
            float ls = 0.f;
#pragma unroll
            for (int nb = 0; nb < 8; nb++) {
                float p0 = exp2f(fmaf(sc[nb][2 * i], L2E, -mnL));
                float p1 = exp2f(fmaf(sc[nb][2 * i + 1], L2E, -mnL));
                sc[nb][2 * i] = p0;
                sc[nb][2 * i + 1] = p1;
                ls += p0 + p1;
            }
            l[i] = l[i] * corr + ls;
#pragma unroll
            for (int nb = 0; nb < 8; nb++) {
                o[nb][2 * i]     *= corr;
                o[nb][2 * i + 1] *= corr;
            }
        }

#pragma unroll
        for (int j = 0; j < 4; j++) {
            uint32_t Ph[4], Pl[4];
            Ph[0] = pack_hi(sc[2 * j][0],     sc[2 * j][1]);
            Ph[1] = pack_hi(sc[2 * j][2],     sc[2 * j][3]);
            Ph[2] = pack_hi(sc[2 * j + 1][0], sc[2 * j + 1][1]);
            Ph[3] = pack_hi(sc[2 * j + 1][2], sc[2 * j + 1][3]);
            Pl[0] = pack_lo(sc[2 * j][0],     sc[2 * j][1],     Ph[0]);
            Pl[1] = pack_lo(sc[2 * j][2],     sc[2 * j][3],     Ph[1]);
            Pl[2] = pack_lo(sc[2 * j + 1][0], sc[2 * j + 1][1], Ph[2]);
            Pl[3] = pack_lo(sc[2 * j + 1][2], sc[2 * j + 1][3], Ph[3]);
#pragma unroll
            for (int g = 0; g < 4; g++) {
                uint32_t vh[4], vl[4];
                uint32_t off = (uint32_t)((j * 16 + vrow_off) * KV_PITCH
                                          + g * 32 + vcol_off);
                ldm_x4_t(vh, vHiB + off);
                ldm_x4_t(vl, vLoB + off);
#pragma unroll
                for (int nb = 0; nb < 2; nb++) {
                    float* oo = o[g * 2 + nb];
                    mma_bf16(oo, Ph, vh[nb * 2], vh[nb * 2 + 1]);
                    mma_bf16(oo, Ph, vl[nb * 2], vl[nb * 2 + 1]);
                    mma_bf16(oo, Pl, vh[nb * 2], vh[nb * 2 + 1]);
                }
            }
        }
        __syncthreads();
    }

    float inv[2];
#pragma unroll
    for (int i = 0; i < 2; i++) {
        float lt = l[i];
        lt += __shfl_xor_sync(0xFFFFFFFFu, lt, 1);
        lt += __shfl_xor_sync(0xFFFFFFFFu, lt, 2);
        inv[i] = 1.f / lt;
    }
    size_t obase = ((size_t)(b * NQ + m0 + warp * 16)) * CDIM + h * HDIM;
#pragma unroll
    for (int nb = 0; nb < 8; nb++) {
#pragma unroll
        for (int i = 0; i < 2; i++) {
            float x0 = o[nb][2 * i] * inv[i];
            float x1 = o[nb][2 * i + 1] * inv[i];
            uint32_t hh = pack_hi(x0, x1);
            uint32_t ll = pack_lo(x0, x1, hh);
            size_t off = obase + (size_t)(r + i * 8) * CDIM + nb * 8 + c2;
            *(uint32_t*)(g_ohi + off) = hh;
            *(uint32_t*)(g_olo + off) = ll;
        }
    }
}

// ---------------------------------------------------------------------------
// Launcher
// ---------------------------------------------------------------------------
extern "C" void kernel_launch(void* const* d_in, const int* in_sizes, int n_in,
                              void* d_out, int out_size)
{
    const float* query = (const float*)d_in[0];
    const float* key   = (const float*)d_in[1];
    const float* value = (const float*)d_in[2];
    const int*   qpos  = (const int*)  d_in[3];
    const int*   kpos  = (const int*)  d_in[4];
    const float* Wq    = (const float*)d_in[5];
    const float* Wk    = (const float*)d_in[6];
    const float* Wv    = (const float*)d_in[7];
    const float* Wp    = (const float*)d_in[8];
    const float* bp    = (const float*)d_in[9];
    float* out = (float*)d_out;

    cudaFuncSetAttribute(qkv_proj_kernel,
                         cudaFuncAttributeMaxDynamicSharedMemorySize, GM_SMEM);
    cudaFuncSetAttribute(out_proj_kernel,
                         cudaFuncAttributeMaxDynamicSharedMemorySize, GM_SMEM);
    cudaFuncSetAttribute(attn_mma_kernel,
                         cudaFuncAttributeMaxDynamicSharedMemorySize, AT_SMEM);

    const int in_n4 = QN4 + 2 * KN4;
    input_split_kernel<<<in_n4 / 256, 256>>>(
        (const float4*)query, (const float4*)key, (const float4*)value);
    w_split_kernel<<<4 * WN4 / 256, 256>>>(
        (const float4*)Wq, (const float4*)Wk, (const float4*)Wv, (const float4*)Wp);

    qkv_proj_kernel<<<1152, 256, GM_SMEM>>>(qpos, kpos);

    attn_mma_kernel<<<dim3(NQ / 256, NHEADS, Bsz), 512, AT_SMEM>>>();

    out_proj_kernel<<<dim3(CDIM / 128, (Bsz * NQ) / 128), 256, GM_SMEM>>>(bp, out);
}

// round 8
// speedup vs baseline: 3.3825x; 1.0268x over previous
#include <cuda_runtime.h>
#include <cuda_bf16.h>
#include <cstdint>
#include <cstddef>

// Problem constants
#define Bsz 4
#define NQ  512
#define NK  2048
#define CDIM 1024
#define NHEADS 16
#define HDIM 64

// ---------------------------------------------------------------------------
// Scratch (device globals — no allocation allowed)
// ---------------------------------------------------------------------------
__device__ __nv_bfloat16 g_inq_hi[(size_t)Bsz * NQ * CDIM];
__device__ __nv_bfloat16 g_inq_lo[(size_t)Bsz * NQ * CDIM];
__device__ __nv_bfloat16 g_ink_hi[(size_t)Bsz * NK * CDIM];
__device__ __nv_bfloat16 g_ink_lo[(size_t)Bsz * NK * CDIM];
__device__ __nv_bfloat16 g_inv_hi[(size_t)Bsz * NK * CDIM];
__device__ __nv_bfloat16 g_inv_lo[(size_t)Bsz * NK * CDIM];
__device__ __nv_bfloat16 g_w_hi[(size_t)4 * CDIM * CDIM];   // Wq,Wk,Wv,Wp
__device__ __nv_bfloat16 g_w_lo[(size_t)4 * CDIM * CDIM];
__device__ __nv_bfloat16 g_qhi[(size_t)Bsz * NQ * CDIM];
__device__ __nv_bfloat16 g_qlo[(size_t)Bsz * NQ * CDIM];
__device__ __nv_bfloat16 g_khi[(size_t)Bsz * NK * CDIM];
__device__ __nv_bfloat16 g_klo[(size_t)Bsz * NK * CDIM];
__device__ __nv_bfloat16 g_vhi[(size_t)Bsz * NK * CDIM];
__device__ __nv_bfloat16 g_vlo[(size_t)Bsz * NK * CDIM];
__device__ __nv_bfloat16 g_ohi[(size_t)Bsz * NQ * CDIM];
__device__ __nv_bfloat16 g_olo[(size_t)Bsz * NQ * CDIM];

// ---------------------------------------------------------------------------
// Common helpers
// ---------------------------------------------------------------------------
__device__ __forceinline__ uint32_t smem_u32(const void* p) {
    uint32_t a;
    asm("{ .reg .u64 t; cvta.to.shared.u64 t, %1; cvt.u32.u64 %0, t; }"
        : "=r"(a) : "l"(p));
    return a;
}

__device__ __forceinline__ void cp16(uint32_t dst, const void* src) {
    asm volatile("cp.async.cg.shared.global [%0], [%1], 16;"
                 :: "r"(dst), "l"(src) : "memory");
}

__device__ __forceinline__ void ldm_x4(uint32_t* r, uint32_t addr) {
    asm volatile("ldmatrix.sync.aligned.m8n8.x4.shared.b16 {%0,%1,%2,%3}, [%4];"
                 : "=r"(r[0]), "=r"(r[1]), "=r"(r[2]), "=r"(r[3]) : "r"(addr));
}

__device__ __forceinline__ void ldm_x4_t(uint32_t* r, uint32_t addr) {
    asm volatile("ldmatrix.sync.aligned.m8n8.x4.trans.shared.b16 {%0,%1,%2,%3}, [%4];"
                 : "=r"(r[0]), "=r"(r[1]), "=r"(r[2]), "=r"(r[3]) : "r"(addr));
}

__device__ __forceinline__ void mma_bf16(float* c, const uint32_t* a,
                                         uint32_t b0, uint32_t b1) {
    asm volatile(
        "mma.sync.aligned.m16n8k16.row.col.f32.bf16.bf16.f32 "
        "{%0,%1,%2,%3}, {%4,%5,%6,%7}, {%8,%9}, {%0,%1,%2,%3};"
        : "+f"(c[0]), "+f"(c[1]), "+f"(c[2]), "+f"(c[3])
        : "r"(a[0]), "r"(a[1]), "r"(a[2]), "r"(a[3]), "r"(b0), "r"(b1));
}

__device__ __forceinline__ uint32_t pack_hi(float a, float b) {
    __nv_bfloat162 t = __floats2bfloat162_rn(a, b);
    return *(uint32_t*)&t;
}
__device__ __forceinline__ uint32_t pack_lo(float a, float b, uint32_t hi) {
    __nv_bfloat162 h = *(__nv_bfloat162*)&hi;
    float2 f = __bfloat1622float2(h);
    __nv_bfloat162 t = __floats2bfloat162_rn(a - f.x, b - f.y);
    return *(uint32_t*)&t;
}

__device__ __forceinline__ void split4(float4 a, __nv_bfloat162* hi,
                                       __nv_bfloat162* lo) {
    __nv_bfloat162 h01 = __floats2bfloat162_rn(a.x, a.y);
    __nv_bfloat162 h23 = __floats2bfloat162_rn(a.z, a.w);
    float2 f01 = __bfloat1622float2(h01);
    float2 f23 = __bfloat1622float2(h23);
    hi[0] = h01;
    hi[1] = h23;
    lo[0] = __floats2bfloat162_rn(a.x - f01.x, a.y - f01.y);
    lo[1] = __floats2bfloat162_rn(a.z - f23.x, a.w - f23.y);
}

// ---------------------------------------------------------------------------
// Fused split: q, k, v inputs + all 4 weights, 2 float4 per thread.
// ---------------------------------------------------------------------------
#define QN4 ((Bsz * NQ * CDIM) / 4)      // 524288
#define KN4 ((Bsz * NK * CDIM) / 4)      // 2097152
#define WN4 ((CDIM * CDIM) / 4)          // 262144
#define SPLIT_TOTAL (QN4 + 2 * KN4 + 4 * WN4)  // 5767168

__global__ void __launch_bounds__(256)
split_all_kernel(const float4* __restrict__ q, const float4* __restrict__ k,
                 const float4* __restrict__ v, const float4* __restrict__ wq,
                 const float4* __restrict__ wk, const float4* __restrict__ wv,
                 const float4* __restrict__ wp)
{
    int base = (blockIdx.x * blockDim.x + threadIdx.x) * 2;
#pragma unroll
    for (int e = 0; e < 2; e++) {
        int idx = base + e;
        const float4* src;
        __nv_bfloat162 *hi, *lo;
        int off;
        if (idx < QN4) {
            src = q; off = idx;
            hi = (__nv_bfloat162*)g_inq_hi; lo = (__nv_bfloat162*)g_inq_lo;
        } else if (idx < QN4 + KN4) {
            src = k; off = idx - QN4;
            hi = (__nv_bfloat162*)g_ink_hi; lo = (__nv_bfloat162*)g_ink_lo;
        } else if (idx < QN4 + 2 * KN4) {
            src = v; off = idx - QN4 - KN4;
            hi = (__nv_bfloat162*)g_inv_hi; lo = (__nv_bfloat162*)g_inv_lo;
        } else {
            int widx = idx - QN4 - 2 * KN4;
            int seg = widx / WN4;
            off = widx - seg * WN4;
            src = (seg == 0) ? wq : (seg == 1) ? wk : (seg == 2) ? wv : wp;
            hi = (__nv_bfloat162*)(g_w_hi + (size_t)seg * CDIM * CDIM);
            lo = (__nv_bfloat162*)(g_w_lo + (size_t)seg * CDIM * CDIM);
        }
        split4(src[off], hi + off * 2, lo + off * 2);
    }
}

// ---------------------------------------------------------------------------
// Shared GEMM mainloop (128x128 tile, BK=32, 8 warps, 3 passes).
// Single __syncthreads per k-chunk; cp.async issued after the barrier.
// ---------------------------------------------------------------------------
#define PITCH_B 80
#define TILE_B  (128 * PITCH_B)
#define STAGE_B (4 * TILE_B)
#define GM_SMEM (2 * STAGE_B)

__device__ __forceinline__ void load_tile_async(const __nv_bfloat16* __restrict__ g,
                                                int row0, int k0,
                                                uint32_t sbase, int tid)
{
#pragma unroll
    for (int i = 0; i < 2; i++) {
        int idx = tid + i * 256;
        int r = idx >> 2;
        int j = idx & 3;
        cp16(sbase + r * PITCH_B + j * 16,
             g + (size_t)(row0 + r) * CDIM + k0 + j * 8);
    }
}

__device__ __forceinline__ void gemm_mainloop(
    const __nv_bfloat16* __restrict__ Ahi, const __nv_bfloat16* __restrict__ Alo,
    const __nv_bfloat16* __restrict__ Whi, const __nv_bfloat16* __restrict__ Wlo,
    int m0, int n0, uint32_t sb, int tid, float acc[2][8][4])
{
    const int lane = tid & 31;
    const int warp = tid >> 5;
    const int wm   = warp >> 1;
    const int wn   = warp & 1;

    const int arow = wm * 32 + ((lane >> 3) & 1) * 8 + (lane & 7);
    const int acol = (lane >> 4) * 8;
    const int brow = wn * 64 + ((lane >> 4) & 1) * 8 + (lane & 7);
    const int bcol = ((lane >> 3) & 1) * 8;

    load_tile_async(Ahi, m0, 0, sb + 0 * TILE_B, tid);
    load_tile_async(Alo, m0, 0, sb + 1 * TILE_B, tid);
    load_tile_async(Whi, n0, 0, sb + 2 * TILE_B, tid);
    load_tile_async(Wlo, n0, 0, sb + 3 * TILE_B, tid);
    asm volatile("cp.async.commit_group;" ::: "memory");

    const int NCHUNK = CDIM / 32;
    for (int c = 0; c < NCHUNK; c++) {
        asm volatile("cp.async.wait_group 0;" ::: "memory");
        __syncthreads();

        const uint32_t stg  = sb + (c & 1) * STAGE_B;
        const uint32_t aHiB = stg + 0 * TILE_B;
        const uint32_t aLoB = stg + 1 * TILE_B;
        const uint32_t wHiB = stg + 2 * TILE_B;
        const uint32_t wLoB = stg + 3 * TILE_B;

#pragma unroll
        for (int s = 0; s < 2; s++) {
            const int kk = s * 16;
            uint32_t Ah[2][4], Al[2][4], Wh[4][4], Wl[4][4];
#pragma unroll
            for (int mi = 0; mi < 2; mi++) {
                uint32_t off = (uint32_t)((arow + mi * 16) * PITCH_B + (kk + acol) * 2);
                ldm_x4(Ah[mi], aHiB + off);
                ldm_x4(Al[mi], aLoB + off);
            }
#pragma unroll
            for (int nj = 0; nj < 4; nj++) {
                uint32_t off = (uint32_t)((brow + nj * 16) * PITCH_B + (kk + bcol) * 2);
                ldm_x4(Wh[nj], wHiB + off);
                ldm_x4(Wl[nj], wLoB + off);
            }
            // Issue next tile's loads after s=0 fragments (post-barrier: safe).
            if (s == 0 && c + 1 < NCHUNK) {
                uint32_t st = sb + ((c + 1) & 1) * STAGE_B;
                int k0 = (c + 1) * 32;
                load_tile_async(Ahi, m0, k0, st + 0 * TILE_B, tid);
                load_tile_async(Alo, m0, k0, st + 1 * TILE_B, tid);
                load_tile_async(Whi, n0, k0, st + 2 * TILE_B, tid);
                load_tile_async(Wlo, n0, k0, st + 3 * TILE_B, tid);
                asm volatile("cp.async.commit_group;" ::: "memory");
            }
#pragma unroll
            for (int mi = 0; mi < 2; mi++)
#pragma unroll
                for (int q = 0; q < 8; q++)
                    mma_bf16(acc[mi][q], Ah[mi],
                             Wh[q >> 1][(q & 1) * 2], Wh[q >> 1][(q & 1) * 2 + 1]);
#pragma unroll
            for (int mi = 0; mi < 2; mi++)
#pragma unroll
                for (int q = 0; q < 8; q++)
                    mma_bf16(acc[mi][q], Ah[mi],
                             Wl[q >> 1][(q & 1) * 2], Wl[q >> 1][(q & 1) * 2 + 1]);
#pragma unroll
            for (int mi = 0; mi < 2; mi++)
#pragma unroll
                for (int q = 0; q < 8; q++)
                    mma_bf16(acc[mi][q], Al[mi],
                             Wh[q >> 1][(q & 1) * 2], Wh[q >> 1][(q & 1) * 2 + 1]);
        }
    }
}

// ---------------------------------------------------------------------------
// Fused QKV projection: 1152 tiles in one launch, 2 CTAs/SM.
// ---------------------------------------------------------------------------
__global__ void __launch_bounds__(256, 2)
qkv_proj_kernel(const int* __restrict__ qpos, const int* __restrict__ kpos)
{
    extern __shared__ __align__(128) char smem[];
    const uint32_t sb = smem_u32(smem);
    const int tid  = threadIdx.x;
    const int lane = tid & 31;
    const int warp = tid >> 5;
    const int t    = blockIdx.x;

    int gemm, local;
    if (t < 512)       { gemm = 1; local = t; }
    else if (t < 1024) { gemm = 2; local = t - 512; }
    else               { gemm = 0; local = t - 1024; }
    const int m0 = (local >> 3) * 128;
    const int n0 = (local & 7) * 128;

    const __nv_bfloat16 *Ah, *Al, *Wh, *Wl;
    if (gemm == 0) { Ah = g_inq_hi; Al = g_inq_lo; Wh = g_w_hi; Wl = g_w_lo; }
    else if (gemm == 1) {
        Ah = g_ink_hi; Al = g_ink_lo;
        Wh = g_w_hi + (size_t)CDIM * CDIM; Wl = g_w_lo + (size_t)CDIM * CDIM;
    } else {
        Ah = g_inv_hi; Al = g_inv_lo;
        Wh = g_w_hi + (size_t)2 * CDIM * CDIM; Wl = g_w_lo + (size_t)2 * CDIM * CDIM;
    }

    float acc[2][8][4];
#pragma unroll
    for (int mi = 0; mi < 2; mi++)
#pragma unroll
        for (int q = 0; q < 8; q++)
#pragma unroll
            for (int u = 0; u < 4; u++) acc[mi][q][u] = 0.f;

    gemm_mainloop(Ah, Al, Wh, Wl, m0, n0, sb, tid, acc);

    const int wm = warp >> 1;
    const int wn = warp & 1;
    const int er = m0 + wm * 32 + (lane >> 2);
    const int ec = n0 + wn * 64 + (lane & 3) * 2;

    if (gemm == 2) {
#pragma unroll
        for (int mi = 0; mi < 2; mi++) {
#pragma unroll
            for (int q = 0; q < 8; q++) {
                size_t off0 = (size_t)(er + mi * 16) * CDIM + ec + q * 8;
                size_t off1 = (size_t)(er + mi * 16 + 8) * CDIM + ec + q * 8;
                uint32_t h0 = pack_hi(acc[mi][q][0], acc[mi][q][1]);
                uint32_t h1 = pack_hi(acc[mi][q][2], acc[mi][q][3]);
                *(uint32_t*)(g_vhi + off0) = h0;
                *(uint32_t*)(g_vhi + off1) = h1;
                *(uint32_t*)(g_vlo + off0) = pack_lo(acc[mi][q][0], acc[mi][q][1], h0);
                *(uint32_t*)(g_vlo + off1) = pack_lo(acc[mi][q][2], acc[mi][q][3], h1);
            }
        }
        return;
    }

    const int* posarr = (gemm == 0) ? qpos : kpos;
    const float scale = (gemm == 0) ? 0.125f : 1.0f;
    __nv_bfloat16* dsthi = (gemm == 0) ? g_qhi : g_khi;
    __nv_bfloat16* dstlo = (gemm == 0) ? g_qlo : g_klo;
    const float kf = 13.2877123795494f / 32.0f;

    float invf[8];
#pragma unroll
    for (int qp = 0; qp < 4; qp++)
#pragma unroll
        for (int c = 0; c < 2; c++) {
            int j = (lane & 3) * 2 + qp * 8 + c;
            invf[qp * 2 + c] = exp2f(-(float)j * kf);
        }

#pragma unroll
    for (int mi = 0; mi < 2; mi++) {
#pragma unroll
        for (int tr = 0; tr < 2; tr++) {
            const int row = er + mi * 16 + tr * 8;
            const float p = (float)posarr[row];
#pragma unroll
            for (int qp = 0; qp < 4; qp++) {
                float y1[2], y2[2];
#pragma unroll
                for (int c = 0; c < 2; c++) {
                    float ang = p * invf[qp * 2 + c];
                    float s, co;
                    sincosf(ang, &s, &co);
                    float x1 = acc[mi][qp][tr * 2 + c];
                    float x2 = acc[mi][qp + 4][tr * 2 + c];
                    y1[c] = (x1 * co - x2 * s) * scale;
                    y2[c] = (x2 * co + x1 * s) * scale;
                }
                size_t offA = (size_t)row * CDIM + ec + qp * 8;
                size_t offB = (size_t)row * CDIM + ec + (qp + 4) * 8;
                uint32_t hA = pack_hi(y1[0], y1[1]);
                uint32_t hB = pack_hi(y2[0], y2[1]);
                *(uint32_t*)(dsthi + offA) = hA;
                *(uint32_t*)(dsthi + offB) = hB;
                *(uint32_t*)(dstlo + offA) = pack_lo(y1[0], y1[1], hA);
                *(uint32_t*)(dstlo + offB) = pack_lo(y2[0], y2[1], hB);
            }
        }
    }
}

// ---------------------------------------------------------------------------
// Output projection GEMM (fp32 out + bias), 2 CTAs/SM.
// ---------------------------------------------------------------------------
__global__ void __launch_bounds__(256, 2)
out_proj_kernel(const float* __restrict__ bias, float* __restrict__ Cout)
{
    extern __shared__ __align__(128) char smem[];
    const uint32_t sb = smem_u32(smem);
    const int tid  = threadIdx.x;
    const int lane = tid & 31;
    const int warp = tid >> 5;
    const int m0   = blockIdx.y * 128;
    const int n0   = blockIdx.x * 128;

    float acc[2][8][4];
#pragma unroll
    for (int mi = 0; mi < 2; mi++)
#pragma unroll
        for (int q = 0; q < 8; q++)
#pragma unroll
            for (int u = 0; u < 4; u++) acc[mi][q][u] = 0.f;

    gemm_mainloop(g_ohi, g_olo,
                  g_w_hi + (size_t)3 * CDIM * CDIM, g_w_lo + (size_t)3 * CDIM * CDIM,
                  m0, n0, sb, tid, acc);

    const int wm = warp >> 1;
    const int wn = warp & 1;
    const int er = m0 + wm * 32 + (lane >> 2);
    const int ec = n0 + wn * 64 + (lane & 3) * 2;
#pragma unroll
    for (int mi = 0; mi < 2; mi++) {
#pragma unroll
        for (int q = 0; q < 8; q++) {
            float b0 = bias[ec + q * 8];
            float b1 = bias[ec + q * 8 + 1];
            float2 v0 = { acc[mi][q][0] + b0, acc[mi][q][1] + b1 };
            float2 v1 = { acc[mi][q][2] + b0, acc[mi][q][3] + b1 };
            *(float2*)&Cout[(size_t)(er + mi * 16) * CDIM + ec + q * 8]     = v0;
            *(float2*)&Cout[(size_t)(er + mi * 16 + 8) * CDIM + ec + q * 8] = v1;
        }
    }
}

// ---------------------------------------------------------------------------
// Flash attention: 512 threads (16 warps), 256 q-rows/CTA, 64-key tiles,
// 3-stage cp.async pipeline, single __syncthreads per tile,
// pass-major mma ordering (8-deep independent accumulator chains).
// ---------------------------------------------------------------------------
#define ATK 64
#define KV_PITCH 144
#define KV_TILE  (ATK * KV_PITCH)      // 9216
#define AT_STAGE (4 * KV_TILE)         // 36864
#define AT_STAGES 3
#define AT_SMEM  (AT_STAGES * AT_STAGE) // 110592

__device__ __forceinline__ void at_load(const __nv_bfloat16* __restrict__ g,
                                        size_t gbase, uint32_t sbase, int tid)
{
    int rr = tid >> 3;
    int ch = tid & 7;
    cp16(sbase + rr * KV_PITCH + ch * 16,
         g + gbase + (size_t)rr * CDIM + ch * 8);
}

__device__ __forceinline__ void at_load_stage(size_t kgbase, int t,
                                              uint32_t sb, int tid)
{
    uint32_t st = sb + (t % AT_STAGES) * AT_STAGE;
    size_t gb = kgbase + (size_t)t * ATK * CDIM;
    at_load(g_khi, gb, st + 0 * KV_TILE, tid);
    at_load(g_klo, gb, st + 1 * KV_TILE, tid);
    at_load(g_vhi, gb, st + 2 * KV_TILE, tid);
    at_load(g_vlo, gb, st + 3 * KV_TILE, tid);
    asm volatile("cp.async.commit_group;" ::: "memory");
}

__global__ void __launch_bounds__(512, 1)
attn_mma_kernel()
{
    extern __shared__ __align__(128) char smem[];
    const uint32_t sb = smem_u32(smem);
    const int tid  = threadIdx.x;
    const int lane = tid & 31;
    const int warp = tid >> 5;        // 0..15
    const int m0   = blockIdx.x * 256;
    const int h    = blockIdx.y;
    const int b    = blockIdx.z;

    const int r  = lane >> 2;
    const int c2 = (lane & 3) * 2;

    uint32_t Qh[4][4], Ql[4][4];
    {
        size_t qbase = ((size_t)(b * NQ + m0 + warp * 16)) * CDIM + h * HDIM;
#pragma unroll
        for (int ks = 0; ks < 4; ks++) {
            int col = ks * 16 + c2;
            Qh[ks][0] = *(const uint32_t*)(g_qhi + qbase + (size_t)r * CDIM + col);
            Qh[ks][1] = *(const uint32_t*)(g_qhi + qbase + (size_t)(r + 8) * CDIM + col);
            Qh[ks][2] = *(const uint32_t*)(g_qhi + qbase + (size_t)r * CDIM + col + 8);
            Qh[ks][3] = *(const uint32_t*)(g_qhi + qbase + (size_t)(r + 8) * CDIM + col + 8);
            Ql[ks][0] = *(const uint32_t*)(g_qlo + qbase + (size_t)r * CDIM + col);
            Ql[ks][1] = *(const uint32_t*)(g_qlo + qbase + (size_t)(r + 8) * CDIM + col);
            Ql[ks][2] = *(const uint32_t*)(g_qlo + qbase + (size_t)r * CDIM + col + 8);
            Ql[ks][3] = *(const uint32_t*)(g_qlo + qbase + (size_t)(r + 8) * CDIM + col + 8);
        }
    }

    const size_t kgbase = ((size_t)(b * NK)) * CDIM + h * HDIM;

    // Preload tiles 0 and 1
    at_load_stage(kgbase, 0, sb, tid);
    at_load_stage(kgbase, 1, sb, tid);

    float m[2] = { -1e30f, -1e30f };
    float l[2] = { 0.f, 0.f };
    float o[8][4];
#pragma unroll
    for (int nb = 0; nb < 8; nb++)
#pragma unroll
        for (int u = 0; u < 4; u++) o[nb][u] = 0.f;

    const int krow_off = ((lane >> 4) & 1) * 8 + (lane & 7);
    const int kcol_off = ((lane >> 3) & 1) * 16;
    const int vrow_off = (lane & 7) + ((lane >> 3) & 1) * 8;
    const int vcol_off = (lane >> 4) * 16;
    const float L2E = 1.44269504f;

    const int NT = NK / ATK;   // 32
    for (int t = 0; t < NT; t++) {
        // Wait for tile t (allow tile t+1 to remain in flight)
        asm volatile("cp.async.wait_group 1;" ::: "memory");
        __syncthreads();
        // Issue tile t+2 after the barrier (stage reuse is now safe)
        if (t + 2 < NT) at_load_stage(kgbase, t + 2, sb, tid);

        const uint32_t stg  = sb + (t % AT_STAGES) * AT_STAGE;
        const uint32_t kHiB = stg + 0 * KV_TILE;
        const uint32_t kLoB = stg + 1 * KV_TILE;
        const uint32_t vHiB = stg + 2 * KV_TILE;
        const uint32_t vLoB = stg + 3 * KV_TILE;

        float sc[8][4];
#pragma unroll
        for (int nb = 0; nb < 8; nb++)
#pragma unroll
            for (int u = 0; u < 4; u++) sc[nb][u] = 0.f;

        // --- QK: pass-major, all-nj K fragments resident ---
#pragma unroll
        for (int ks = 0; ks < 4; ks++) {
            uint32_t kf4[4][4];
#pragma unroll
            for (int nj = 0; nj < 4; nj++)
                ldm_x4(kf4[nj], kHiB + (uint32_t)((nj * 16 + krow_off) * KV_PITCH
                                                  + ks * 32 + kcol_off));
            // pass hh (8 independent acc chains)
#pragma unroll
            for (int nj = 0; nj < 4; nj++)
#pragma unroll
                for (int nb = 0; nb < 2; nb++)
                    mma_bf16(sc[nj * 2 + nb], Qh[ks],
                             kf4[nj][nb * 2], kf4[nj][nb * 2 + 1]);
            // pass lh (Ql x Khi)
#pragma unroll
            for (int nj = 0; nj < 4; nj++)
#pragma unroll
                for (int nb = 0; nb < 2; nb++)
                    mma_bf16(sc[nj * 2 + nb], Ql[ks],
                             kf4[nj][nb * 2], kf4[nj][nb * 2 + 1]);
            // reload as Klo
#pragma unroll
            for (int nj = 0; nj < 4; nj++)
                ldm_x4(kf4[nj], kLoB + (uint32_t)((nj * 16 + krow_off) * KV_PITCH
                                                  + ks * 32 + kcol_off));
            // pass hl (Qh x Klo)
#pragma unroll
            for (int nj = 0; nj < 4; nj++)
#pragma unroll
                for (int nb = 0; nb < 2; nb++)
                    mma_bf16(sc[nj * 2 + nb], Qh[ks],
                             kf4[nj][nb * 2], kf4[nj][nb * 2 + 1]);
        }

        // --- softmax (rows r, r+8) ---
#pragma unroll
        for (int i = 0; i < 2; i++) {
            float mx = sc[0][2 * i];
#pragma unroll
            for (int nb = 0; nb < 8; nb++)
                mx = fmaxf(mx, fmaxf(sc[nb][2 * i], sc[nb][2 * i + 1]));
            mx = fmaxf(mx, __shfl_xor_sync(0xFFFFFFFFu, mx, 1));
            mx = fmaxf(mx, __shfl_xor_sync(0xFFFFFFFFu, mx, 2));
            float mn = fmaxf(m[i], mx);
            float corr = exp2f((m[i] - mn) * L2E);
            m[i] = mn;
            float mnL = mn * L2E;
            float ls = 0.f;
#pragma unroll
            for (int nb = 0; nb < 8; nb++) {
                float p0 = exp2f(fmaf(sc[nb][2 * i], L2E, -mnL));
                float p1 = exp2f(fmaf(sc[nb][2 * i + 1], L2E, -mnL));
                sc[nb][2 * i] = p0;
                sc[nb][2 * i + 1] = p1;
                ls += p0 + p1;
            }
            l[i] = l[i] * corr + ls;
#pragma unroll
            for (int nb = 0; nb < 8; nb++) {
                o[nb][2 * i]     *= corr;
                o[nb][2 * i + 1] *= corr;
            }
        }

        // --- PV: precompute all P fragments, then g-paired passes ---
        uint32_t Ph[4][4], Pl[4][4];
#pragma unroll
        for (int j = 0; j < 4; j++) {
            Ph[j][0] = pack_hi(sc[2 * j][0],     sc[2 * j][1]);
            Ph[j][1] = pack_hi(sc[2 * j][2],     sc[2 * j][3]);
            Ph[j][2] = pack_hi(sc[2 * j + 1][0], sc[2 * j + 1][1]);
            Ph[j][3] = pack_hi(sc[2 * j + 1][2], sc[2 * j + 1][3]);
            Pl[j][0] = pack_lo(sc[2 * j][0],     sc[2 * j][1],     Ph[j][0]);
            Pl[j][1] = pack_lo(sc[2 * j][2],     sc[2 * j][3],     Ph[j][1]);
            Pl[j][2] = pack_lo(sc[2 * j + 1][0], sc[2 * j + 1][1], Ph[j][2]);
            Pl[j][3] = pack_lo(sc[2 * j + 1][2], sc[2 * j + 1][3], Ph[j][3]);
        }

#pragma unroll
        for (int gp = 0; gp < 2; gp++) {
            uint32_t vf[2][4];
#pragma unroll
            for (int gg = 0; gg < 2; gg++)
                ldm_x4_t(vf[gg], vHiB + (uint32_t)
                         ((0 * 16 + vrow_off) * KV_PITCH
                          + (gp * 2 + gg) * 32 + vcol_off));
            // Note: V fragments depend on j (row dim is the reduction).
            // Loop j as reduction with per-j transposed loads:
#pragma unroll
            for (int j = 0; j < 4; j++) {
                if (j > 0) {
#pragma unroll
                    for (int gg = 0; gg < 2; gg++)
                        ldm_x4_t(vf[gg], vHiB + (uint32_t)
                                 ((j * 16 + vrow_off) * KV_PITCH
                                  + (gp * 2 + gg) * 32 + vcol_off));
                }
                // pass Ph·Vhi and Pl·Vhi (4 acc chains interleaved)
#pragma unroll
                for (int gg = 0; gg < 2; gg++)
#pragma unroll
                    for (int nb = 0; nb < 2; nb++)
                        mma_bf16(o[(gp * 2 + gg) * 2 + nb], Ph[j],
                                 vf[gg][nb * 2], vf[gg][nb * 2 + 1]);
#pragma unroll
                for (int gg = 0; gg < 2; gg++)
#pragma unroll
                    for (int nb = 0; nb < 2; nb++)
                        mma_bf16(o[(gp * 2 + gg) * 2 + nb], Pl[j],
                                 vf[gg][nb * 2], vf[gg][nb * 2 + 1]);
                // Vlo pass
                uint32_t vl[2][4];
#pragma unroll
                for (int gg = 0; gg < 2; gg++)
                    ldm_x4_t(vl[gg], vLoB + (uint32_t)
                             ((j * 16 + vrow_off) * KV_PITCH
                              + (gp * 2 + gg) * 32 + vcol_off));
#pragma unroll
                for (int gg = 0; gg < 2; gg++)
#pragma unroll
                    for (int nb = 0; nb < 2; nb++)
                        mma_bf16(o[(gp * 2 + gg) * 2 + nb], Ph[j],
                                 vl[gg][nb * 2], vl[gg][nb * 2 + 1]);
            }
        }
    }

    float inv[2];
#pragma unroll
    for (int i = 0; i < 2; i++) {
        float lt = l[i];
        lt += __shfl_xor_sync(0xFFFFFFFFu, lt, 1);
        lt += __shfl_xor_sync(0xFFFFFFFFu, lt, 2);
        inv[i] = 1.f / lt;
    }
    size_t obase = ((size_t)(b * NQ + m0 + warp * 16)) * CDIM + h * HDIM;
#pragma unroll
    for (int nb = 0; nb < 8; nb++) {
#pragma unroll
        for (int i = 0; i < 2; i++) {
            float x0 = o[nb][2 * i] * inv[i];
            float x1 = o[nb][2 * i + 1] * inv[i];
            uint32_t hh = pack_hi(x0, x1);
            uint32_t ll = pack_lo(x0, x1, hh);
            size_t off = obase + (size_t)(r + i * 8) * CDIM + nb * 8 + c2;
            *(uint32_t*)(g_ohi + off) = hh;
            *(uint32_t*)(g_olo + off) = ll;
        }
    }
}

// ---------------------------------------------------------------------------
// Launcher
// ---------------------------------------------------------------------------
extern "C" void kernel_launch(void* const* d_in, const int* in_sizes, int n_in,
                              void* d_out, int out_size)
{
    const float* query = (const float*)d_in[0];
    const float* key   = (const float*)d_in[1];
    const float* value = (const float*)d_in[2];
    const int*   qpos  = (const int*)  d_in[3];
    const int*   kpos  = (const int*)  d_in[4];
    const float* Wq    = (const float*)d_in[5];
    const float* Wk    = (const float*)d_in[6];
    const float* Wv    = (const float*)d_in[7];
    const float* Wp    = (const float*)d_in[8];
    const float* bp    = (const float*)d_in[9];
    float* out = (float*)d_out;

    cudaFuncSetAttribute(qkv_proj_kernel,
                         cudaFuncAttributeMaxDynamicSharedMemorySize, GM_SMEM);
    cudaFuncSetAttribute(out_proj_kernel,
                         cudaFuncAttributeMaxDynamicSharedMemorySize, GM_SMEM);
    cudaFuncSetAttribute(attn_mma_kernel,
                         cudaFuncAttributeMaxDynamicSharedMemorySize, AT_SMEM);

    split_all_kernel<<<SPLIT_TOTAL / 512, 256>>>(
        (const float4*)query, (const float4*)key, (const float4*)value,
        (const float4*)Wq, (const float4*)Wk, (const float4*)Wv, (const float4*)Wp);

    qkv_proj_kernel<<<1152, 256, GM_SMEM>>>(qpos, kpos);

    attn_mma_kernel<<<dim3(NQ / 256, NHEADS, Bsz), 512, AT_SMEM>>>();

    out_proj_kernel<<<dim3(CDIM / 128, (Bsz * NQ) / 128), 256, GM_SMEM>>>(bp, out);
}

// round 9
// speedup vs baseline: 5.2243x; 1.5445x over previous
#include <cuda_runtime.h>
#include <cuda_fp16.h>
#include <cstdint>
#include <cstddef>

// Problem constants
#define Bsz 4
#define NQ  512
#define NK  2048
#define CDIM 1024
#define NHEADS 16
#define HDIM 64

// ---------------------------------------------------------------------------
// Scratch (device globals — no allocation allowed). All fp16.
// ---------------------------------------------------------------------------
__device__ __half g_inq[(size_t)Bsz * NQ * CDIM];
__device__ __half g_ink[(size_t)Bsz * NK * CDIM];
__device__ __half g_inv[(size_t)Bsz * NK * CDIM];
__device__ __half g_w_hi[(size_t)4 * CDIM * CDIM];   // Wq,Wk,Wv,Wp
__device__ __half g_w_lo[(size_t)4 * CDIM * CDIM];
__device__ __half g_q[(size_t)Bsz * NQ * CDIM];
__device__ __half g_k[(size_t)Bsz * NK * CDIM];
__device__ __half g_v[(size_t)Bsz * NK * CDIM];
__device__ __half g_o[(size_t)Bsz * NQ * CDIM];

// ---------------------------------------------------------------------------
// Common helpers
// ---------------------------------------------------------------------------
__device__ __forceinline__ uint32_t smem_u32(const void* p) {
    uint32_t a;
    asm("{ .reg .u64 t; cvta.to.shared.u64 t, %1; cvt.u32.u64 %0, t; }"
        : "=r"(a) : "l"(p));
    return a;
}

__device__ __forceinline__ void cp16(uint32_t dst, const void* src) {
    asm volatile("cp.async.cg.shared.global [%0], [%1], 16;"
                 :: "r"(dst), "l"(src) : "memory");
}

__device__ __forceinline__ void ldm_x4(uint32_t* r, uint32_t addr) {
    asm volatile("ldmatrix.sync.aligned.m8n8.x4.shared.b16 {%0,%1,%2,%3}, [%4];"
                 : "=r"(r[0]), "=r"(r[1]), "=r"(r[2]), "=r"(r[3]) : "r"(addr));
}

__device__ __forceinline__ void ldm_x4_t(uint32_t* r, uint32_t addr) {
    asm volatile("ldmatrix.sync.aligned.m8n8.x4.trans.shared.b16 {%0,%1,%2,%3}, [%4];"
                 : "=r"(r[0]), "=r"(r[1]), "=r"(r[2]), "=r"(r[3]) : "r"(addr));
}

__device__ __forceinline__ void mma_f16(float* c, const uint32_t* a,
                                        uint32_t b0, uint32_t b1) {
    asm volatile(
        "mma.sync.aligned.m16n8k16.row.col.f32.f16.f16.f32 "
        "{%0,%1,%2,%3}, {%4,%5,%6,%7}, {%8,%9}, {%0,%1,%2,%3};"
        : "+f"(c[0]), "+f"(c[1]), "+f"(c[2]), "+f"(c[3])
        : "r"(a[0]), "r"(a[1]), "r"(a[2]), "r"(a[3]), "r"(b0), "r"(b1));
}

__device__ __forceinline__ uint32_t pack_h2(float a, float b) {
    __half2 t = __floats2half2_rn(a, b);
    return *(uint32_t*)&t;
}

// ---------------------------------------------------------------------------
// Fused split kernel: q,k,v -> single fp16; weights -> fp16 hi/lo.
// ---------------------------------------------------------------------------
#define QN4 ((Bsz * NQ * CDIM) / 4)      // 524288
#define KN4 ((Bsz * NK * CDIM) / 4)      // 2097152
#define WN4 ((CDIM * CDIM) / 4)          // 262144
#define SPLIT_TOTAL (QN4 + 2 * KN4 + 4 * WN4)  // 5767168

__global__ void __launch_bounds__(256)
split_all_kernel(const float4* __restrict__ q, const float4* __restrict__ k,
                 const float4* __restrict__ v, const float4* __restrict__ wq,
                 const float4* __restrict__ wk, const float4* __restrict__ wv,
                 const float4* __restrict__ wp)
{
    int base = (blockIdx.x * blockDim.x + threadIdx.x) * 2;
#pragma unroll
    for (int e = 0; e < 2; e++) {
        int idx = base + e;
        if (idx < QN4 + 2 * KN4) {
            const float4* src;
            __half2* dst;
            int off;
            if (idx < QN4) { src = q; off = idx; dst = (__half2*)g_inq; }
            else if (idx < QN4 + KN4) { src = k; off = idx - QN4; dst = (__half2*)g_ink; }
            else { src = v; off = idx - QN4 - KN4; dst = (__half2*)g_inv; }
            float4 a = src[off];
            dst[off * 2 + 0] = __floats2half2_rn(a.x, a.y);
            dst[off * 2 + 1] = __floats2half2_rn(a.z, a.w);
        } else {
            int widx = idx - QN4 - 2 * KN4;
            int seg = widx / WN4;
            int off = widx - seg * WN4;
            const float4* src = (seg == 0) ? wq : (seg == 1) ? wk
                              : (seg == 2) ? wv : wp;
            __half2* hi = (__half2*)(g_w_hi + (size_t)seg * CDIM * CDIM);
            __half2* lo = (__half2*)(g_w_lo + (size_t)seg * CDIM * CDIM);
            float4 a = src[off];
            __half2 h01 = __floats2half2_rn(a.x, a.y);
            __half2 h23 = __floats2half2_rn(a.z, a.w);
            float2 f01 = __half22float2(h01);
            float2 f23 = __half22float2(h23);
            hi[off * 2 + 0] = h01;
            hi[off * 2 + 1] = h23;
            lo[off * 2 + 0] = __floats2half2_rn(a.x - f01.x, a.y - f01.y);
            lo[off * 2 + 1] = __floats2half2_rn(a.z - f23.x, a.w - f23.y);
        }
    }
}

// ---------------------------------------------------------------------------
// GEMM mainloop, templated on MI (M tile = MI*64 rows), N tile = 128, BK=32.
// A single fp16, W split hi/lo fp16. 2 passes. Single sync per chunk.
// ---------------------------------------------------------------------------
#define PITCH_B 80
#define TILE_W (128 * PITCH_B)

template <int MI>
struct GemmCfg {
    static const int TILE_A  = MI * 64 * PITCH_B;
    static const int STAGE_B = TILE_A + 2 * TILE_W;
    static const int SMEM    = 2 * STAGE_B;
};

template <int MI>
__device__ __forceinline__ void load_A_async(const __half* __restrict__ g,
                                             int row0, int k0,
                                             uint32_t sbase, int tid)
{
#pragma unroll
    for (int i = 0; i < MI; i++) {
        int idx = tid + i * 256;
        int r = idx >> 2;
        int j = idx & 3;
        cp16(sbase + r * PITCH_B + j * 16,
             g + (size_t)(row0 + r) * CDIM + k0 + j * 8);
    }
}

__device__ __forceinline__ void load_W_async(const __half* __restrict__ g,
                                             int row0, int k0,
                                             uint32_t sbase, int tid)
{
#pragma unroll
    for (int i = 0; i < 2; i++) {
        int idx = tid + i * 256;
        int r = idx >> 2;
        int j = idx & 3;
        cp16(sbase + r * PITCH_B + j * 16,
             g + (size_t)(row0 + r) * CDIM + k0 + j * 8);
    }
}

template <int MI>
__device__ __forceinline__ void gemm_mainloop2(
    const __half* __restrict__ A,
    const __half* __restrict__ Wh, const __half* __restrict__ Wl,
    int m0, int n0, uint32_t sb, int tid, float acc[MI][8][4])
{
    const int lane = tid & 31;
    const int warp = tid >> 5;
    const int wm   = warp >> 1;
    const int wn   = warp & 1;

    const int arow = wm * (16 * MI) + ((lane >> 3) & 1) * 8 + (lane & 7);
    const int acol = (lane >> 4) * 8;
    const int brow = wn * 64 + ((lane >> 4) & 1) * 8 + (lane & 7);
    const int bcol = ((lane >> 3) & 1) * 8;

    const int TILE_A  = GemmCfg<MI>::TILE_A;
    const int STAGE_B = GemmCfg<MI>::STAGE_B;

    load_A_async<MI>(A, m0, 0, sb, tid);
    load_W_async(Wh, n0, 0, sb + TILE_A, tid);
    load_W_async(Wl, n0, 0, sb + TILE_A + TILE_W, tid);
    asm volatile("cp.async.commit_group;" ::: "memory");

    const int NCHUNK = CDIM / 32;
    for (int c = 0; c < NCHUNK; c++) {
        asm volatile("cp.async.wait_group 0;" ::: "memory");
        __syncthreads();

        const uint32_t stg = sb + (c & 1) * STAGE_B;
        const uint32_t aB  = stg;
        const uint32_t whB = stg + TILE_A;
        const uint32_t wlB = stg + TILE_A + TILE_W;

#pragma unroll
        for (int s = 0; s < 2; s++) {
            const int kk = s * 16;
            uint32_t Af[MI][4], Wf[4][4];
#pragma unroll
            for (int mi = 0; mi < MI; mi++)
                ldm_x4(Af[mi], aB + (uint32_t)((arow + mi * 16) * PITCH_B
                                               + (kk + acol) * 2));
#pragma unroll
            for (int nj = 0; nj < 4; nj++)
                ldm_x4(Wf[nj], whB + (uint32_t)((brow + nj * 16) * PITCH_B
                                                + (kk + bcol) * 2));
            if (s == 0 && c + 1 < NCHUNK) {
                uint32_t st = sb + ((c + 1) & 1) * STAGE_B;
                int k0 = (c + 1) * 32;
                load_A_async<MI>(A, m0, k0, st, tid);
                load_W_async(Wh, n0, k0, st + TILE_A, tid);
                load_W_async(Wl, n0, k0, st + TILE_A + TILE_W, tid);
                asm volatile("cp.async.commit_group;" ::: "memory");
            }
            // Pass 1: A * Whi
#pragma unroll
            for (int mi = 0; mi < MI; mi++)
#pragma unroll
                for (int q = 0; q < 8; q++)
                    mma_f16(acc[mi][q], Af[mi],
                            Wf[q >> 1][(q & 1) * 2], Wf[q >> 1][(q & 1) * 2 + 1]);
            // Pass 2: A * Wlo
#pragma unroll
            for (int nj = 0; nj < 4; nj++)
                ldm_x4(Wf[nj], wlB + (uint32_t)((brow + nj * 16) * PITCH_B
                                                + (kk + bcol) * 2));
#pragma unroll
            for (int mi = 0; mi < MI; mi++)
#pragma unroll
                for (int q = 0; q < 8; q++)
                    mma_f16(acc[mi][q], Af[mi],
                            Wf[q >> 1][(q & 1) * 2], Wf[q >> 1][(q & 1) * 2 + 1]);
        }
    }
}

#define GM_SMEM  (GemmCfg<2>::SMEM)   // qkv: 128x128 tiles
#define GO_SMEM  (GemmCfg<1>::SMEM)   // out_proj: 64x128 tiles

// ---------------------------------------------------------------------------
// Fused QKV projection: 1152 tiles, one launch, 2 CTAs/SM.
// Epilogues: Q/K -> RoPE -> fp16; V -> fp16.
// ---------------------------------------------------------------------------
__global__ void __launch_bounds__(256, 2)
qkv_proj_kernel(const int* __restrict__ qpos, const int* __restrict__ kpos)
{
    extern __shared__ __align__(128) char smem[];
    const uint32_t sb = smem_u32(smem);
    const int tid  = threadIdx.x;
    const int lane = tid & 31;
    const int warp = tid >> 5;
    const int t    = blockIdx.x;

    int gemm, local;
    if (t < 512)       { gemm = 1; local = t; }
    else if (t < 1024) { gemm = 2; local = t - 512; }
    else               { gemm = 0; local = t - 1024; }
    const int m0 = (local >> 3) * 128;
    const int n0 = (local & 7) * 128;

    const __half *A, *Wh, *Wl;
    if (gemm == 0) { A = g_inq; Wh = g_w_hi; Wl = g_w_lo; }
    else if (gemm == 1) {
        A = g_ink;
        Wh = g_w_hi + (size_t)CDIM * CDIM; Wl = g_w_lo + (size_t)CDIM * CDIM;
    } else {
        A = g_inv;
        Wh = g_w_hi + (size_t)2 * CDIM * CDIM; Wl = g_w_lo + (size_t)2 * CDIM * CDIM;
    }

    float acc[2][8][4];
#pragma unroll
    for (int mi = 0; mi < 2; mi++)
#pragma unroll
        for (int q = 0; q < 8; q++)
#pragma unroll
            for (int u = 0; u < 4; u++) acc[mi][q][u] = 0.f;

    gemm_mainloop2<2>(A, Wh, Wl, m0, n0, sb, tid, acc);

    const int wm = warp >> 1;
    const int wn = warp & 1;
    const int er = m0 + wm * 32 + (lane >> 2);
    const int ec = n0 + wn * 64 + (lane & 3) * 2;

    if (gemm == 2) {
#pragma unroll
        for (int mi = 0; mi < 2; mi++) {
#pragma unroll
            for (int q = 0; q < 8; q++) {
                size_t off0 = (size_t)(er + mi * 16) * CDIM + ec + q * 8;
                size_t off1 = (size_t)(er + mi * 16 + 8) * CDIM + ec + q * 8;
                *(uint32_t*)(g_v + off0) = pack_h2(acc[mi][q][0], acc[mi][q][1]);
                *(uint32_t*)(g_v + off1) = pack_h2(acc[mi][q][2], acc[mi][q][3]);
            }
        }
        return;
    }

    const int* posarr = (gemm == 0) ? qpos : kpos;
    const float scale = (gemm == 0) ? 0.125f : 1.0f;
    __half* dst = (gemm == 0) ? g_q : g_k;
    const float kf = 13.2877123795494f / 32.0f;   // log2(10000)/32

    float invf[8];
#pragma unroll
    for (int qp = 0; qp < 4; qp++)
#pragma unroll
        for (int c = 0; c < 2; c++) {
            int j = (lane & 3) * 2 + qp * 8 + c;
            invf[qp * 2 + c] = exp2f(-(float)j * kf);
        }

#pragma unroll
    for (int mi = 0; mi < 2; mi++) {
#pragma unroll
        for (int tr = 0; tr < 2; tr++) {
            const int row = er + mi * 16 + tr * 8;
            const float p = (float)posarr[row];
#pragma unroll
            for (int qp = 0; qp < 4; qp++) {
                float y1[2], y2[2];
#pragma unroll
                for (int c = 0; c < 2; c++) {
                    float ang = p * invf[qp * 2 + c];
                    float s, co;
                    sincosf(ang, &s, &co);
                    float x1 = acc[mi][qp][tr * 2 + c];
                    float x2 = acc[mi][qp + 4][tr * 2 + c];
                    y1[c] = (x1 * co - x2 * s) * scale;
                    y2[c] = (x2 * co + x1 * s) * scale;
                }
                size_t offA = (size_t)row * CDIM + ec + qp * 8;
                size_t offB = (size_t)row * CDIM + ec + (qp + 4) * 8;
                *(uint32_t*)(dst + offA) = pack_h2(y1[0], y1[1]);
                *(uint32_t*)(dst + offB) = pack_h2(y2[0], y2[1]);
            }
        }
    }
}

// ---------------------------------------------------------------------------
// Output projection: 64x128 tiles -> grid 256, 2 CTAs/SM. fp32 out + bias.
// ---------------------------------------------------------------------------
__global__ void __launch_bounds__(256, 2)
out_proj_kernel(const float* __restrict__ bias, float* __restrict__ Cout)
{
    extern __shared__ __align__(128) char smem[];
    const uint32_t sb = smem_u32(smem);
    const int tid  = threadIdx.x;
    const int lane = tid & 31;
    const int warp = tid >> 5;
    const int m0   = blockIdx.y * 64;
    const int n0   = blockIdx.x * 128;

    float acc[1][8][4];
#pragma unroll
    for (int q = 0; q < 8; q++)
#pragma unroll
        for (int u = 0; u < 4; u++) acc[0][q][u] = 0.f;

    gemm_mainloop2<1>(g_o,
                      g_w_hi + (size_t)3 * CDIM * CDIM,
                      g_w_lo + (size_t)3 * CDIM * CDIM,
                      m0, n0, sb, tid, acc);

    const int wm = warp >> 1;
    const int wn = warp & 1;
    const int er = m0 + wm * 16 + (lane >> 2);
    const int ec = n0 + wn * 64 + (lane & 3) * 2;
#pragma unroll
    for (int q = 0; q < 8; q++) {
        float b0 = bias[ec + q * 8];
        float b1 = bias[ec + q * 8 + 1];
        float2 v0 = { acc[0][q][0] + b0, acc[0][q][1] + b1 };
        float2 v1 = { acc[0][q][2] + b0, acc[0][q][3] + b1 };
        *(float2*)&Cout[(size_t)er * CDIM + ec + q * 8]       = v0;
        *(float2*)&Cout[(size_t)(er + 8) * CDIM + ec + q * 8] = v1;
    }
}

// ---------------------------------------------------------------------------
// Flash attention, all-fp16 exact mma: 256 threads, 128 q-rows/CTA,
// 64-key tiles, single-pass QK and PV, 3-stage pipeline.
// grid = (4, 16, 4) = 256 CTAs, 2 CTAs/SM.
// ---------------------------------------------------------------------------
#define ATK 64
#define KV_PITCH 144
#define KV_TILE  (ATK * KV_PITCH)       // 9216
#define AT_STAGE (2 * KV_TILE)          // 18432 (K + V)
#define AT_STAGES 3
#define AT_SMEM  (AT_STAGES * AT_STAGE) // 55296

__device__ __forceinline__ void at_load_tile(const __half* __restrict__ g,
                                             size_t gbase, uint32_t sbase, int tid)
{
#pragma unroll
    for (int i = 0; i < 2; i++) {
        int idx = tid + i * 256;
        int rr = idx >> 3;
        int ch = idx & 7;
        cp16(sbase + rr * KV_PITCH + ch * 16,
             g + gbase + (size_t)rr * CDIM + ch * 8);
    }
}

__device__ __forceinline__ void at_load_stage(size_t kgbase, int t,
                                              uint32_t sb, int tid)
{
    uint32_t st = sb + (t % AT_STAGES) * AT_STAGE;
    size_t gb = kgbase + (size_t)t * ATK * CDIM;
    at_load_tile(g_k, gb, st, tid);
    at_load_tile(g_v, gb, st + KV_TILE, tid);
    asm volatile("cp.async.commit_group;" ::: "memory");
}

__global__ void __launch_bounds__(256, 2)
attn_mma_kernel()
{
    extern __shared__ __align__(128) char smem[];
    const uint32_t sb = smem_u32(smem);
    const int tid  = threadIdx.x;
    const int lane = tid & 31;
    const int warp = tid >> 5;        // 0..7
    const int m0   = blockIdx.x * 128;
    const int h    = blockIdx.y;
    const int b    = blockIdx.z;

    const int r  = lane >> 2;
    const int c2 = (lane & 3) * 2;

    uint32_t Qf[4][4];
    {
        size_t qbase = ((size_t)(b * NQ + m0 + warp * 16)) * CDIM + h * HDIM;
#pragma unroll
        for (int ks = 0; ks < 4; ks++) {
            int col = ks * 16 + c2;
            Qf[ks][0] = *(const uint32_t*)(g_q + qbase + (size_t)r * CDIM + col);
            Qf[ks][1] = *(const uint32_t*)(g_q + qbase + (size_t)(r + 8) * CDIM + col);
            Qf[ks][2] = *(const uint32_t*)(g_q + qbase + (size_t)r * CDIM + col + 8);
            Qf[ks][3] = *(const uint32_t*)(g_q + qbase + (size_t)(r + 8) * CDIM + col + 8);
        }
    }

    const size_t kgbase = ((size_t)(b * NK)) * CDIM + h * HDIM;

    at_load_stage(kgbase, 0, sb, tid);
    at_load_stage(kgbase, 1, sb, tid);

    float m[2] = { -1e30f, -1e30f };
    float l[2] = { 0.f, 0.f };
    float o[8][4];
#pragma unroll
    for (int nb = 0; nb < 8; nb++)
#pragma unroll
        for (int u = 0; u < 4; u++) o[nb][u] = 0.f;

    const int krow_off = ((lane >> 4) & 1) * 8 + (lane & 7);
    const int kcol_off = ((lane >> 3) & 1) * 16;
    const int vrow_off = (lane & 7) + ((lane >> 3) & 1) * 8;
    const int vcol_off = (lane >> 4) * 16;
    const float L2E = 1.44269504f;

    const int NT = NK / ATK;   // 32
    for (int t = 0; t < NT; t++) {
        asm volatile("cp.async.wait_group 1;" ::: "memory");
        __syncthreads();
        if (t + 2 < NT) at_load_stage(kgbase, t + 2, sb, tid);

        const uint32_t stg = sb + (t % AT_STAGES) * AT_STAGE;
        const uint32_t kB  = stg;
        const uint32_t vB  = stg + KV_TILE;

        float sc[8][4];
#pragma unroll
        for (int nb = 0; nb < 8; nb++)
#pragma unroll
            for (int u = 0; u < 4; u++) sc[nb][u] = 0.f;

        // --- QK: single pass (exact fp16 products) ---
#pragma unroll
        for (int ks = 0; ks < 4; ks++) {
            uint32_t kf4[4][4];
#pragma unroll
            for (int nj = 0; nj < 4; nj++)
                ldm_x4(kf4[nj], kB + (uint32_t)((nj * 16 + krow_off) * KV_PITCH
                                                + ks * 32 + kcol_off));
#pragma unroll
            for (int nj = 0; nj < 4; nj++)
#pragma unroll
                for (int nb = 0; nb < 2; nb++)
                    mma_f16(sc[nj * 2 + nb], Qf[ks],
                            kf4[nj][nb * 2], kf4[nj][nb * 2 + 1]);
        }

        // --- softmax (rows r, r+8) ---
#pragma unroll
        for (int i = 0; i < 2; i++) {
            float mx = sc[0][2 * i];
#pragma unroll
            for (int nb = 0; nb < 8; nb++)
                mx = fmaxf(mx, fmaxf(sc[nb][2 * i], sc[nb][2 * i + 1]));
            mx = fmaxf(mx, __shfl_xor_sync(0xFFFFFFFFu, mx, 1));
            mx = fmaxf(mx, __shfl_xor_sync(0xFFFFFFFFu, mx, 2));
            float mn = fmaxf(m[i], mx);
            float corr = exp2f((m[i] - mn) * L2E);
            m[i] = mn;
            float mnL = mn * L2E;
            float ls = 0.f;
#pragma unroll
            for (int nb = 0; nb < 8; nb++) {
                float p0 = exp2f(fmaf(sc[nb][2 * i], L2E, -mnL));
                float p1 = exp2f(fmaf(sc[nb][2 * i + 1], L2E, -mnL));
                sc[nb][2 * i] = p0;
                sc[nb][2 * i + 1] = p1;
                ls += p0 + p1;
            }
            l[i] = l[i] * corr + ls;
#pragma unroll
            for (int nb = 0; nb < 8; nb++) {
                o[nb][2 * i]     *= corr;
                o[nb][2 * i + 1] *= corr;
            }
        }

        // --- PV: single pass ---
        uint32_t Pf[4][4];
#pragma unroll
        for (int j = 0; j < 4; j++) {
            Pf[j][0] = pack_h2(sc[2 * j][0],     sc[2 * j][1]);
            Pf[j][1] = pack_h2(sc[2 * j][2],     sc[2 * j][3]);
            Pf[j][2] = pack_h2(sc[2 * j + 1][0], sc[2 * j + 1][1]);
            Pf[j][3] = pack_h2(sc[2 * j + 1][2], sc[2 * j + 1][3]);
        }
#pragma unroll
        for (int j = 0; j < 4; j++) {
            uint32_t vf[4][4];
#pragma unroll
            for (int g = 0; g < 4; g++)
                ldm_x4_t(vf[g], vB + (uint32_t)((j * 16 + vrow_off) * KV_PITCH
                                                + g * 32 + vcol_off));
#pragma unroll
            for (int g = 0; g < 4; g++)
#pragma unroll
                for (int nb = 0; nb < 2; nb++)
                    mma_f16(o[g * 2 + nb], Pf[j],
                            vf[g][nb * 2], vf[g][nb * 2 + 1]);
        }
    }

    float inv[2];
#pragma unroll
    for (int i = 0; i < 2; i++) {
        float lt = l[i];
        lt += __shfl_xor_sync(0xFFFFFFFFu, lt, 1);
        lt += __shfl_xor_sync(0xFFFFFFFFu, lt, 2);
        inv[i] = 1.f / lt;
    }
    size_t obase = ((size_t)(b * NQ + m0 + warp * 16)) * CDIM + h * HDIM;
#pragma unroll
    for (int nb = 0; nb < 8; nb++) {
#pragma unroll
        for (int i = 0; i < 2; i++) {
            float x0 = o[nb][2 * i] * inv[i];
            float x1 = o[nb][2 * i + 1] * inv[i];
            size_t off = obase + (size_t)(r + i * 8) * CDIM + nb * 8 + c2;
            *(uint32_t*)(g_o + off) = pack_h2(x0, x1);
        }
    }
}

// ---------------------------------------------------------------------------
// Launcher
// ---------------------------------------------------------------------------
extern "C" void kernel_launch(void* const* d_in, const int* in_sizes, int n_in,
                              void* d_out, int out_size)
{
    const float* query = (const float*)d_in[0];
    const float* key   = (const float*)d_in[1];
    const float* value = (const float*)d_in[2];
    const int*   qpos  = (const int*)  d_in[3];
    const int*   kpos  = (const int*)  d_in[4];
    const float* Wq    = (const float*)d_in[5];
    const float* Wk    = (const float*)d_in[6];
    const float* Wv    = (const float*)d_in[7];
    const float* Wp    = (const float*)d_in[8];
    const float* bp    = (const float*)d_in[9];
    float* out = (float*)d_out;

    cudaFuncSetAttribute(qkv_proj_kernel,
                         cudaFuncAttributeMaxDynamicSharedMemorySize, GM_SMEM);
    cudaFuncSetAttribute(out_proj_kernel,
                         cudaFuncAttributeMaxDynamicSharedMemorySize, GO_SMEM);
    cudaFuncSetAttribute(attn_mma_kernel,
                         cudaFuncAttributeMaxDynamicSharedMemorySize, AT_SMEM);

    split_all_kernel<<<SPLIT_TOTAL / 512, 256>>>(
        (const float4*)query, (const float4*)key, (const float4*)value,
        (const float4*)Wq, (const float4*)Wk, (const float4*)Wv, (const float4*)Wp);

    qkv_proj_kernel<<<1152, 256, GM_SMEM>>>(qpos, kpos);

    attn_mma_kernel<<<dim3(NQ / 128, NHEADS, Bsz), 256, AT_SMEM>>>();

    out_proj_kernel<<<dim3(CDIM / 128, (Bsz * NQ) / 64), 256, GO_SMEM>>>(bp, out);
}

// round 10
// speedup vs baseline: 7.4363x; 1.4234x over previous
#include <cuda_runtime.h>
#include <cuda_fp16.h>
#include <cstdint>
#include <cstddef>

// Problem constants
#define Bsz 4
#define NQ  512
#define NK  2048
#define CDIM 1024
#define NHEADS 16
#define HDIM 64

// ---------------------------------------------------------------------------
// Scratch (device globals — no allocation allowed). All fp16.
// ---------------------------------------------------------------------------
__device__ __half g_inq[(size_t)Bsz * NQ * CDIM];
__device__ __half g_ink[(size_t)Bsz * NK * CDIM];
__device__ __half g_inv[(size_t)Bsz * NK * CDIM];
__device__ __half g_w[(size_t)4 * CDIM * CDIM];   // Wq,Wk,Wv,Wp (single fp16)
__device__ __half g_q[(size_t)Bsz * NQ * CDIM];
__device__ __half g_k[(size_t)Bsz * NK * CDIM];
__device__ __half g_v[(size_t)Bsz * NK * CDIM];
__device__ __half g_o[(size_t)Bsz * NQ * CDIM];

// ---------------------------------------------------------------------------
// Common helpers
// ---------------------------------------------------------------------------
__device__ __forceinline__ uint32_t smem_u32(const void* p) {
    uint32_t a;
    asm("{ .reg .u64 t; cvta.to.shared.u64 t, %1; cvt.u32.u64 %0, t; }"
        : "=r"(a) : "l"(p));
    return a;
}

__device__ __forceinline__ void cp16(uint32_t dst, const void* src) {
    asm volatile("cp.async.cg.shared.global [%0], [%1], 16;"
                 :: "r"(dst), "l"(src) : "memory");
}

__device__ __forceinline__ void ldm_x4(uint32_t* r, uint32_t addr) {
    asm volatile("ldmatrix.sync.aligned.m8n8.x4.shared.b16 {%0,%1,%2,%3}, [%4];"
                 : "=r"(r[0]), "=r"(r[1]), "=r"(r[2]), "=r"(r[3]) : "r"(addr));
}

__device__ __forceinline__ void ldm_x4_t(uint32_t* r, uint32_t addr) {
    asm volatile("ldmatrix.sync.aligned.m8n8.x4.trans.shared.b16 {%0,%1,%2,%3}, [%4];"
                 : "=r"(r[0]), "=r"(r[1]), "=r"(r[2]), "=r"(r[3]) : "r"(addr));
}

__device__ __forceinline__ void mma_f16(float* c, const uint32_t* a,
                                        uint32_t b0, uint32_t b1) {
    asm volatile(
        "mma.sync.aligned.m16n8k16.row.col.f32.f16.f16.f32 "
        "{%0,%1,%2,%3}, {%4,%5,%6,%7}, {%8,%9}, {%0,%1,%2,%3};"
        : "+f"(c[0]), "+f"(c[1]), "+f"(c[2]), "+f"(c[3])
        : "r"(a[0]), "r"(a[1]), "r"(a[2]), "r"(a[3]), "r"(b0), "r"(b1));
}

__device__ __forceinline__ uint32_t pack_h2(float a, float b) {
    __half2 t = __floats2half2_rn(a, b);
    return *(uint32_t*)&t;
}

// ---------------------------------------------------------------------------
// Fused convert kernel: q,k,v,W* fp32 -> fp16.
// ---------------------------------------------------------------------------
#define QN4 ((Bsz * NQ * CDIM) / 4)      // 524288
#define KN4 ((Bsz * NK * CDIM) / 4)      // 2097152
#define WN4 ((CDIM * CDIM) / 4)          // 262144
#define SPLIT_TOTAL (QN4 + 2 * KN4 + 4 * WN4)  // 5767168

__global__ void __launch_bounds__(256)
split_all_kernel(const float4* __restrict__ q, const float4* __restrict__ k,
                 const float4* __restrict__ v, const float4* __restrict__ wq,
                 const float4* __restrict__ wk, const float4* __restrict__ wv,
                 const float4* __restrict__ wp)
{
    int base = (blockIdx.x * blockDim.x + threadIdx.x) * 2;
#pragma unroll
    for (int e = 0; e < 2; e++) {
        int idx = base + e;
        const float4* src;
        __half2* dst;
        int off;
        if (idx < QN4) { src = q; off = idx; dst = (__half2*)g_inq; }
        else if (idx < QN4 + KN4) { src = k; off = idx - QN4; dst = (__half2*)g_ink; }
        else if (idx < QN4 + 2 * KN4) { src = v; off = idx - QN4 - KN4; dst = (__half2*)g_inv; }
        else {
            int widx = idx - QN4 - 2 * KN4;
            int seg = widx / WN4;
            off = widx - seg * WN4;
            src = (seg == 0) ? wq : (seg == 1) ? wk : (seg == 2) ? wv : wp;
            dst = (__half2*)(g_w + (size_t)seg * CDIM * CDIM);
        }
        float4 a = src[off];
        dst[off * 2 + 0] = __floats2half2_rn(a.x, a.y);
        dst[off * 2 + 1] = __floats2half2_rn(a.z, a.w);
    }
}

// ---------------------------------------------------------------------------
// GEMM mainloop, templated on MI (M tile = MI*64 rows), N tile = 128, BK=32.
// A fp16 x W fp16, single pass. Single sync per chunk, double-buffered.
// ---------------------------------------------------------------------------
#define PITCH_B 80
#define TILE_W (128 * PITCH_B)

template <int MI>
struct GemmCfg {
    static const int TILE_A  = MI * 64 * PITCH_B;
    static const int STAGE_B = TILE_A + TILE_W;
    static const int SMEM    = 2 * STAGE_B;
};

template <int MI>
__device__ __forceinline__ void load_A_async(const __half* __restrict__ g,
                                             int row0, int k0,
                                             uint32_t sbase, int tid)
{
#pragma unroll
    for (int i = 0; i < MI; i++) {
        int idx = tid + i * 256;
        int r = idx >> 2;
        int j = idx & 3;
        cp16(sbase + r * PITCH_B + j * 16,
             g + (size_t)(row0 + r) * CDIM + k0 + j * 8);
    }
}

__device__ __forceinline__ void load_W_async(const __half* __restrict__ g,
                                             int row0, int k0,
                                             uint32_t sbase, int tid)
{
#pragma unroll
    for (int i = 0; i < 2; i++) {
        int idx = tid + i * 256;
        int r = idx >> 2;
        int j = idx & 3;
        cp16(sbase + r * PITCH_B + j * 16,
             g + (size_t)(row0 + r) * CDIM + k0 + j * 8);
    }
}

template <int MI>
__device__ __forceinline__ void gemm_mainloop1(
    const __half* __restrict__ A, const __half* __restrict__ W,
    int m0, int n0, uint32_t sb, int tid, float acc[MI][8][4])
{
    const int lane = tid & 31;
    const int warp = tid >> 5;
    const int wm   = warp >> 1;
    const int wn   = warp & 1;

    const int arow = wm * (16 * MI) + ((lane >> 3) & 1) * 8 + (lane & 7);
    const int acol = (lane >> 4) * 8;
    const int brow = wn * 64 + ((lane >> 4) & 1) * 8 + (lane & 7);
    const int bcol = ((lane >> 3) & 1) * 8;

    const int TILE_A  = GemmCfg<MI>::TILE_A;
    const int STAGE_B = GemmCfg<MI>::STAGE_B;

    load_A_async<MI>(A, m0, 0, sb, tid);
    load_W_async(W, n0, 0, sb + TILE_A, tid);
    asm volatile("cp.async.commit_group;" ::: "memory");

    const int NCHUNK = CDIM / 32;
    for (int c = 0; c < NCHUNK; c++) {
        asm volatile("cp.async.wait_group 0;" ::: "memory");
        __syncthreads();

        const uint32_t stg = sb + (c & 1) * STAGE_B;
        const uint32_t aB  = stg;
        const uint32_t wB  = stg + TILE_A;

#pragma unroll
        for (int s = 0; s < 2; s++) {
            const int kk = s * 16;
            uint32_t Af[MI][4], Wf[4][4];
#pragma unroll
            for (int mi = 0; mi < MI; mi++)
                ldm_x4(Af[mi], aB + (uint32_t)((arow + mi * 16) * PITCH_B
                                               + (kk + acol) * 2));
#pragma unroll
            for (int nj = 0; nj < 4; nj++)
                ldm_x4(Wf[nj], wB + (uint32_t)((brow + nj * 16) * PITCH_B
                                               + (kk + bcol) * 2));
            if (s == 0 && c + 1 < NCHUNK) {
                uint32_t st = sb + ((c + 1) & 1) * STAGE_B;
                int k0 = (c + 1) * 32;
                load_A_async<MI>(A, m0, k0, st, tid);
                load_W_async(W, n0, k0, st + TILE_A, tid);
                asm volatile("cp.async.commit_group;" ::: "memory");
            }
#pragma unroll
            for (int mi = 0; mi < MI; mi++)
#pragma unroll
                for (int q = 0; q < 8; q++)
                    mma_f16(acc[mi][q], Af[mi],
                            Wf[q >> 1][(q & 1) * 2], Wf[q >> 1][(q & 1) * 2 + 1]);
        }
    }
}

#define GM_SMEM  (GemmCfg<2>::SMEM)   // qkv: 128x128 tiles (61440 B)
#define GO_SMEM  (GemmCfg<1>::SMEM)   // out_proj: 64x128 tiles (40960 B)

// ---------------------------------------------------------------------------
// Fused QKV projection: 1152 tiles, one launch, 2 CTAs/SM.
// Epilogues: Q/K -> RoPE -> fp16; V -> fp16.
// ---------------------------------------------------------------------------
__global__ void __launch_bounds__(256, 2)
qkv_proj_kernel(const int* __restrict__ qpos, const int* __restrict__ kpos)
{
    extern __shared__ __align__(128) char smem[];
    const uint32_t sb = smem_u32(smem);
    const int tid  = threadIdx.x;
    const int lane = tid & 31;
    const int warp = tid >> 5;
    const int t    = blockIdx.x;

    int gemm, local;
    if (t < 512)       { gemm = 1; local = t; }
    else if (t < 1024) { gemm = 2; local = t - 512; }
    else               { gemm = 0; local = t - 1024; }
    const int m0 = (local >> 3) * 128;
    const int n0 = (local & 7) * 128;

    const __half *A, *W;
    if (gemm == 0)      { A = g_inq; W = g_w; }
    else if (gemm == 1) { A = g_ink; W = g_w + (size_t)CDIM * CDIM; }
    else                { A = g_inv; W = g_w + (size_t)2 * CDIM * CDIM; }

    float acc[2][8][4];
#pragma unroll
    for (int mi = 0; mi < 2; mi++)
#pragma unroll
        for (int q = 0; q < 8; q++)
#pragma unroll
            for (int u = 0; u < 4; u++) acc[mi][q][u] = 0.f;

    gemm_mainloop1<2>(A, W, m0, n0, sb, tid, acc);

    const int wm = warp >> 1;
    const int wn = warp & 1;
    const int er = m0 + wm * 32 + (lane >> 2);
    const int ec = n0 + wn * 64 + (lane & 3) * 2;

    if (gemm == 2) {
#pragma unroll
        for (int mi = 0; mi < 2; mi++) {
#pragma unroll
            for (int q = 0; q < 8; q++) {
                size_t off0 = (size_t)(er + mi * 16) * CDIM + ec + q * 8;
                size_t off1 = (size_t)(er + mi * 16 + 8) * CDIM + ec + q * 8;
                *(uint32_t*)(g_v + off0) = pack_h2(acc[mi][q][0], acc[mi][q][1]);
                *(uint32_t*)(g_v + off1) = pack_h2(acc[mi][q][2], acc[mi][q][3]);
            }
        }
        return;
    }

    const int* posarr = (gemm == 0) ? qpos : kpos;
    const float scale = (gemm == 0) ? 0.125f : 1.0f;
    __half* dst = (gemm == 0) ? g_q : g_k;
    const float kf = 13.2877123795494f / 32.0f;   // log2(10000)/32

    float invf[8];
#pragma unroll
    for (int qp = 0; qp < 4; qp++)
#pragma unroll
        for (int c = 0; c < 2; c++) {
            int j = (lane & 3) * 2 + qp * 8 + c;
            invf[qp * 2 + c] = exp2f(-(float)j * kf);
        }

#pragma unroll
    for (int mi = 0; mi < 2; mi++) {
#pragma unroll
        for (int tr = 0; tr < 2; tr++) {
            const int row = er + mi * 16 + tr * 8;
            const float p = (float)posarr[row];
#pragma unroll
            for (int qp = 0; qp < 4; qp++) {
                float y1[2], y2[2];
#pragma unroll
                for (int c = 0; c < 2; c++) {
                    float ang = p * invf[qp * 2 + c];
                    float s, co;
                    sincosf(ang, &s, &co);
                    float x1 = acc[mi][qp][tr * 2 + c];
                    float x2 = acc[mi][qp + 4][tr * 2 + c];
                    y1[c] = (x1 * co - x2 * s) * scale;
                    y2[c] = (x2 * co + x1 * s) * scale;
                }
                size_t offA = (size_t)row * CDIM + ec + qp * 8;
                size_t offB = (size_t)row * CDIM + ec + (qp + 4) * 8;
                *(uint32_t*)(dst + offA) = pack_h2(y1[0], y1[1]);
                *(uint32_t*)(dst + offB) = pack_h2(y2[0], y2[1]);
            }
        }
    }
}

// ---------------------------------------------------------------------------
// Output projection: 64x128 tiles -> grid 256, 2 CTAs/SM. fp32 out + bias.
// ---------------------------------------------------------------------------
__global__ void __launch_bounds__(256, 2)
out_proj_kernel(const float* __restrict__ bias, float* __restrict__ Cout)
{
    extern __shared__ __align__(128) char smem[];
    const uint32_t sb = smem_u32(smem);
    const int tid  = threadIdx.x;
    const int lane = tid & 31;
    const int warp = tid >> 5;
    const int m0   = blockIdx.y * 64;
    const int n0   = blockIdx.x * 128;

    float acc[1][8][4];
#pragma unroll
    for (int q = 0; q < 8; q++)
#pragma unroll
        for (int u = 0; u < 4; u++) acc[0][q][u] = 0.f;

    gemm_mainloop1<1>(g_o, g_w + (size_t)3 * CDIM * CDIM, m0, n0, sb, tid, acc);

    const int wm = warp >> 1;
    const int wn = warp & 1;
    const int er = m0 + wm * 16 + (lane >> 2);
    const int ec = n0 + wn * 64 + (lane & 3) * 2;
#pragma unroll
    for (int q = 0; q < 8; q++) {
        float b0 = bias[ec + q * 8];
        float b1 = bias[ec + q * 8 + 1];
        float2 v0 = { acc[0][q][0] + b0, acc[0][q][1] + b1 };
        float2 v1 = { acc[0][q][2] + b0, acc[0][q][3] + b1 };
        *(float2*)&Cout[(size_t)er * CDIM + ec + q * 8]       = v0;
        *(float2*)&Cout[(size_t)(er + 8) * CDIM + ec + q * 8] = v1;
    }
}

// ---------------------------------------------------------------------------
// Flash attention, all-fp16 exact mma: 256 threads, 128 q-rows/CTA,
// 64-key tiles, single-pass QK and PV, 3-stage pipeline, 2 CTAs/SM.
// ---------------------------------------------------------------------------
#define ATK 64
#define KV_PITCH 144
#define KV_TILE  (ATK * KV_PITCH)       // 9216
#define AT_STAGE (2 * KV_TILE)          // 18432 (K + V)
#define AT_STAGES 3
#define AT_SMEM  (AT_STAGES * AT_STAGE) // 55296

__device__ __forceinline__ void at_load_tile(const __half* __restrict__ g,
                                             size_t gbase, uint32_t sbase, int tid)
{
#pragma unroll
    for (int i = 0; i < 2; i++) {
        int idx = tid + i * 256;
        int rr = idx >> 3;
        int ch = idx & 7;
        cp16(sbase + rr * KV_PITCH + ch * 16,
             g + gbase + (size_t)rr * CDIM + ch * 8);
    }
}

__device__ __forceinline__ void at_load_stage(size_t kgbase, int t,
                                              uint32_t sb, int tid)
{
    uint32_t st = sb + (t % AT_STAGES) * AT_STAGE;
    size_t gb = kgbase + (size_t)t * ATK * CDIM;
    at_load_tile(g_k, gb, st, tid);
    at_load_tile(g_v, gb, st + KV_TILE, tid);
    asm volatile("cp.async.commit_group;" ::: "memory");
}

__global__ void __launch_bounds__(256, 2)
attn_mma_kernel()
{
    extern __shared__ __align__(128) char smem[];
    const uint32_t sb = smem_u32(smem);
    const int tid  = threadIdx.x;
    const int lane = tid & 31;
    const int warp = tid >> 5;        // 0..7
    const int m0   = blockIdx.x * 128;
    const int h    = blockIdx.y;
    const int b    = blockIdx.z;

    const int r  = lane >> 2;
    const int c2 = (lane & 3) * 2;

    uint32_t Qf[4][4];
    {
        size_t qbase = ((size_t)(b * NQ + m0 + warp * 16)) * CDIM + h * HDIM;
#pragma unroll
        for (int ks = 0; ks < 4; ks++) {
            int col = ks * 16 + c2;
            Qf[ks][0] = *(const uint32_t*)(g_q + qbase + (size_t)r * CDIM + col);
            Qf[ks][1] = *(const uint32_t*)(g_q + qbase + (size_t)(r + 8) * CDIM + col);
            Qf[ks][2] = *(const uint32_t*)(g_q + qbase + (size_t)r * CDIM + col + 8);
            Qf[ks][3] = *(const uint32_t*)(g_q + qbase + (size_t)(r + 8) * CDIM + col + 8);
        }
    }

    const size_t kgbase = ((size_t)(b * NK)) * CDIM + h * HDIM;

    at_load_stage(kgbase, 0, sb, tid);
    at_load_stage(kgbase, 1, sb, tid);

    float m[2] = { -1e30f, -1e30f };
    float l[2] = { 0.f, 0.f };
    float o[8][4];
#pragma unroll
    for (int nb = 0; nb < 8; nb++)
#pragma unroll
        for (int u = 0; u < 4; u++) o[nb][u] = 0.f;

    const int krow_off = ((lane >> 4) & 1) * 8 + (lane & 7);
    const int kcol_off = ((lane >> 3) & 1) * 16;
    const int vrow_off = (lane & 7) + ((lane >> 3) & 1) * 8;
    const int vcol_off = (lane >> 4) * 16;
    const float L2E = 1.44269504f;

    const int NT = NK / ATK;   // 32
    for (int t = 0; t < NT; t++) {
        asm volatile("cp.async.wait_group 1;" ::: "memory");
        __syncthreads();
        if (t + 2 < NT) at_load_stage(kgbase, t + 2, sb, tid);

        const uint32_t stg = sb + (t % AT_STAGES) * AT_STAGE;
        const uint32_t kB  = stg;
        const uint32_t vB  = stg + KV_TILE;

        float sc[8][4];
#pragma unroll
        for (int nb = 0; nb < 8; nb++)
#pragma unroll
            for (int u = 0; u < 4; u++) sc[nb][u] = 0.f;

        // --- QK: single pass (exact fp16 products) ---
#pragma unroll
        for (int ks = 0; ks < 4; ks++) {
            uint32_t kf4[4][4];
#pragma unroll
            for (int nj = 0; nj < 4; nj++)
                ldm_x4(kf4[nj], kB + (uint32_t)((nj * 16 + krow_off) * KV_PITCH
                                                + ks * 32 + kcol_off));
#pragma unroll
            for (int nj = 0; nj < 4; nj++)
#pragma unroll
                for (int nb = 0; nb < 2; nb++)
                    mma_f16(sc[nj * 2 + nb], Qf[ks],
                            kf4[nj][nb * 2], kf4[nj][nb * 2 + 1]);
        }

        // --- softmax (rows r, r+8) ---
#pragma unroll
        for (int i = 0; i < 2; i++) {
            float mx = sc[0][2 * i];
#pragma unroll
            for (int nb = 0; nb < 8; nb++)
                mx = fmaxf(mx, fmaxf(sc[nb][2 * i], sc[nb][2 * i + 1]));
            mx = fmaxf(mx, __shfl_xor_sync(0xFFFFFFFFu, mx, 1));
            mx = fmaxf(mx, __shfl_xor_sync(0xFFFFFFFFu, mx, 2));
            float mn = fmaxf(m[i], mx);
            float corr = exp2f((m[i] - mn) * L2E);
            m[i] = mn;
            float mnL = mn * L2E;
            float ls = 0.f;
#pragma unroll
            for (int nb = 0; nb < 8; nb++) {
                float p0 = exp2f(fmaf(sc[nb][2 * i], L2E, -mnL));
                float p1 = exp2f(fmaf(sc[nb][2 * i + 1], L2E, -mnL));
                sc[nb][2 * i] = p0;
                sc[nb][2 * i + 1] = p1;
                ls += p0 + p1;
            }
            l[i] = l[i] * corr + ls;
#pragma unroll
            for (int nb = 0; nb < 8; nb++) {
                o[nb][2 * i]     *= corr;
                o[nb][2 * i + 1] *= corr;
            }
        }

        // --- PV: single pass ---
        uint32_t Pf[4][4];
#pragma unroll
        for (int j = 0; j < 4; j++) {
            Pf[j][0] = pack_h2(sc[2 * j][0],     sc[2 * j][1]);
            Pf[j][1] = pack_h2(sc[2 * j][2],     sc[2 * j][3]);
            Pf[j][2] = pack_h2(sc[2 * j + 1][0], sc[2 * j + 1][1]);
            Pf[j][3] = pack_h2(sc[2 * j + 1][2], sc[2 * j + 1][3]);
        }
#pragma unroll
        for (int j = 0; j < 4; j++) {
            uint32_t vf[4][4];
#pragma unroll
            for (int g = 0; g < 4; g++)
                ldm_x4_t(vf[g], vB + (uint32_t)((j * 16 + vrow_off) * KV_PITCH
                                                + g * 32 + vcol_off));
#pragma unroll
            for (int g = 0; g < 4; g++)
#pragma unroll
                for (int nb = 0; nb < 2; nb++)
                    mma_f16(o[g * 2 + nb], Pf[j],
                            vf[g][nb * 2], vf[g][nb * 2 + 1]);
        }
    }

    float inv[2];
#pragma unroll
    for (int i = 0; i < 2; i++) {
        float lt = l[i];
        lt += __shfl_xor_sync(0xFFFFFFFFu, lt, 1);
        lt += __shfl_xor_sync(0xFFFFFFFFu, lt, 2);
        inv[i] = 1.f / lt;
    }
    size_t obase = ((size_t)(b * NQ + m0 + warp * 16)) * CDIM + h * HDIM;
#pragma unroll
    for (int nb = 0; nb < 8; nb++) {
#pragma unroll
        for (int i = 0; i < 2; i++) {
            float x0 = o[nb][2 * i] * inv[i];
            float x1 = o[nb][2 * i + 1] * inv[i];
            size_t off = obase + (size_t)(r + i * 8) * CDIM + nb * 8 + c2;
            *(uint32_t*)(g_o + off) = pack_h2(x0, x1);
        }
    }
}

// ---------------------------------------------------------------------------
// Launcher
// ---------------------------------------------------------------------------
extern "C" void kernel_launch(void* const* d_in, const int* in_sizes, int n_in,
                              void* d_out, int out_size)
{
    const float* query = (const float*)d_in[0];
    const float* key   = (const float*)d_in[1];
    const float* value = (const float*)d_in[2];
    const int*   qpos  = (const int*)  d_in[3];
    const int*   kpos  = (const int*)  d_in[4];
    const float* Wq    = (const float*)d_in[5];
    const float* Wk    = (const float*)d_in[6];
    const float* Wv    = (const float*)d_in[7];
    const float* Wp    = (const float*)d_in[8];
    const float* bp    = (const float*)d_in[9];
    float* out = (float*)d_out;

    cudaFuncSetAttribute(qkv_proj_kernel,
                         cudaFuncAttributeMaxDynamicSharedMemorySize, GM_SMEM);
    cudaFuncSetAttribute(out_proj_kernel,
                         cudaFuncAttributeMaxDynamicSharedMemorySize, GO_SMEM);
    cudaFuncSetAttribute(attn_mma_kernel,
                         cudaFuncAttributeMaxDynamicSharedMemorySize, AT_SMEM);

    split_all_kernel<<<SPLIT_TOTAL / 512, 256>>>(
        (const float4*)query, (const float4*)key, (const float4*)value,
        (const float4*)Wq, (const float4*)Wk, (const float4*)Wv, (const float4*)Wp);

    qkv_proj_kernel<<<1152, 256, GM_SMEM>>>(qpos, kpos);

    attn_mma_kernel<<<dim3(NQ / 128, NHEADS, Bsz), 256, AT_SMEM>>>();

    out_proj_kernel<<<dim3(CDIM / 128, (Bsz * NQ) / 64), 256, GO_SMEM>>>(bp, out);
}